// round 2
// baseline (speedup 1.0000x reference)
#include <cuda_runtime.h>
#include <cuda_bf16.h>
#include <math.h>

#define Nn 40000
#define Ee 320000
#define Dd 128
#define Hh 4
#define Tt 3
#define Rr 5
#define Kk 3
#define DKk 32
#define NPAD (Nn + 64*Tt)
#define ND (Nn*Dd)

// ---------------- scratch (static device globals; no allocation) ----------------
__device__ float g_qn[ND], g_kn[ND], g_vn[ND];
__device__ float g_ebuf[Ee*Hh];            // logits then exp values
__device__ float g_nmax[Nn*Hh], g_nsum[Nn*Hh];
__device__ int   g_deg[Nn];
__device__ float g_aggX[Kk][ND];           // pre-WMk aggregates (root applied to k=2)
__device__ float g_aggm[Kk][ND];
__device__ float g_front[Kk][ND];
__device__ float g_tail[Kk][ND];
__device__ float g_hb[ND];                 // gelu(res)
__device__ float g_trans[ND];
__device__ int   g_perm[NPAD], g_hist[Tt], g_cursor[Tt], g_offA[Tt+1];
__device__ float g_Wc[Kk][Dd*Dd], g_bc[Kk][Dd];

// ---------------- helpers ----------------
__device__ __forceinline__ void atomicMaxFloat(float* addr, float v) {
    if (v >= 0.f) atomicMax((int*)addr, __float_as_int(v));
    else          atomicMin((unsigned int*)addr, __float_as_uint(v));
}

__device__ __forceinline__ float warp_sum(float v) {
    v += __shfl_xor_sync(0xffffffffu, v, 16);
    v += __shfl_xor_sync(0xffffffffu, v, 8);
    v += __shfl_xor_sync(0xffffffffu, v, 4);
    v += __shfl_xor_sync(0xffffffffu, v, 2);
    v += __shfl_xor_sync(0xffffffffu, v, 1);
    return v;
}

__device__ __forceinline__ float signed_cbrt(float z) {
    return (z == 0.f) ? 0.f : copysignf(cbrtf(fabsf(z) + 1e-18f), z);
}

// ---------------- setup kernels ----------------
__global__ void k_init() {
    int i = blockIdx.x * blockDim.x + threadIdx.x;
    if (i < Nn*Hh) { g_nmax[i] = __int_as_float(0xff800000); g_nsum[i] = 0.f; }
    if (i < Nn)    g_deg[i] = 0;
    if (i < NPAD)  g_perm[i] = -1;
    if (i < Tt)    { g_hist[i] = 0; g_cursor[i] = 0; }
}

__global__ void k_hist(const int* __restrict__ ntype) {
    int n = blockIdx.x * blockDim.x + threadIdx.x;
    if (n < Nn) atomicAdd(&g_hist[ntype[n]], 1);
}

__global__ void k_offsets() {
    int off = 0;
    for (int t = 0; t < Tt; t++) { g_offA[t] = off; off += ((g_hist[t] + 63) & ~63); }
    g_offA[Tt] = off;
}

__global__ void k_scatter(const int* __restrict__ ntype) {
    int n = blockIdx.x * blockDim.x + threadIdx.x;
    if (n < Nn) {
        int t = ntype[n];
        int p = atomicAdd(&g_cursor[t], 1);
        g_perm[g_offA[t] + p] = n;
    }
}

__global__ void k_bc(const float* __restrict__ bq, const float* __restrict__ Wak) {
    int k = blockIdx.x, o = threadIdx.x;
    float s = 0.f;
    for (int j = 0; j < Dd; j++) s += bq[j] * Wak[k*Dd*Dd + j*Dd + o];
    g_bc[k][o] = s;
}

// ---------------- fp32 tiled GEMM core: [64 rows] x [128 out], K=128 ----------------
__device__ __forceinline__ void gemm_core(
    const float* __restrict__ X, const int* __restrict__ perm,
    int row0, int rowlimit,
    const float* __restrict__ W, const float* __restrict__ bias,
    float* __restrict__ Y)
{
    __shared__ float As[128][68];   // transposed [k][m], +4 pad: conflict-free & 16B aligned
    __shared__ float Bs[8][128];
    __shared__ int   rowNode[64];

    int tid = threadIdx.x;              // 256
    int m = tid & 63, seg = tid >> 6;

    if (tid < 64) {
        int gr = row0 + tid;
        int nd = -1;
        if (gr < rowlimit) nd = perm ? perm[gr] : gr;
        rowNode[tid] = nd;
    }
    __syncthreads();

    int node = rowNode[m];
    if (node >= 0) {
        const float4* xr = (const float4*)(X + node*Dd + seg*32);
        #pragma unroll
        for (int j = 0; j < 8; j++) {
            float4 v = xr[j];
            int k = seg*32 + j*4;
            As[k][m] = v.x; As[k+1][m] = v.y; As[k+2][m] = v.z; As[k+3][m] = v.w;
        }
    } else {
        #pragma unroll
        for (int j = 0; j < 8; j++) {
            int k = seg*32 + j*4;
            As[k][m] = 0.f; As[k+1][m] = 0.f; As[k+2][m] = 0.f; As[k+3][m] = 0.f;
        }
    }

    float acc[8][4];
    #pragma unroll
    for (int r = 0; r < 8; r++) { acc[r][0]=0.f; acc[r][1]=0.f; acc[r][2]=0.f; acc[r][3]=0.f; }

    int tx = tid & 31, ty = tid >> 5;
    int wr = tid >> 5, wc = (tid & 31) * 4;

    for (int kt = 0; kt < 16; kt++) {
        __syncthreads();
        *(float4*)&Bs[wr][wc] = *(const float4*)(W + (kt*8 + wr)*Dd + wc);
        __syncthreads();
        #pragma unroll
        for (int kk = 0; kk < 8; kk++) {
            float4 b = *(const float4*)&Bs[kk][tx*4];
            const float4* ap = (const float4*)&As[kt*8 + kk][ty*8];
            float4 a0 = ap[0], a1 = ap[1];
            float a[8] = {a0.x, a0.y, a0.z, a0.w, a1.x, a1.y, a1.z, a1.w};
            #pragma unroll
            for (int r = 0; r < 8; r++) {
                acc[r][0] += a[r]*b.x; acc[r][1] += a[r]*b.y;
                acc[r][2] += a[r]*b.z; acc[r][3] += a[r]*b.w;
            }
        }
    }

    float4 bv = make_float4(0.f, 0.f, 0.f, 0.f);
    if (bias) bv = *(const float4*)(bias + tx*4);
    #pragma unroll
    for (int r = 0; r < 8; r++) {
        int nd = rowNode[ty*8 + r];
        if (nd >= 0) {
            float4 o = make_float4(acc[r][0]+bv.x, acc[r][1]+bv.y,
                                   acc[r][2]+bv.z, acc[r][3]+bv.w);
            *(float4*)(Y + nd*Dd + tx*4) = o;
        }
    }
}

// ---------------- GEMM wrappers ----------------
__global__ void k_gemm_wc(const float* __restrict__ Wq, const float* __restrict__ Wak) {
    int z = blockIdx.z;
    gemm_core(Wq, nullptr, blockIdx.x*64, Dd, Wak + z*Dd*Dd, nullptr, g_Wc[z]);
}

__global__ void k_gemm_qkv(const float* __restrict__ X,
                           const float* __restrict__ qw, const float* __restrict__ qb,
                           const float* __restrict__ kw, const float* __restrict__ kb,
                           const float* __restrict__ vw, const float* __restrict__ vb)
{
    int row0 = blockIdx.x * 64;
    int t = 0;
    if (row0 >= g_offA[1]) t = 1;
    if (row0 >= g_offA[2]) t = 2;
    const float *W, *B; float* Y;
    int z = blockIdx.z;
    if (z == 0)      { W = qw; B = qb; Y = g_qn; }
    else if (z == 1) { W = kw; B = kb; Y = g_kn; }
    else             { W = vw; B = vb; Y = g_vn; }
    gemm_core(X, g_perm, row0, NPAD, W + t*Dd*Dd, B + t*Dd, Y);
}

__global__ void k_gemm_aggm(const float* __restrict__ WMk) {
    int z = blockIdx.z;
    gemm_core(g_aggX[z], nullptr, blockIdx.x*64, Nn, WMk + z*Dd*Dd, nullptr, g_aggm[z]);
}

__global__ void k_gemm_front(const float* __restrict__ X) {
    int z = blockIdx.z;
    gemm_core(X, nullptr, blockIdx.x*64, Nn, g_Wc[z], g_bc[z], g_front[z]);
}

__global__ void k_gemm_tail(const float* __restrict__ Wkl, const float* __restrict__ bkl) {
    int z = blockIdx.z;
    gemm_core(g_aggm[z], nullptr, blockIdx.x*64, Nn, Wkl, bkl, g_tail[z]);
}

__global__ void k_gemm_a(const float* __restrict__ aw, const float* __restrict__ ab) {
    int row0 = blockIdx.x * 64;
    int t = 0;
    if (row0 >= g_offA[1]) t = 1;
    if (row0 >= g_offA[2]) t = 2;
    gemm_core(g_hb, g_perm, row0, NPAD, aw + t*Dd*Dd, ab + t*Dd, g_trans);
}

// ---------------- edge phase ----------------
// Pass B1: logits[e][h] = (q[tgt] . (k[src] @ rel_att[r])) * pri / sqrt(dk); seg-max; indegree
__global__ void k_edge_logits(const int* __restrict__ ei, const int* __restrict__ et,
                              const float* __restrict__ ratt, const float* __restrict__ rpri)
{
    __shared__ float sk[4][128];
    int warp = threadIdx.x >> 5, lane = threadIdx.x & 31;
    int e = blockIdx.x*4 + warp;
    if (e >= Ee) return;
    int s = ei[e], tg = ei[Ee + e], r = et[e];
    *(float4*)&sk[warp][lane*4] = ((const float4*)(g_kn + s*Dd))[lane];
    __syncwarp();
    int h = lane >> 3, m0 = (lane & 7) * 4;
    const float* A = ratt + (r*Hh + h)*(DKk*DKk) + m0;
    float ax = 0.f, ay = 0.f, az = 0.f, aw = 0.f;
    const float* kh = &sk[warp][h*32];
    #pragma unroll
    for (int d = 0; d < DKk; d++) {
        float kv = kh[d];
        float4 a = *(const float4*)(A + d*DKk);
        ax += kv*a.x; ay += kv*a.y; az += kv*a.z; aw += kv*a.w;
    }
    float4 qv = *(const float4*)(g_qn + tg*Dd + h*32 + m0);
    float p = ax*qv.x + ay*qv.y + az*qv.z + aw*qv.w;
    p += __shfl_xor_sync(0xffffffffu, p, 1);
    p += __shfl_xor_sync(0xffffffffu, p, 2);
    p += __shfl_xor_sync(0xffffffffu, p, 4);
    if ((lane & 7) == 0) {
        float logit = p * rpri[r*Hh + h] * 0.17677669529663687f; // 1/sqrt(32)
        g_ebuf[e*Hh + h] = logit;
        atomicMaxFloat(&g_nmax[tg*Hh + h], logit);
    }
    if (lane == 0) atomicAdd(&g_deg[tg], 1);
}

// Pass B2: ex = exp(logit - max); seg-sum
__global__ void k_edge_exp(const int* __restrict__ ei) {
    int idx = blockIdx.x * blockDim.x + threadIdx.x;
    if (idx >= Ee*Hh) return;
    int e = idx >> 2, h = idx & 3;
    int tg = ei[Ee + e];
    float ex = expf(g_ebuf[idx] - g_nmax[tg*Hh + h]);
    g_ebuf[idx] = ex;
    atomicAdd(&g_nsum[tg*Hh + h], ex);
}

// Pass C: for edge index n<N: vp = v[src]@rel_msg[r]; att; agg[k][n] = deg(n)*vp^(k+1)*att;
// k=2 gets signed cube root. (agg = segment_sum(msgs[tgt]) collapses to deg*msgs[n].)
__global__ void k_msg(const int* __restrict__ ei, const int* __restrict__ et,
                      const float* __restrict__ rmsg)
{
    __shared__ float sv[4][128];
    int warp = threadIdx.x >> 5, lane = threadIdx.x & 31;
    int n = blockIdx.x*4 + warp;
    if (n >= Nn) return;
    int s = ei[n], tg = ei[Ee + n], r = et[n];
    *(float4*)&sv[warp][lane*4] = ((const float4*)(g_vn + s*Dd))[lane];
    __syncwarp();
    int h = lane >> 3, m0 = (lane & 7) * 4;
    const float* A = rmsg + (r*Hh + h)*(DKk*DKk) + m0;
    float ax = 0.f, ay = 0.f, az = 0.f, aw = 0.f;
    const float* vh = &sv[warp][h*32];
    #pragma unroll
    for (int d = 0; d < DKk; d++) {
        float vv = vh[d];
        float4 a = *(const float4*)(A + d*DKk);
        ax += vv*a.x; ay += vv*a.y; az += vv*a.z; aw += vv*a.w;
    }
    float att = g_ebuf[n*Hh + h] / (g_nsum[tg*Hh + h] + 1e-16f);
    float c1 = (float)g_deg[n] * att;
    int base = n*Dd + lane*4;
    float4 o1, o2, o3;
    o1.x = c1*ax;       o1.y = c1*ay;       o1.z = c1*az;       o1.w = c1*aw;
    o2.x = c1*ax*ax;    o2.y = c1*ay*ay;    o2.z = c1*az*az;    o2.w = c1*aw*aw;
    o3.x = signed_cbrt(c1*ax*ax*ax);
    o3.y = signed_cbrt(c1*ay*ay*ay);
    o3.z = signed_cbrt(c1*az*az*az);
    o3.w = signed_cbrt(c1*aw*aw*aw);
    *(float4*)(g_aggX[0] + base) = o1;
    *(float4*)(g_aggX[1] + base) = o2;
    *(float4*)(g_aggX[2] + base) = o3;
}

// ---------------- gating + gelu ----------------
__global__ void k_gate() {
    int warp = threadIdx.x >> 5, lane = threadIdx.x & 31;
    int n = blockIdx.x*4 + warp;
    if (n >= Nn) return;
    int base = n*Dd + lane*4;
    float4 res = make_float4(0.f, 0.f, 0.f, 0.f);
    #pragma unroll
    for (int k = 0; k < Kk; k++) {
        float4 f = *(const float4*)(g_front[k] + base);
        float4 t = *(const float4*)(g_tail[k] + base);
        float p = f.x*t.x + f.y*t.y + f.z*t.z + f.w*t.w;
        p = warp_sum(p);
        float tk = 1.f / (1.f + expf(-p));
        float4 a = *(const float4*)(g_aggm[k] + base);
        res.x += tk*a.x; res.y += tk*a.y; res.z += tk*a.z; res.w += tk*a.w;
    }
    float4 ho;
    ho.x = 0.5f*res.x*(1.f + erff(res.x*0.7071067811865475f));
    ho.y = 0.5f*res.y*(1.f + erff(res.y*0.7071067811865475f));
    ho.z = 0.5f*res.z*(1.f + erff(res.z*0.7071067811865475f));
    ho.w = 0.5f*res.w*(1.f + erff(res.w*0.7071067811865475f));
    *(float4*)(g_hb + base) = ho;
}

// ---------------- skip + layernorm ----------------
__global__ void k_final(const float* __restrict__ X, const int* __restrict__ ntype,
                        const float* __restrict__ skip, const float* __restrict__ lng,
                        const float* __restrict__ lnb, float* __restrict__ out)
{
    int warp = threadIdx.x >> 5, lane = threadIdx.x & 31;
    int n = blockIdx.x*4 + warp;
    if (n >= Nn) return;
    int t = ntype[n];
    float alpha = 1.f / (1.f + expf(-skip[t]));
    int base = n*Dd + lane*4;
    float4 x  = *(const float4*)(X + base);
    float4 tr = *(const float4*)(g_trans + base);
    float4 y;
    y.x = tr.x*alpha + x.x*(1.f - alpha);
    y.y = tr.y*alpha + x.y*(1.f - alpha);
    y.z = tr.z*alpha + x.z*(1.f - alpha);
    y.w = tr.w*alpha + x.w*(1.f - alpha);
    float mu = warp_sum(y.x + y.y + y.z + y.w) * (1.f/128.f);
    float4 d = make_float4(y.x - mu, y.y - mu, y.z - mu, y.w - mu);
    float var = warp_sum(d.x*d.x + d.y*d.y + d.z*d.z + d.w*d.w) * (1.f/128.f);
    float rstd = rsqrtf(var + 1e-5f);
    int gi = t*Dd + lane*4;
    float4 g = *(const float4*)(lng + gi);
    float4 b = *(const float4*)(lnb + gi);
    float4 o;
    o.x = d.x*rstd*g.x + b.x;
    o.y = d.y*rstd*g.y + b.y;
    o.z = d.z*rstd*g.z + b.z;
    o.w = d.w*rstd*g.w + b.w;
    *(float4*)(out + base) = o;
}

// ---------------- launch ----------------
extern "C" void kernel_launch(void* const* d_in, const int* in_sizes, int n_in,
                              void* d_out, int out_size)
{
    const float* meta = (const float*)d_in[0];
    const int*   ntype = (const int*)d_in[1];
    const int*   ei    = (const int*)d_in[2];
    const int*   et    = (const int*)d_in[3];
    // d_in[4] = edge_time (unused)
    const float* qw = (const float*)d_in[5],  *qb = (const float*)d_in[6];
    const float* kw = (const float*)d_in[7],  *kb = (const float*)d_in[8];
    const float* vw = (const float*)d_in[9],  *vb = (const float*)d_in[10];
    const float* aw = (const float*)d_in[11], *ab = (const float*)d_in[12];
    const float* rpri = (const float*)d_in[13];
    const float* ratt = (const float*)d_in[14];
    const float* rmsg = (const float*)d_in[15];
    const float* WMk  = (const float*)d_in[16];
    const float* Wak  = (const float*)d_in[17];
    const float* Wq   = (const float*)d_in[18], *bq  = (const float*)d_in[19];
    const float* Wkl  = (const float*)d_in[20], *bkl = (const float*)d_in[21];
    const float* skp  = (const float*)d_in[22];
    const float* lng  = (const float*)d_in[23], *lnb = (const float*)d_in[24];
    float* out = (float*)d_out;

    k_init<<<(Nn*Hh + 255)/256, 256>>>();
    k_hist<<<(Nn + 255)/256, 256>>>(ntype);
    k_offsets<<<1, 1>>>();
    k_scatter<<<(Nn + 255)/256, 256>>>(ntype);

    k_gemm_wc<<<dim3(2, 1, 3), 256>>>(Wq, Wak);
    k_bc<<<3, 128>>>(bq, Wak);

    k_gemm_qkv<<<dim3(NPAD/64, 1, 3), 256>>>(meta, qw, qb, kw, kb, vw, vb);

    k_edge_logits<<<Ee/4, 128>>>(ei, et, ratt, rpri);
    k_edge_exp<<<(Ee*Hh + 255)/256, 256>>>(ei);
    k_msg<<<Nn/4, 128>>>(ei, et, rmsg);

    k_gemm_aggm<<<dim3((Nn + 63)/64, 1, 3), 256>>>(WMk);
    k_gemm_front<<<dim3((Nn + 63)/64, 1, 3), 256>>>(meta);
    k_gemm_tail<<<dim3((Nn + 63)/64, 1, 3), 256>>>(Wkl, bkl);

    k_gate<<<Nn/4, 128>>>();
    k_gemm_a<<<dim3(NPAD/64, 1, 1), 256>>>(aw, ab);
    k_final<<<Nn/4, 128>>>(meta, ntype, skp, lng, lnb, out);
}

// round 7
// speedup vs baseline: 1.0067x; 1.0067x over previous
#include <cuda_runtime.h>
#include <cuda_bf16.h>
#include <stdint.h>
#include <math.h>

#define Nn 40000
#define Ee 320000
#define Dd 128
#define Hh 4
#define Tt 3
#define Rr 5
#define Kk 3
#define DKk 32
#define NPAD (Nn + 64*Tt)
#define ND (Nn*Dd)
#define GS 132   // padded smem stride (floats): conflict-free frag loads, 16B-aligned

// ---------------- scratch (static device globals; no allocation) ----------------
__device__ float g_qn[ND], g_kn[ND], g_vn[ND];
__device__ float g_ebuf[Ee*Hh];            // logits then exp values
__device__ float g_nmax[Nn*Hh], g_nsum[Nn*Hh];
__device__ int   g_deg[Nn];
__device__ float g_aggX[Kk][ND];           // pre-WMk aggregates (root applied to k=2)
__device__ float g_aggm[Kk][ND];
__device__ float g_front[Kk][ND];
__device__ float g_tail[Kk][ND];
__device__ float g_hb[ND];                 // gelu(res)
__device__ float g_trans[ND];
__device__ int   g_perm[NPAD], g_hist[Tt], g_cursor[Tt], g_offA[Tt+1];
__device__ float g_Wc[Kk][Dd*Dd], g_bc[Kk][Dd];

// ---------------- helpers ----------------
__device__ __forceinline__ void atomicMaxFloat(float* addr, float v) {
    if (v >= 0.f) atomicMax((int*)addr, __float_as_int(v));
    else          atomicMin((unsigned int*)addr, __float_as_uint(v));
}

__device__ __forceinline__ float warp_sum(float v) {
    v += __shfl_xor_sync(0xffffffffu, v, 16);
    v += __shfl_xor_sync(0xffffffffu, v, 8);
    v += __shfl_xor_sync(0xffffffffu, v, 4);
    v += __shfl_xor_sync(0xffffffffu, v, 2);
    v += __shfl_xor_sync(0xffffffffu, v, 1);
    return v;
}

__device__ __forceinline__ float signed_cbrt(float z) {
    return (z == 0.f) ? 0.f : copysignf(cbrtf(fabsf(z) + 1e-18f), z);
}

__device__ __forceinline__ uint32_t f2tf32(float x) {
    uint32_t u;
    asm("cvt.rna.tf32.f32 %0, %1;" : "=r"(u) : "f"(x));
    return u;
}

// 3xTF32 split: x = hi + lo with hi,lo representable in tf32.
__device__ __forceinline__ void tf32_split(float x, uint32_t& hi, uint32_t& lo) {
    hi = f2tf32(x);
    lo = f2tf32(x - __uint_as_float(hi));
}

// ---------------- setup kernels ----------------
__global__ void k_init() {
    int i = blockIdx.x * blockDim.x + threadIdx.x;
    if (i < Nn*Hh) { g_nmax[i] = __int_as_float(0xff800000); g_nsum[i] = 0.f; }
    if (i < Nn)    g_deg[i] = 0;
    if (i < NPAD)  g_perm[i] = -1;
    if (i < Tt)    { g_hist[i] = 0; g_cursor[i] = 0; }
}

__global__ void k_hist(const int* __restrict__ ntype) {
    int n = blockIdx.x * blockDim.x + threadIdx.x;
    if (n < Nn) atomicAdd(&g_hist[ntype[n]], 1);
}

__global__ void k_offsets() {
    int off = 0;
    for (int t = 0; t < Tt; t++) { g_offA[t] = off; off += ((g_hist[t] + 63) & ~63); }
    g_offA[Tt] = off;
}

__global__ void k_scatter(const int* __restrict__ ntype) {
    int n = blockIdx.x * blockDim.x + threadIdx.x;
    if (n < Nn) {
        int t = ntype[n];
        int p = atomicAdd(&g_cursor[t], 1);
        g_perm[g_offA[t] + p] = n;
    }
}

__global__ void k_bc(const float* __restrict__ bq, const float* __restrict__ Wak) {
    int k = blockIdx.x, o = threadIdx.x;
    float s = 0.f;
    for (int j = 0; j < Dd; j++) s += bq[j] * Wak[k*Dd*Dd + j*Dd + o];
    g_bc[k][o] = s;
}

// ------- 3xTF32 tensor-core GEMM core: [64 rows] x [128 out], K=128 -------
// block = 256 threads = 8 warps (4 M-groups x 2 N-groups). Warp tile: 16x64.
// A/B staged in smem as fp32; hi/lo tf32 split in registers at frag load;
// 3 mma.sync.m16n8k8 per fragment pair (ah*bh + al*bh + ah*bl), fp32 accum.
__device__ __forceinline__ void gemm_tc(
    const float* __restrict__ X, const int* __restrict__ perm,
    int row0, int rowlimit,
    const float* __restrict__ W, const float* __restrict__ bias,
    float* __restrict__ Y)
{
    __shared__ float As[64*GS];   // 33792 B  (full 64x128 A tile, fp32)
    __shared__ float Bs[16*GS];   // 8448  B  (16x128 B chunk, fp32)
    __shared__ int rowNode[64];

    int tid  = threadIdx.x;
    int lane = tid & 31, wid = tid >> 5;
    int mw = wid >> 1, nw = wid & 1;
    int g = lane >> 2, t = lane & 3;

    if (tid < 64) {
        int gr = row0 + tid;
        int nd = (gr < rowlimit) ? (perm ? perm[gr] : gr) : -1;
        rowNode[tid] = nd;
    }
    __syncthreads();

    // Stage A: thread handles row m = tid&63, quarter q = tid>>6 (32 cols)
    {
        int m = tid & 63, q = tid >> 6;
        int nd = rowNode[m];
        float* dst = As + m*GS + q*32;
        if (nd >= 0) {
            const float4* src = (const float4*)(X + nd*Dd + q*32);
            #pragma unroll
            for (int j = 0; j < 8; j++)
                *(float4*)(dst + j*4) = src[j];
        } else {
            #pragma unroll
            for (int j = 0; j < 8; j++)
                *(float4*)(dst + j*4) = make_float4(0.f, 0.f, 0.f, 0.f);
        }
    }

    float c[8][4];
    #pragma unroll
    for (int nb = 0; nb < 8; nb++) {
        c[nb][0] = 0.f; c[nb][1] = 0.f; c[nb][2] = 0.f; c[nb][3] = 0.f;
    }

    int arow0 = (mw*16 + g) * GS;
    int arow1 = (mw*16 + g + 8) * GS;

    for (int kc = 0; kc < 8; kc++) {
        __syncthreads();
        // Stage B chunk: rows kc*16 .. kc*16+15. thread: r = tid>>4, cols (tid&15)*8..+8
        {
            int r = tid >> 4, coff = (tid & 15) * 8;
            const float4* src = (const float4*)(W + (kc*16 + r)*Dd + coff);
            float* dst = Bs + r*GS + coff;
            *(float4*)(dst)     = src[0];
            *(float4*)(dst + 4) = src[1];
        }
        __syncthreads();

        #pragma unroll
        for (int ks = 0; ks < 2; ks++) {
            int kb = kc*16 + ks*8;          // global k base for A
            uint32_t ah[4], al[4];
            tf32_split(As[arow0 + kb + t],     ah[0], al[0]);
            tf32_split(As[arow1 + kb + t],     ah[1], al[1]);
            tf32_split(As[arow0 + kb + t + 4], ah[2], al[2]);
            tf32_split(As[arow1 + kb + t + 4], ah[3], al[3]);
            int kbl = ks*8;                 // local k base for B chunk
            #pragma unroll
            for (int nb = 0; nb < 8; nb++) {
                int ncol = nw*64 + nb*8 + g;
                uint32_t bh0, bl0, bh1, bl1;
                tf32_split(Bs[(kbl + t)*GS + ncol],     bh0, bl0);
                tf32_split(Bs[(kbl + t + 4)*GS + ncol], bh1, bl1);
                asm volatile(
                    "mma.sync.aligned.m16n8k8.row.col.f32.tf32.tf32.f32 "
                    "{%0,%1,%2,%3}, {%4,%5,%6,%7}, {%8,%9}, {%0,%1,%2,%3};"
                    : "+f"(c[nb][0]), "+f"(c[nb][1]), "+f"(c[nb][2]), "+f"(c[nb][3])
                    : "r"(ah[0]), "r"(ah[1]), "r"(ah[2]), "r"(ah[3]), "r"(bh0), "r"(bh1));
                asm volatile(
                    "mma.sync.aligned.m16n8k8.row.col.f32.tf32.tf32.f32 "
                    "{%0,%1,%2,%3}, {%4,%5,%6,%7}, {%8,%9}, {%0,%1,%2,%3};"
                    : "+f"(c[nb][0]), "+f"(c[nb][1]), "+f"(c[nb][2]), "+f"(c[nb][3])
                    : "r"(al[0]), "r"(al[1]), "r"(al[2]), "r"(al[3]), "r"(bh0), "r"(bh1));
                asm volatile(
                    "mma.sync.aligned.m16n8k8.row.col.f32.tf32.tf32.f32 "
                    "{%0,%1,%2,%3}, {%4,%5,%6,%7}, {%8,%9}, {%0,%1,%2,%3};"
                    : "+f"(c[nb][0]), "+f"(c[nb][1]), "+f"(c[nb][2]), "+f"(c[nb][3])
                    : "r"(ah[0]), "r"(ah[1]), "r"(ah[2]), "r"(ah[3]), "r"(bl0), "r"(bl1));
            }
        }
    }

    // Epilogue: c0,c1 -> (row mw*16+g, col nw*64+nb*8+2t); c2,c3 -> row+8
    int nd0 = rowNode[mw*16 + g];
    int nd1 = rowNode[mw*16 + g + 8];
    #pragma unroll
    for (int nb = 0; nb < 8; nb++) {
        int col = nw*64 + nb*8 + 2*t;
        float2 bv = make_float2(0.f, 0.f);
        if (bias) bv = *(const float2*)(bias + col);
        if (nd0 >= 0)
            *(float2*)(Y + nd0*Dd + col) = make_float2(c[nb][0] + bv.x, c[nb][1] + bv.y);
        if (nd1 >= 0)
            *(float2*)(Y + nd1*Dd + col) = make_float2(c[nb][2] + bv.x, c[nb][3] + bv.y);
    }
}

// ---------------- GEMM wrappers ----------------
__global__ void k_gemm_wc(const float* __restrict__ Wq, const float* __restrict__ Wak) {
    int z = blockIdx.z;
    gemm_tc(Wq, nullptr, blockIdx.x*64, Dd, Wak + z*Dd*Dd, nullptr, g_Wc[z]);
}

__global__ void k_gemm_qkv(const float* __restrict__ X,
                           const float* __restrict__ qw, const float* __restrict__ qb,
                           const float* __restrict__ kw, const float* __restrict__ kb,
                           const float* __restrict__ vw, const float* __restrict__ vb)
{
    int row0 = blockIdx.x * 64;
    int t = 0;
    if (row0 >= g_offA[1]) t = 1;
    if (row0 >= g_offA[2]) t = 2;
    const float *W, *B; float* Y;
    int z = blockIdx.z;
    if (z == 0)      { W = qw; B = qb; Y = g_qn; }
    else if (z == 1) { W = kw; B = kb; Y = g_kn; }
    else             { W = vw; B = vb; Y = g_vn; }
    gemm_tc(X, g_perm, row0, NPAD, W + t*Dd*Dd, B + t*Dd, Y);
}

__global__ void k_gemm_aggm(const float* __restrict__ WMk) {
    int z = blockIdx.z;
    gemm_tc(g_aggX[z], nullptr, blockIdx.x*64, Nn, WMk + z*Dd*Dd, nullptr, g_aggm[z]);
}

__global__ void k_gemm_front(const float* __restrict__ X) {
    int z = blockIdx.z;
    gemm_tc(X, nullptr, blockIdx.x*64, Nn, g_Wc[z], g_bc[z], g_front[z]);
}

__global__ void k_gemm_tail(const float* __restrict__ Wkl, const float* __restrict__ bkl) {
    int z = blockIdx.z;
    gemm_tc(g_aggm[z], nullptr, blockIdx.x*64, Nn, Wkl, bkl, g_tail[z]);
}

__global__ void k_gemm_a(const float* __restrict__ aw, const float* __restrict__ ab) {
    int row0 = blockIdx.x * 64;
    int t = 0;
    if (row0 >= g_offA[1]) t = 1;
    if (row0 >= g_offA[2]) t = 2;
    gemm_tc(g_hb, g_perm, row0, NPAD, aw + t*Dd*Dd, ab + t*Dd, g_trans);
}

// ---------------- edge phase ----------------
__global__ void k_edge_logits(const int* __restrict__ ei, const int* __restrict__ et,
                              const float* __restrict__ ratt, const float* __restrict__ rpri)
{
    __shared__ float sk[4][128];
    int warp = threadIdx.x >> 5, lane = threadIdx.x & 31;
    int e = blockIdx.x*4 + warp;
    if (e >= Ee) return;
    int s = ei[e], tg = ei[Ee + e], r = et[e];
    *(float4*)&sk[warp][lane*4] = ((const float4*)(g_kn + s*Dd))[lane];
    __syncwarp();
    int h = lane >> 3, m0 = (lane & 7) * 4;
    const float* A = ratt + (r*Hh + h)*(DKk*DKk) + m0;
    float ax = 0.f, ay = 0.f, az = 0.f, aw = 0.f;
    const float* kh = &sk[warp][h*32];
    #pragma unroll
    for (int d = 0; d < DKk; d++) {
        float kv = kh[d];
        float4 a = *(const float4*)(A + d*DKk);
        ax += kv*a.x; ay += kv*a.y; az += kv*a.z; aw += kv*a.w;
    }
    float4 qv = *(const float4*)(g_qn + tg*Dd + h*32 + m0);
    float p = ax*qv.x + ay*qv.y + az*qv.z + aw*qv.w;
    p += __shfl_xor_sync(0xffffffffu, p, 1);
    p += __shfl_xor_sync(0xffffffffu, p, 2);
    p += __shfl_xor_sync(0xffffffffu, p, 4);
    if ((lane & 7) == 0) {
        float logit = p * rpri[r*Hh + h] * 0.17677669529663687f;
        g_ebuf[e*Hh + h] = logit;
        atomicMaxFloat(&g_nmax[tg*Hh + h], logit);
    }
    if (lane == 0) atomicAdd(&g_deg[tg], 1);
}

__global__ void k_edge_exp(const int* __restrict__ ei) {
    int idx = blockIdx.x * blockDim.x + threadIdx.x;
    if (idx >= Ee*Hh) return;
    int e = idx >> 2, h = idx & 3;
    int tg = ei[Ee + e];
    float ex = expf(g_ebuf[idx] - g_nmax[tg*Hh + h]);
    g_ebuf[idx] = ex;
    atomicAdd(&g_nsum[tg*Hh + h], ex);
}

__global__ void k_msg(const int* __restrict__ ei, const int* __restrict__ et,
                      const float* __restrict__ rmsg)
{
    __shared__ float sv[4][128];
    int warp = threadIdx.x >> 5, lane = threadIdx.x & 31;
    int n = blockIdx.x*4 + warp;
    if (n >= Nn) return;
    int s = ei[n], tg = ei[Ee + n], r = et[n];
    *(float4*)&sv[warp][lane*4] = ((const float4*)(g_vn + s*Dd))[lane];
    __syncwarp();
    int h = lane >> 3, m0 = (lane & 7) * 4;
    const float* A = rmsg + (r*Hh + h)*(DKk*DKk) + m0;
    float ax = 0.f, ay = 0.f, az = 0.f, aw = 0.f;
    const float* vh = &sv[warp][h*32];
    #pragma unroll
    for (int d = 0; d < DKk; d++) {
        float vv = vh[d];
        float4 a = *(const float4*)(A + d*DKk);
        ax += vv*a.x; ay += vv*a.y; az += vv*a.z; aw += vv*a.w;
    }
    float att = g_ebuf[n*Hh + h] / (g_nsum[tg*Hh + h] + 1e-16f);
    float c1 = (float)g_deg[n] * att;
    int base = n*Dd + lane*4;
    float4 o1, o2, o3;
    o1.x = c1*ax;       o1.y = c1*ay;       o1.z = c1*az;       o1.w = c1*aw;
    o2.x = c1*ax*ax;    o2.y = c1*ay*ay;    o2.z = c1*az*az;    o2.w = c1*aw*aw;
    o3.x = signed_cbrt(c1*ax*ax*ax);
    o3.y = signed_cbrt(c1*ay*ay*ay);
    o3.z = signed_cbrt(c1*az*az*az);
    o3.w = signed_cbrt(c1*aw*aw*aw);
    *(float4*)(g_aggX[0] + base) = o1;
    *(float4*)(g_aggX[1] + base) = o2;
    *(float4*)(g_aggX[2] + base) = o3;
}

// ---------------- gating + gelu ----------------
__global__ void k_gate() {
    int warp = threadIdx.x >> 5, lane = threadIdx.x & 31;
    int n = blockIdx.x*4 + warp;
    if (n >= Nn) return;
    int base = n*Dd + lane*4;
    float4 res = make_float4(0.f, 0.f, 0.f, 0.f);
    #pragma unroll
    for (int k = 0; k < Kk; k++) {
        float4 f = *(const float4*)(g_front[k] + base);
        float4 t = *(const float4*)(g_tail[k] + base);
        float p = f.x*t.x + f.y*t.y + f.z*t.z + f.w*t.w;
        p = warp_sum(p);
        float tk = 1.f / (1.f + expf(-p));
        float4 a = *(const float4*)(g_aggm[k] + base);
        res.x += tk*a.x; res.y += tk*a.y; res.z += tk*a.z; res.w += tk*a.w;
    }
    float4 ho;
    ho.x = 0.5f*res.x*(1.f + erff(res.x*0.7071067811865475f));
    ho.y = 0.5f*res.y*(1.f + erff(res.y*0.7071067811865475f));
    ho.z = 0.5f*res.z*(1.f + erff(res.z*0.7071067811865475f));
    ho.w = 0.5f*res.w*(1.f + erff(res.w*0.7071067811865475f));
    *(float4*)(g_hb + base) = ho;
}

// ---------------- skip + layernorm ----------------
__global__ void k_final(const float* __restrict__ X, const int* __restrict__ ntype,
                        const float* __restrict__ skip, const float* __restrict__ lng,
                        const float* __restrict__ lnb, float* __restrict__ out)
{
    int warp = threadIdx.x >> 5, lane = threadIdx.x & 31;
    int n = blockIdx.x*4 + warp;
    if (n >= Nn) return;
    int t = ntype[n];
    float alpha = 1.f / (1.f + expf(-skip[t]));
    int base = n*Dd + lane*4;
    float4 x  = *(const float4*)(X + base);
    float4 tr = *(const float4*)(g_trans + base);
    float4 y;
    y.x = tr.x*alpha + x.x*(1.f - alpha);
    y.y = tr.y*alpha + x.y*(1.f - alpha);
    y.z = tr.z*alpha + x.z*(1.f - alpha);
    y.w = tr.w*alpha + x.w*(1.f - alpha);
    float mu = warp_sum(y.x + y.y + y.z + y.w) * (1.f/128.f);
    float4 d = make_float4(y.x - mu, y.y - mu, y.z - mu, y.w - mu);
    float var = warp_sum(d.x*d.x + d.y*d.y + d.z*d.z + d.w*d.w) * (1.f/128.f);
    float rstd = rsqrtf(var + 1e-5f);
    int gi = t*Dd + lane*4;
    float4 g = *(const float4*)(lng + gi);
    float4 b = *(const float4*)(lnb + gi);
    float4 o;
    o.x = d.x*rstd*g.x + b.x;
    o.y = d.y*rstd*g.y + b.y;
    o.z = d.z*rstd*g.z + b.z;
    o.w = d.w*rstd*g.w + b.w;
    *(float4*)(out + base) = o;
}

// ---------------- launch ----------------
extern "C" void kernel_launch(void* const* d_in, const int* in_sizes, int n_in,
                              void* d_out, int out_size)
{
    const float* meta = (const float*)d_in[0];
    const int*   ntype = (const int*)d_in[1];
    const int*   ei    = (const int*)d_in[2];
    const int*   et    = (const int*)d_in[3];
    // d_in[4] = edge_time (unused)
    const float* qw = (const float*)d_in[5],  *qb = (const float*)d_in[6];
    const float* kw = (const float*)d_in[7],  *kb = (const float*)d_in[8];
    const float* vw = (const float*)d_in[9],  *vb = (const float*)d_in[10];
    const float* aw = (const float*)d_in[11], *ab = (const float*)d_in[12];
    const float* rpri = (const float*)d_in[13];
    const float* ratt = (const float*)d_in[14];
    const float* rmsg = (const float*)d_in[15];
    const float* WMk  = (const float*)d_in[16];
    const float* Wak  = (const float*)d_in[17];
    const float* Wq   = (const float*)d_in[18], *bq  = (const float*)d_in[19];
    const float* Wkl  = (const float*)d_in[20], *bkl = (const float*)d_in[21];
    const float* skp  = (const float*)d_in[22];
    const float* lng  = (const float*)d_in[23], *lnb = (const float*)d_in[24];
    float* out = (float*)d_out;

    k_init<<<(Nn*Hh + 255)/256, 256>>>();
    k_hist<<<(Nn + 255)/256, 256>>>(ntype);
    k_offsets<<<1, 1>>>();
    k_scatter<<<(Nn + 255)/256, 256>>>(ntype);

    k_gemm_wc<<<dim3(2, 1, 3), 256>>>(Wq, Wak);
    k_bc<<<3, 128>>>(bq, Wak);

    k_gemm_qkv<<<dim3(NPAD/64, 1, 3), 256>>>(meta, qw, qb, kw, kb, vw, vb);

    k_edge_logits<<<Ee/4, 128>>>(ei, et, ratt, rpri);
    k_edge_exp<<<(Ee*Hh + 255)/256, 256>>>(ei);
    k_msg<<<Nn/4, 128>>>(ei, et, rmsg);

    k_gemm_aggm<<<dim3((Nn + 63)/64, 1, 3), 256>>>(WMk);
    k_gemm_front<<<dim3((Nn + 63)/64, 1, 3), 256>>>(meta);
    k_gemm_tail<<<dim3((Nn + 63)/64, 1, 3), 256>>>(Wkl, bkl);

    k_gate<<<Nn/4, 128>>>();
    k_gemm_a<<<dim3(NPAD/64, 1, 1), 256>>>(aw, ab);
    k_final<<<Nn/4, 128>>>(meta, ntype, skp, lng, lnb, out);
}

// round 8
// speedup vs baseline: 1.0490x; 1.0420x over previous
#include <cuda_runtime.h>
#include <cuda_bf16.h>
#include <stdint.h>
#include <math.h>

#define Nn 40000
#define Ee 320000
#define Dd 128
#define Hh 4
#define Tt 3
#define Rr 5
#define Kk 3
#define DKk 32
#define NPAD (Nn + 64*Tt)
#define ND (Nn*Dd)

// ---------------- scratch (static device globals; no allocation) ----------------
__device__ float g_qn[ND], g_kn[ND], g_vn[ND];
__device__ float g_ebuf[Ee*Hh];
__device__ float g_nmax[Nn*Hh], g_nsum[Nn*Hh];
__device__ int   g_deg[Nn];
__device__ float g_aggX[Kk][ND];     // moments; overwritten in-place with t*aggX by k_gate
__device__ float g_V[Kk][ND];        // V_k = X @ P_k
__device__ float g_hb[ND];           // gelu(res)
__device__ float g_trans[ND];
__device__ int   g_perm[NPAD], g_hist[Tt], g_cursor[Tt], g_offA[Tt+1];
__device__ float g_Wc[Kk][Dd*Dd], g_bc[Kk][Dd];
__device__ float g_T1[Kk][Dd*Dd], g_P[Kk][Dd*Dd];
__device__ float g_u[Kk][Dd], g_w[Kk][Dd], g_s[Kk];

// ---------------- helpers ----------------
__device__ __forceinline__ void atomicMaxFloat(float* addr, float v) {
    if (v >= 0.f) atomicMax((int*)addr, __float_as_int(v));
    else          atomicMin((unsigned int*)addr, __float_as_uint(v));
}

__device__ __forceinline__ float warp_sum(float v) {
    v += __shfl_xor_sync(0xffffffffu, v, 16);
    v += __shfl_xor_sync(0xffffffffu, v, 8);
    v += __shfl_xor_sync(0xffffffffu, v, 4);
    v += __shfl_xor_sync(0xffffffffu, v, 2);
    v += __shfl_xor_sync(0xffffffffu, v, 1);
    return v;
}

__device__ __forceinline__ float signed_cbrt(float z) {
    return (z == 0.f) ? 0.f : copysignf(cbrtf(fabsf(z) + 1e-18f), z);
}

__device__ __forceinline__ void split_bf16(float x, __nv_bfloat16& h, __nv_bfloat16& l) {
    h = __float2bfloat16(x);
    l = __float2bfloat16(x - __bfloat162float(h));
}

#define MMA_BF16(c, a0, a1, a2, a3, b0, b1) \
    asm volatile("mma.sync.aligned.m16n8k16.row.col.f32.bf16.bf16.f32 " \
        "{%0,%1,%2,%3}, {%4,%5,%6,%7}, {%8,%9}, {%0,%1,%2,%3};" \
        : "+f"((c)[0]), "+f"((c)[1]), "+f"((c)[2]), "+f"((c)[3]) \
        : "r"(a0), "r"(a1), "r"(a2), "r"(a3), "r"(b0), "r"(b1))

// ---------------- setup ----------------
__global__ void k_init(const int* __restrict__ ntype) {
    int i = blockIdx.x * blockDim.x + threadIdx.x;
    if (i < Nn*Hh) { g_nmax[i] = __int_as_float(0xff800000); g_nsum[i] = 0.f; }
    if (i < Nn) { g_deg[i] = 0; atomicAdd(&g_hist[ntype[i]], 1); }
    if (i < NPAD) g_perm[i] = -1;
    if (i < Tt)   g_cursor[i] = 0;
}

__global__ void k_offsets() {
    int off = 0;
    for (int t = 0; t < Tt; t++) { g_offA[t] = off; off += ((g_hist[t] + 63) & ~63); g_hist[t] = 0; }
    g_offA[Tt] = off;
}

__global__ void k_scatter(const int* __restrict__ ntype) {
    int n = blockIdx.x * blockDim.x + threadIdx.x;
    if (n < Nn) {
        int t = ntype[n];
        int p = atomicAdd(&g_cursor[t], 1);
        g_perm[g_offA[t] + p] = n;
    }
}

// ---------------- small prep kernels (fp32 exact) ----------------
// C = A @ B  (all 128x128 row-major), z-batched
__global__ void k_ab(float* __restrict__ C, const float* __restrict__ A,
                     const float* __restrict__ B, int aStrideZ, int bStrideZ) {
    int i = blockIdx.x, z = blockIdx.z, j = threadIdx.x;
    const float* a = A + z*aStrideZ + i*Dd;
    const float* b = B + z*bStrideZ;
    float s = 0.f;
    #pragma unroll 8
    for (int d = 0; d < Dd; d++) s += a[d] * b[d*Dd + j];
    C[z*Dd*Dd + i*Dd + j] = s;
}

// C = A @ B^T  (row-dot of A row i with B row j), z-batched
__global__ void k_abT(float* __restrict__ C, const float* __restrict__ A,
                      const float* __restrict__ B, int aStrideZ, int bStrideZ) {
    int i = blockIdx.x, z = blockIdx.z, j = threadIdx.x;
    const float* a = A + z*aStrideZ + i*Dd;
    const float* b = B + z*bStrideZ + j*Dd;
    float s = 0.f;
    #pragma unroll 8
    for (int d = 0; d < Dd; d++) s += a[d] * b[d];
    C[z*Dd*Dd + i*Dd + j] = s;
}

__global__ void k_bc(const float* __restrict__ bq, const float* __restrict__ Wak) {
    int k = blockIdx.x, o = threadIdx.x;
    float s = 0.f;
    for (int j = 0; j < Dd; j++) s += bq[j] * Wak[k*Dd*Dd + j*Dd + o];
    g_bc[k][o] = s;
}

// u_k = Wc_k @ bkl ; y = Wkl @ bc_k ; w_k = WMk_k @ y ; s_k = bc_k . bkl
__global__ void k_vecs(const float* __restrict__ Wkl, const float* __restrict__ bkl,
                       const float* __restrict__ WMk) {
    __shared__ float y[Dd];
    int k = blockIdx.x, i = threadIdx.x;
    float u = 0.f, yy = 0.f;
    for (int d = 0; d < Dd; d++) {
        u  += g_Wc[k][i*Dd + d] * bkl[d];
        yy += Wkl[i*Dd + d] * g_bc[k][d];
    }
    g_u[k][i] = u;
    y[i] = yy;
    __syncthreads();
    float w = 0.f;
    for (int j = 0; j < Dd; j++) w += WMk[k*Dd*Dd + i*Dd + j] * y[j];
    g_w[k][i] = w;
    if (i == 0) {
        float s = 0.f;
        for (int d = 0; d < Dd; d++) s += g_bc[k][d] * bkl[d];
        g_s[k] = s;
    }
}

// ---------- bf16 3-term tensor-core GEMM core: [64 rows] x [128 out], K=128 ----------
// 256 threads = 8 warps (4 M x 2 N). Warp tile 16x64. mma m16n8k16 bf16, fp32 acc.
// A staged once per source (hi/lo bf16, stride 136 halves -> word stride 68 == 4 mod 32,
// conflict-free). B staged per 16-k chunk, transposed blocked layout:
// [16 nblk][8 n][24 halves] -> word stride 12 == 12 mod 32, conflict-free frag loads.
#define AS 136

struct GemmSM {
    __nv_bfloat16 Ah[64*AS], Al[64*AS];     // 17408 B each
    __nv_bfloat16 Bh[16*8*24], Bl[16*8*24]; // 6144 B each
    int rowNode[64];
};

__device__ __forceinline__ void gemm_stage_rows(GemmSM* s, int row0, int rowlimit,
                                                const int* perm) {
    int tid = threadIdx.x;
    if (tid < 64) {
        int gr = row0 + tid;
        int nd = (gr < rowlimit) ? (perm ? perm[gr] : gr) : -1;
        s->rowNode[tid] = nd;
    }
}

__device__ __forceinline__ void gemm_stage_A(GemmSM* s, const float* __restrict__ X) {
    int tid = threadIdx.x;
    int m = tid & 63, q = tid >> 6;
    int node = s->rowNode[m];
    __nv_bfloat162* Ah2 = (__nv_bfloat162*)s->Ah;
    __nv_bfloat162* Al2 = (__nv_bfloat162*)s->Al;
    int wbase = m*(AS/2) + q*16;
    if (node >= 0) {
        const float4* src = (const float4*)(X + node*Dd + q*32);
        #pragma unroll
        for (int j = 0; j < 8; j++) {
            float4 v = src[j];
            __nv_bfloat16 h0,l0,h1,l1,h2,l2,h3,l3;
            split_bf16(v.x, h0, l0); split_bf16(v.y, h1, l1);
            split_bf16(v.z, h2, l2); split_bf16(v.w, h3, l3);
            Ah2[wbase + j*2]     = __nv_bfloat162(h0, h1);
            Ah2[wbase + j*2 + 1] = __nv_bfloat162(h2, h3);
            Al2[wbase + j*2]     = __nv_bfloat162(l0, l1);
            Al2[wbase + j*2 + 1] = __nv_bfloat162(l2, l3);
        }
    } else {
        __nv_bfloat162 z2 = __nv_bfloat162(__nv_bfloat16(0.f), __nv_bfloat16(0.f));
        #pragma unroll
        for (int j = 0; j < 8; j++) {
            Ah2[wbase + j*2] = z2; Ah2[wbase + j*2 + 1] = z2;
            Al2[wbase + j*2] = z2; Al2[wbase + j*2 + 1] = z2;
        }
    }
}

// Accumulate C += A_tile @ W (W row-major [128 k][128 n]) into c[8][4].
__device__ __forceinline__ void gemm_accum(GemmSM* s, const float* __restrict__ W,
                                           float c[8][4]) {
    int tid = threadIdx.x;
    int lane = tid & 31, wid = tid >> 5;
    int mw = wid >> 1, nw = wid & 1;
    int qr = lane >> 2, qt = lane & 3;
    const uint32_t* AhW = (const uint32_t*)s->Ah;
    const uint32_t* AlW = (const uint32_t*)s->Al;
    const uint32_t* BhW = (const uint32_t*)s->Bh;
    const uint32_t* BlW = (const uint32_t*)s->Bl;
    int row0w = (mw*16 + qr)*(AS/2);
    int row1w = row0w + 8*(AS/2);

    for (int ks = 0; ks < 8; ks++) {
        __syncthreads();
        {   // stage B chunk ks: rows ks*16..+15, transposed hi/lo
            int kr = tid & 15, bi = tid >> 4;
            const float4* src = (const float4*)(W + (ks*16 + kr)*Dd + bi*8);
            float4 v0 = src[0], v1 = src[1];
            float vv[8] = {v0.x, v0.y, v0.z, v0.w, v1.x, v1.y, v1.z, v1.w};
            #pragma unroll
            for (int g2 = 0; g2 < 8; g2++) {
                __nv_bfloat16 h, l;
                split_bf16(vv[g2], h, l);
                int idx = bi*192 + g2*24 + kr;
                s->Bh[idx] = h; s->Bl[idx] = l;
            }
        }
        __syncthreads();

        int kw = ks*8;
        uint32_t ah0 = AhW[row0w + kw + qt],     ah1 = AhW[row1w + kw + qt];
        uint32_t ah2 = AhW[row0w + kw + qt + 4], ah3 = AhW[row1w + kw + qt + 4];
        uint32_t al0 = AlW[row0w + kw + qt],     al1 = AlW[row1w + kw + qt];
        uint32_t al2 = AlW[row0w + kw + qt + 4], al3 = AlW[row1w + kw + qt + 4];
        #pragma unroll
        for (int nb = 0; nb < 8; nb++) {
            int bbase = (nw*8 + nb)*96 + qr*12;
            uint32_t bh0 = BhW[bbase + qt], bh1 = BhW[bbase + qt + 4];
            uint32_t bl0 = BlW[bbase + qt], bl1 = BlW[bbase + qt + 4];
            MMA_BF16(c[nb], ah0, ah1, ah2, ah3, bh0, bh1);
            MMA_BF16(c[nb], al0, al1, al2, al3, bh0, bh1);
            MMA_BF16(c[nb], ah0, ah1, ah2, ah3, bl0, bl1);
        }
    }
}

__device__ __forceinline__ void gemm_epilogue(GemmSM* s, float c[8][4],
                                              const float* bias, float* __restrict__ Y,
                                              bool gelu) {
    int tid = threadIdx.x;
    int lane = tid & 31, wid = tid >> 5;
    int mw = wid >> 1, nw = wid & 1;
    int qr = lane >> 2, qt = lane & 3;
    int nd0 = s->rowNode[mw*16 + qr];
    int nd1 = s->rowNode[mw*16 + qr + 8];
    #pragma unroll
    for (int nb = 0; nb < 8; nb++) {
        int col = nw*64 + nb*8 + 2*qt;
        float2 bv = make_float2(0.f, 0.f);
        if (bias) bv = *(const float2*)(bias + col);
        float o0 = c[nb][0] + bv.x, o1 = c[nb][1] + bv.y;
        float o2 = c[nb][2] + bv.x, o3 = c[nb][3] + bv.y;
        if (gelu) {
            o0 = 0.5f*o0*(1.f + erff(o0*0.7071067811865475f));
            o1 = 0.5f*o1*(1.f + erff(o1*0.7071067811865475f));
            o2 = 0.5f*o2*(1.f + erff(o2*0.7071067811865475f));
            o3 = 0.5f*o3*(1.f + erff(o3*0.7071067811865475f));
        }
        if (nd0 >= 0) *(float2*)(Y + nd0*Dd + col) = make_float2(o0, o1);
        if (nd1 >= 0) *(float2*)(Y + nd1*Dd + col) = make_float2(o2, o3);
    }
}

__device__ __forceinline__ void czero(float c[8][4]) {
    #pragma unroll
    for (int nb = 0; nb < 8; nb++) { c[nb][0]=0.f; c[nb][1]=0.f; c[nb][2]=0.f; c[nb][3]=0.f; }
}

// ---------------- GEMM kernels ----------------
// QKV fused: one A staging, three weight sets (per node type)
__global__ void k_gemm_qkv(const float* __restrict__ X,
                           const float* __restrict__ qw, const float* __restrict__ qb,
                           const float* __restrict__ kw, const float* __restrict__ kb,
                           const float* __restrict__ vw, const float* __restrict__ vb)
{
    __shared__ GemmSM sm;
    int row0 = blockIdx.x * 64;
    int t = 0;
    if (row0 >= g_offA[1]) t = 1;
    if (row0 >= g_offA[2]) t = 2;
    gemm_stage_rows(&sm, row0, NPAD, g_perm);
    __syncthreads();
    gemm_stage_A(&sm, X);
    float c[8][4];
    czero(c); gemm_accum(&sm, qw + t*Dd*Dd, c); gemm_epilogue(&sm, c, qb + t*Dd, g_qn, false);
    czero(c); gemm_accum(&sm, kw + t*Dd*Dd, c); gemm_epilogue(&sm, c, kb + t*Dd, g_kn, false);
    czero(c); gemm_accum(&sm, vw + t*Dd*Dd, c); gemm_epilogue(&sm, c, vb + t*Dd, g_vn, false);
}

// V_k = X @ P_k, fused over k
__global__ void k_gemm_V(const float* __restrict__ X) {
    __shared__ GemmSM sm;
    int row0 = blockIdx.x * 64;
    gemm_stage_rows(&sm, row0, Nn, nullptr);
    __syncthreads();
    gemm_stage_A(&sm, X);
    float c[8][4];
    #pragma unroll
    for (int z = 0; z < Kk; z++) {
        czero(c);
        gemm_accum(&sm, &g_P[z][0], c);
        gemm_epilogue(&sm, c, nullptr, &g_V[z][0], false);
    }
}

// res = sum_k (t_k*aggX_k) @ WMk_k, then gelu -> g_hb
__global__ void k_gemm_res(const float* __restrict__ WMk) {
    __shared__ GemmSM sm;
    int row0 = blockIdx.x * 64;
    gemm_stage_rows(&sm, row0, Nn, nullptr);
    float c[8][4];
    czero(c);
    #pragma unroll
    for (int z = 0; z < Kk; z++) {
        __syncthreads();                    // prior z's mma reads of A done
        gemm_stage_A(&sm, &g_aggX[z][0]);   // gate wrote t*aggX in place
        gemm_accum(&sm, WMk + z*Dd*Dd, c);
    }
    gemm_epilogue(&sm, c, nullptr, g_hb, true);
}

// trans = typed(gelu(res)) per node type
__global__ void k_gemm_a(const float* __restrict__ aw, const float* __restrict__ ab) {
    __shared__ GemmSM sm;
    int row0 = blockIdx.x * 64;
    int t = 0;
    if (row0 >= g_offA[1]) t = 1;
    if (row0 >= g_offA[2]) t = 2;
    gemm_stage_rows(&sm, row0, NPAD, g_perm);
    __syncthreads();
    gemm_stage_A(&sm, g_hb);
    float c[8][4];
    czero(c);
    gemm_accum(&sm, aw + t*Dd*Dd, c);
    gemm_epilogue(&sm, c, ab + t*Dd, g_trans, false);
}

// ---------------- edge phase ----------------
__global__ void k_edge_logits(const int* __restrict__ ei, const int* __restrict__ et,
                              const float* __restrict__ ratt, const float* __restrict__ rpri)
{
    __shared__ float sk[4][128];
    int warp = threadIdx.x >> 5, lane = threadIdx.x & 31;
    int e = blockIdx.x*4 + warp;
    if (e >= Ee) return;
    int s = ei[e], tg = ei[Ee + e], r = et[e];
    *(float4*)&sk[warp][lane*4] = ((const float4*)(g_kn + s*Dd))[lane];
    __syncwarp();
    int h = lane >> 3, m0 = (lane & 7) * 4;
    const float* A = ratt + (r*Hh + h)*(DKk*DKk) + m0;
    float ax = 0.f, ay = 0.f, az = 0.f, aw = 0.f;
    const float* kh = &sk[warp][h*32];
    #pragma unroll
    for (int d = 0; d < DKk; d++) {
        float kv = kh[d];
        float4 a = *(const float4*)(A + d*DKk);
        ax += kv*a.x; ay += kv*a.y; az += kv*a.z; aw += kv*a.w;
    }
    float4 qv = *(const float4*)(g_qn + tg*Dd + h*32 + m0);
    float p = ax*qv.x + ay*qv.y + az*qv.z + aw*qv.w;
    p += __shfl_xor_sync(0xffffffffu, p, 1);
    p += __shfl_xor_sync(0xffffffffu, p, 2);
    p += __shfl_xor_sync(0xffffffffu, p, 4);
    if ((lane & 7) == 0) {
        float logit = p * rpri[r*Hh + h] * 0.17677669529663687f;
        g_ebuf[e*Hh + h] = logit;
        atomicMaxFloat(&g_nmax[tg*Hh + h], logit);
    }
    if (lane == 0) atomicAdd(&g_deg[tg], 1);
}

__global__ void k_edge_exp(const int* __restrict__ ei) {
    int idx = blockIdx.x * blockDim.x + threadIdx.x;
    if (idx >= Ee*Hh) return;
    int e = idx >> 2, h = idx & 3;
    int tg = ei[Ee + e];
    float ex = expf(g_ebuf[idx] - g_nmax[tg*Hh + h]);
    g_ebuf[idx] = ex;
    atomicAdd(&g_nsum[tg*Hh + h], ex);
}

__global__ void k_msg(const int* __restrict__ ei, const int* __restrict__ et,
                      const float* __restrict__ rmsg)
{
    __shared__ float sv[4][128];
    int warp = threadIdx.x >> 5, lane = threadIdx.x & 31;
    int n = blockIdx.x*4 + warp;
    if (n >= Nn) return;
    int s = ei[n], tg = ei[Ee + n], r = et[n];
    *(float4*)&sv[warp][lane*4] = ((const float4*)(g_vn + s*Dd))[lane];
    __syncwarp();
    int h = lane >> 3, m0 = (lane & 7) * 4;
    const float* A = rmsg + (r*Hh + h)*(DKk*DKk) + m0;
    float ax = 0.f, ay = 0.f, az = 0.f, aw = 0.f;
    const float* vh = &sv[warp][h*32];
    #pragma unroll
    for (int d = 0; d < DKk; d++) {
        float vv = vh[d];
        float4 a = *(const float4*)(A + d*DKk);
        ax += vv*a.x; ay += vv*a.y; az += vv*a.z; aw += vv*a.w;
    }
    float att = g_ebuf[n*Hh + h] / (g_nsum[tg*Hh + h] + 1e-16f);
    float c1 = (float)g_deg[n] * att;
    int base = n*Dd + lane*4;
    float4 o1, o2, o3;
    o1.x = c1*ax;       o1.y = c1*ay;       o1.z = c1*az;       o1.w = c1*aw;
    o2.x = c1*ax*ax;    o2.y = c1*ay*ay;    o2.z = c1*az*az;    o2.w = c1*aw*aw;
    o3.x = signed_cbrt(c1*ax*ax*ax);
    o3.y = signed_cbrt(c1*ay*ay*ay);
    o3.z = signed_cbrt(c1*az*az*az);
    o3.w = signed_cbrt(c1*aw*aw*aw);
    *(float4*)(&g_aggX[0][0] + base) = o1;
    *(float4*)(&g_aggX[1][0] + base) = o2;
    *(float4*)(&g_aggX[2][0] + base) = o3;
}

// ---------------- gate: t_k = sigmoid(V.aggX + x.u + aggX.w + s); aggX *= t ----------------
__global__ void k_gate(const float* __restrict__ X) {
    int warp = threadIdx.x >> 5, lane = threadIdx.x & 31;
    int n = blockIdx.x*4 + warp;
    if (n >= Nn) return;
    int base = n*Dd + lane*4;
    float4 xv = *(const float4*)(X + base);
    #pragma unroll
    for (int k = 0; k < Kk; k++) {
        float4 vv = *(const float4*)(&g_V[k][0] + base);
        float4 ax = *(const float4*)(&g_aggX[k][0] + base);
        float4 uu = *(const float4*)(&g_u[k][0] + lane*4);
        float4 ww = *(const float4*)(&g_w[k][0] + lane*4);
        float p = vv.x*ax.x + vv.y*ax.y + vv.z*ax.z + vv.w*ax.w
                + xv.x*uu.x + xv.y*uu.y + xv.z*uu.z + xv.w*uu.w
                + ax.x*ww.x + ax.y*ww.y + ax.z*ww.z + ax.w*ww.w;
        p = warp_sum(p) + g_s[k];
        float tk = 1.f / (1.f + expf(-p));
        float4 o = make_float4(tk*ax.x, tk*ax.y, tk*ax.z, tk*ax.w);
        *(float4*)(&g_aggX[k][0] + base) = o;
    }
}

// ---------------- skip + layernorm ----------------
__global__ void k_final(const float* __restrict__ X, const int* __restrict__ ntype,
                        const float* __restrict__ skip, const float* __restrict__ lng,
                        const float* __restrict__ lnb, float* __restrict__ out)
{
    int warp = threadIdx.x >> 5, lane = threadIdx.x & 31;
    int n = blockIdx.x*4 + warp;
    if (n >= Nn) return;
    int t = ntype[n];
    float alpha = 1.f / (1.f + expf(-skip[t]));
    int base = n*Dd + lane*4;
    float4 x  = *(const float4*)(X + base);
    float4 tr = *(const float4*)(g_trans + base);
    float4 y;
    y.x = tr.x*alpha + x.x*(1.f - alpha);
    y.y = tr.y*alpha + x.y*(1.f - alpha);
    y.z = tr.z*alpha + x.z*(1.f - alpha);
    y.w = tr.w*alpha + x.w*(1.f - alpha);
    float mu = warp_sum(y.x + y.y + y.z + y.w) * (1.f/128.f);
    float4 d = make_float4(y.x - mu, y.y - mu, y.z - mu, y.w - mu);
    float var = warp_sum(d.x*d.x + d.y*d.y + d.z*d.z + d.w*d.w) * (1.f/128.f);
    float rstd = rsqrtf(var + 1e-5f);
    int gi = t*Dd + lane*4;
    float4 g = *(const float4*)(lng + gi);
    float4 b = *(const float4*)(lnb + gi);
    float4 o;
    o.x = d.x*rstd*g.x + b.x;
    o.y = d.y*rstd*g.y + b.y;
    o.z = d.z*rstd*g.z + b.z;
    o.w = d.w*rstd*g.w + b.w;
    *(float4*)(out + base) = o;
}

// ---------------- launch ----------------
extern "C" void kernel_launch(void* const* d_in, const int* in_sizes, int n_in,
                              void* d_out, int out_size)
{
    const float* meta = (const float*)d_in[0];
    const int*   ntype = (const int*)d_in[1];
    const int*   ei    = (const int*)d_in[2];
    const int*   et    = (const int*)d_in[3];
    // d_in[4] = edge_time (unused)
    const float* qw = (const float*)d_in[5],  *qb = (const float*)d_in[6];
    const float* kw = (const float*)d_in[7],  *kb = (const float*)d_in[8];
    const float* vw = (const float*)d_in[9],  *vb = (const float*)d_in[10];
    const float* aw = (const float*)d_in[11], *ab = (const float*)d_in[12];
    const float* rpri = (const float*)d_in[13];
    const float* ratt = (const float*)d_in[14];
    const float* rmsg = (const float*)d_in[15];
    const float* WMk  = (const float*)d_in[16];
    const float* Wak  = (const float*)d_in[17];
    const float* Wq   = (const float*)d_in[18], *bq  = (const float*)d_in[19];
    const float* Wkl  = (const float*)d_in[20], *bkl = (const float*)d_in[21];
    const float* skp  = (const float*)d_in[22];
    const float* lng  = (const float*)d_in[23], *lnb = (const float*)d_in[24];
    float* out = (float*)d_out;

    float* WcP = nullptr; float* T1P = nullptr; float* PP = nullptr;
    cudaGetSymbolAddress((void**)&WcP, g_Wc);
    cudaGetSymbolAddress((void**)&T1P, g_T1);
    cudaGetSymbolAddress((void**)&PP,  g_P);

    k_init<<<(Nn*Hh + 255)/256, 256>>>(ntype);                 // 1
    k_offsets<<<1, 1>>>();                                     // 2
    k_scatter<<<(Nn + 255)/256, 256>>>(ntype);                 // 3
    k_gemm_qkv<<<NPAD/64, 256>>>(meta, qw, qb, kw, kb, vw, vb);// 4  <- ncu slot

    k_ab<<<dim3(Dd,1,Kk), Dd>>>(WcP, Wq, Wak, 0, Dd*Dd);       // Wc_k = Wq @ Wak_k
    k_bc<<<Kk, Dd>>>(bq, Wak);                                  // bc_k = bq @ Wak_k
    k_abT<<<dim3(Dd,1,Kk), Dd>>>(T1P, WcP, Wkl, Dd*Dd, 0);     // T1_k = Wc_k @ Wkl^T
    k_abT<<<dim3(Dd,1,Kk), Dd>>>(PP, T1P, WMk, Dd*Dd, Dd*Dd);  // P_k  = T1_k @ WMk_k^T
    k_vecs<<<Kk, Dd>>>(Wkl, bkl, WMk);                          // u, w, s

    k_edge_logits<<<Ee/4, 128>>>(ei, et, ratt, rpri);
    k_edge_exp<<<(Ee*Hh + 255)/256, 256>>>(ei);
    k_msg<<<Nn/4, 128>>>(ei, et, rmsg);

    k_gemm_V<<<Nn/64, 256>>>(meta);
    k_gate<<<Nn/4, 128>>>(meta);
    k_gemm_res<<<Nn/64, 256>>>(WMk);
    k_gemm_a<<<NPAD/64, 256>>>(aw, ab);
    k_final<<<Nn/4, 128>>>(meta, ntype, skp, lng, lnb, out);
}

// round 9
// speedup vs baseline: 1.2139x; 1.1572x over previous
#include <cuda_runtime.h>
#include <cuda_bf16.h>
#include <stdint.h>
#include <math.h>

#define Nn 40000
#define Ee 320000
#define Dd 128
#define Hh 4
#define Tt 3
#define Rr 5
#define Kk 3
#define DKk 32
#define NPAD (Nn + 64*Tt)
#define ND (Nn*Dd)

// ---------------- scratch (static device globals; no allocation) ----------------
__device__ float g_qn[ND], g_kn[ND], g_vn[ND];
__device__ float g_ebuf[Ee*Hh];
__device__ float g_nmax[Nn*Hh], g_nsum[Nn*Hh];
__device__ int   g_deg[Nn];
__device__ float g_aggX[Kk][ND];     // moments; overwritten in-place with t*aggX by k_gate
__device__ float g_V[Kk][ND];        // V_k = X @ P_k
__device__ float g_hb[ND];           // gelu(res)
__device__ float g_trans[ND];
__device__ int   g_perm[NPAD], g_hist[Tt], g_cursor[Tt], g_offA[Tt+1];
__device__ float g_Wc[Kk][Dd*Dd], g_bc[Kk][Dd];
__device__ float g_T1[Kk][Dd*Dd], g_P[Kk][Dd*Dd];
__device__ float g_u[Kk][Dd], g_w[Kk][Dd], g_s[Kk];

// Prepped weights: bf16 hi/lo in MMA word layout.
// Per matrix: [8 kchunks][128 n][8 kpair-words] = 8192 uint32 (32 KB).
// Matrix ids: 0-2 qw_t, 3-5 kw_t, 6-8 vw_t, 9-11 aw_t, 12-14 P_k, 15-17 WMk_k.
#define NMAT 18
__device__ uint32_t g_Wbh[NMAT*8192];
__device__ uint32_t g_Wbl[NMAT*8192];

// ---------------- helpers ----------------
__device__ __forceinline__ void atomicMaxFloat(float* addr, float v) {
    if (v >= 0.f) atomicMax((int*)addr, __float_as_int(v));
    else          atomicMin((unsigned int*)addr, __float_as_uint(v));
}

__device__ __forceinline__ float warp_sum(float v) {
    v += __shfl_xor_sync(0xffffffffu, v, 16);
    v += __shfl_xor_sync(0xffffffffu, v, 8);
    v += __shfl_xor_sync(0xffffffffu, v, 4);
    v += __shfl_xor_sync(0xffffffffu, v, 2);
    v += __shfl_xor_sync(0xffffffffu, v, 1);
    return v;
}

__device__ __forceinline__ float signed_cbrt(float z) {
    return (z == 0.f) ? 0.f : copysignf(cbrtf(fabsf(z) + 1e-18f), z);
}

__device__ __forceinline__ void split_bf16(float x, __nv_bfloat16& h, __nv_bfloat16& l) {
    h = __float2bfloat16(x);
    l = __float2bfloat16(x - __bfloat162float(h));
}

__device__ __forceinline__ uint32_t pack_bf16x2(__nv_bfloat16 lo16, __nv_bfloat16 hi16) {
    return (uint32_t)__bfloat16_as_ushort(lo16) | ((uint32_t)__bfloat16_as_ushort(hi16) << 16);
}

#define MMA_BF16(c, a0, a1, a2, a3, b0, b1) \
    asm volatile("mma.sync.aligned.m16n8k16.row.col.f32.bf16.bf16.f32 " \
        "{%0,%1,%2,%3}, {%4,%5,%6,%7}, {%8,%9}, {%0,%1,%2,%3};" \
        : "+f"((c)[0]), "+f"((c)[1]), "+f"((c)[2]), "+f"((c)[3]) \
        : "r"(a0), "r"(a1), "r"(a2), "r"(a3), "r"(b0), "r"(b1))

// ---------------- weight prep: fp32 [128k][128n] -> word layout hi/lo ----------------
// Chunk ks: word(n, j) = bf16x2( W[ks*16+2j][n], W[ks*16+2j+1][n] ), j=0..7.
__device__ __forceinline__ void wprep_chunk(const float* __restrict__ W, int mat, int ks) {
    int tid = threadIdx.x;
    int n = tid >> 1, half = tid & 1;
    uint32_t outh[4], outl[4];
    #pragma unroll
    for (int jj = 0; jj < 4; jj++) {
        int j = half*4 + jj;
        int k0 = ks*16 + 2*j;
        float a = W[k0*Dd + n], b = W[(k0+1)*Dd + n];
        __nv_bfloat16 ha, la, hb, lb;
        split_bf16(a, ha, la);
        split_bf16(b, hb, lb);
        outh[jj] = pack_bf16x2(ha, hb);
        outl[jj] = pack_bf16x2(la, lb);
    }
    int base = mat*8192 + ks*1024 + n*8 + half*4;
    *(uint4*)(g_Wbh + base) = make_uint4(outh[0], outh[1], outh[2], outh[3]);
    *(uint4*)(g_Wbl + base) = make_uint4(outl[0], outl[1], outl[2], outl[3]);
}

// ---------------- setup (init + hist + input-weight prep, one launch) ----------------
__global__ void k_init(const int* __restrict__ ntype,
                       const float* __restrict__ qw, const float* __restrict__ kw,
                       const float* __restrict__ vw, const float* __restrict__ aw,
                       const float* __restrict__ WMk) {
    int i = blockIdx.x * blockDim.x + threadIdx.x;
    if (i < Nn*Hh) { g_nmax[i] = __int_as_float(0xff800000); g_nsum[i] = 0.f; }
    if (i < Nn) { g_deg[i] = 0; atomicAdd(&g_hist[ntype[i]], 1); }
    if (i < NPAD) g_perm[i] = -1;
    if (i < Tt)   g_cursor[i] = 0;
    // weight prep: 15 matrices x 8 chunks = 120 blocks
    if (blockIdx.x < 120) {
        int m = blockIdx.x >> 3, ks = blockIdx.x & 7;
        const float* srcs[5] = {qw, kw, vw, aw, WMk};
        const float* src = srcs[m/3] + (m%3)*Dd*Dd;
        int dstMat = (m < 12) ? m : (15 + m - 12);
        wprep_chunk(src, dstMat, ks);
    }
}

__global__ void k_offsets() {
    int off = 0;
    for (int t = 0; t < Tt; t++) { g_offA[t] = off; off += ((g_hist[t] + 63) & ~63); g_hist[t] = 0; }
    g_offA[Tt] = off;
}

__global__ void k_scatter(const int* __restrict__ ntype) {
    int n = blockIdx.x * blockDim.x + threadIdx.x;
    if (n < Nn) {
        int t = ntype[n];
        int p = atomicAdd(&g_cursor[t], 1);
        g_perm[g_offA[t] + p] = n;
    }
}

__global__ void k_wprep(const float* __restrict__ W, int dstBase) {
    wprep_chunk(W + blockIdx.z*Dd*Dd, dstBase + blockIdx.z, blockIdx.x);
}

// ---------------- small prep kernels (fp32 exact) ----------------
__global__ void k_ab(float* __restrict__ C, const float* __restrict__ A,
                     const float* __restrict__ B, int aStrideZ, int bStrideZ) {
    int i = blockIdx.x, z = blockIdx.z, j = threadIdx.x;
    const float* a = A + z*aStrideZ + i*Dd;
    const float* b = B + z*bStrideZ;
    float s = 0.f;
    #pragma unroll 8
    for (int d = 0; d < Dd; d++) s += a[d] * b[d*Dd + j];
    C[z*Dd*Dd + i*Dd + j] = s;
}

__global__ void k_abT(float* __restrict__ C, const float* __restrict__ A,
                      const float* __restrict__ B, int aStrideZ, int bStrideZ) {
    int i = blockIdx.x, z = blockIdx.z, j = threadIdx.x;
    const float* a = A + z*aStrideZ + i*Dd;
    const float* b = B + z*bStrideZ + j*Dd;
    float s = 0.f;
    #pragma unroll 8
    for (int d = 0; d < Dd; d++) s += a[d] * b[d];
    C[z*Dd*Dd + i*Dd + j] = s;
}

__global__ void k_bc(const float* __restrict__ bq, const float* __restrict__ Wak) {
    int k = blockIdx.x, o = threadIdx.x;
    float s = 0.f;
    for (int j = 0; j < Dd; j++) s += bq[j] * Wak[k*Dd*Dd + j*Dd + o];
    g_bc[k][o] = s;
}

__global__ void k_vecs(const float* __restrict__ Wkl, const float* __restrict__ bkl,
                       const float* __restrict__ WMk) {
    __shared__ float y[Dd];
    int k = blockIdx.x, i = threadIdx.x;
    float u = 0.f, yy = 0.f;
    for (int d = 0; d < Dd; d++) {
        u  += g_Wc[k][i*Dd + d] * bkl[d];
        yy += Wkl[i*Dd + d] * g_bc[k][d];
    }
    g_u[k][i] = u;
    y[i] = yy;
    __syncthreads();
    float w = 0.f;
    for (int j = 0; j < Dd; j++) w += WMk[k*Dd*Dd + i*Dd + j] * y[j];
    g_w[k][i] = w;
    if (i == 0) {
        float s = 0.f;
        for (int d = 0; d < Dd; d++) s += g_bc[k][d] * bkl[d];
        g_s[k] = s;
    }
}

// ---------- bf16 3-term tensor-core GEMM core: [64 rows] x [128 out], K=128 ----------
// 256 threads = 8 warps (4 M x 2 N). Warp tile 16x64. mma m16n8k16 bf16, fp32 acc.
// A staged hi/lo bf16 (word stride 68 -> conflict-free). B copied from prepped gmem
// (uint4) into padded layout stride 12 words (all 32 banks distinct for frag loads).
#define AS 136

struct GemmSM {
    __nv_bfloat16 Ah[64*AS], Al[64*AS];     // 17408 B each
    uint32_t Bh[128*12], Bl[128*12];        // 6144 B each
    int rowNode[64];
};

__device__ __forceinline__ void gemm_stage_rows(GemmSM* s, int row0, int rowlimit,
                                                const int* perm) {
    int tid = threadIdx.x;
    if (tid < 64) {
        int gr = row0 + tid;
        int nd = (gr < rowlimit) ? (perm ? perm[gr] : gr) : -1;
        s->rowNode[tid] = nd;
    }
}

__device__ __forceinline__ void gemm_stage_A(GemmSM* s, const float* __restrict__ X) {
    int tid = threadIdx.x;
    int m = tid & 63, q = tid >> 6;
    int node = s->rowNode[m];
    __nv_bfloat162* Ah2 = (__nv_bfloat162*)s->Ah;
    __nv_bfloat162* Al2 = (__nv_bfloat162*)s->Al;
    int wbase = m*(AS/2) + q*16;
    if (node >= 0) {
        const float4* src = (const float4*)(X + node*Dd + q*32);
        #pragma unroll
        for (int j = 0; j < 8; j++) {
            float4 v = src[j];
            __nv_bfloat16 h0,l0,h1,l1,h2,l2,h3,l3;
            split_bf16(v.x, h0, l0); split_bf16(v.y, h1, l1);
            split_bf16(v.z, h2, l2); split_bf16(v.w, h3, l3);
            Ah2[wbase + j*2]     = __nv_bfloat162(h0, h1);
            Ah2[wbase + j*2 + 1] = __nv_bfloat162(h2, h3);
            Al2[wbase + j*2]     = __nv_bfloat162(l0, l1);
            Al2[wbase + j*2 + 1] = __nv_bfloat162(l2, l3);
        }
    } else {
        __nv_bfloat162 z2 = __nv_bfloat162(__nv_bfloat16(0.f), __nv_bfloat16(0.f));
        #pragma unroll
        for (int j = 0; j < 8; j++) {
            Ah2[wbase + j*2] = z2; Ah2[wbase + j*2 + 1] = z2;
            Al2[wbase + j*2] = z2; Al2[wbase + j*2 + 1] = z2;
        }
    }
}

// Accumulate C += A_tile @ W_mat into c[8][4], W from prepped gmem (matrix id).
__device__ __forceinline__ void gemm_accum(GemmSM* s, int mat, float c[8][4]) {
    int tid = threadIdx.x;
    int lane = tid & 31, wid = tid >> 5;
    int mw = wid >> 1, nw = wid & 1;
    int qr = lane >> 2, qt = lane & 3;
    const uint32_t* AhW = (const uint32_t*)s->Ah;
    const uint32_t* AlW = (const uint32_t*)s->Al;
    int row0w = (mw*16 + qr)*(AS/2);
    int row1w = row0w + 8*(AS/2);
    int n = tid >> 1, half = tid & 1;
    const uint4* srcH = (const uint4*)(g_Wbh + mat*8192);
    const uint4* srcL = (const uint4*)(g_Wbl + mat*8192);
    int cpSrc = n*2 + half;
    int cpDst = n*12 + half*4;

    for (int ks = 0; ks < 8; ks++) {
        __syncthreads();
        *(uint4*)(s->Bh + cpDst) = srcH[ks*256 + cpSrc];
        *(uint4*)(s->Bl + cpDst) = srcL[ks*256 + cpSrc];
        __syncthreads();

        int kw = ks*8;
        uint32_t ah0 = AhW[row0w + kw + qt],     ah1 = AhW[row1w + kw + qt];
        uint32_t ah2 = AhW[row0w + kw + qt + 4], ah3 = AhW[row1w + kw + qt + 4];
        uint32_t al0 = AlW[row0w + kw + qt],     al1 = AlW[row1w + kw + qt];
        uint32_t al2 = AlW[row0w + kw + qt + 4], al3 = AlW[row1w + kw + qt + 4];
        #pragma unroll
        for (int nb = 0; nb < 8; nb++) {
            int bbase = (nw*64 + nb*8 + qr)*12;
            uint32_t bh0 = s->Bh[bbase + qt], bh1 = s->Bh[bbase + qt + 4];
            uint32_t bl0 = s->Bl[bbase + qt], bl1 = s->Bl[bbase + qt + 4];
            MMA_BF16(c[nb], ah0, ah1, ah2, ah3, bh0, bh1);
            MMA_BF16(c[nb], al0, al1, al2, al3, bh0, bh1);
            MMA_BF16(c[nb], ah0, ah1, ah2, ah3, bl0, bl1);
        }
    }
}

__device__ __forceinline__ void gemm_epilogue(GemmSM* s, float c[8][4],
                                              const float* bias, float* __restrict__ Y,
                                              bool gelu) {
    int tid = threadIdx.x;
    int lane = tid & 31, wid = tid >> 5;
    int mw = wid >> 1, nw = wid & 1;
    int qr = lane >> 2, qt = lane & 3;
    int nd0 = s->rowNode[mw*16 + qr];
    int nd1 = s->rowNode[mw*16 + qr + 8];
    #pragma unroll
    for (int nb = 0; nb < 8; nb++) {
        int col = nw*64 + nb*8 + 2*qt;
        float2 bv = make_float2(0.f, 0.f);
        if (bias) bv = *(const float2*)(bias + col);
        float o0 = c[nb][0] + bv.x, o1 = c[nb][1] + bv.y;
        float o2 = c[nb][2] + bv.x, o3 = c[nb][3] + bv.y;
        if (gelu) {
            o0 = 0.5f*o0*(1.f + erff(o0*0.7071067811865475f));
            o1 = 0.5f*o1*(1.f + erff(o1*0.7071067811865475f));
            o2 = 0.5f*o2*(1.f + erff(o2*0.7071067811865475f));
            o3 = 0.5f*o3*(1.f + erff(o3*0.7071067811865475f));
        }
        if (nd0 >= 0) *(float2*)(Y + nd0*Dd + col) = make_float2(o0, o1);
        if (nd1 >= 0) *(float2*)(Y + nd1*Dd + col) = make_float2(o2, o3);
    }
}

__device__ __forceinline__ void czero(float c[8][4]) {
    #pragma unroll
    for (int nb = 0; nb < 8; nb++) { c[nb][0]=0.f; c[nb][1]=0.f; c[nb][2]=0.f; c[nb][3]=0.f; }
}

// ---------------- GEMM kernels ----------------
__global__ void k_gemm_qkv(const float* __restrict__ X,
                           const float* __restrict__ qb, const float* __restrict__ kb,
                           const float* __restrict__ vb)
{
    __shared__ GemmSM sm;
    int row0 = blockIdx.x * 64;
    int t = 0;
    if (row0 >= g_offA[1]) t = 1;
    if (row0 >= g_offA[2]) t = 2;
    gemm_stage_rows(&sm, row0, NPAD, g_perm);
    __syncthreads();
    gemm_stage_A(&sm, X);
    float c[8][4];
    czero(c); gemm_accum(&sm, 0 + t, c); gemm_epilogue(&sm, c, qb + t*Dd, g_qn, false);
    czero(c); gemm_accum(&sm, 3 + t, c); gemm_epilogue(&sm, c, kb + t*Dd, g_kn, false);
    czero(c); gemm_accum(&sm, 6 + t, c); gemm_epilogue(&sm, c, vb + t*Dd, g_vn, false);
}

__global__ void k_gemm_V(const float* __restrict__ X) {
    __shared__ GemmSM sm;
    int row0 = blockIdx.x * 64;
    gemm_stage_rows(&sm, row0, Nn, nullptr);
    __syncthreads();
    gemm_stage_A(&sm, X);
    float c[8][4];
    #pragma unroll
    for (int z = 0; z < Kk; z++) {
        czero(c);
        gemm_accum(&sm, 12 + z, c);
        gemm_epilogue(&sm, c, nullptr, &g_V[z][0], false);
    }
}

__global__ void k_gemm_res() {
    __shared__ GemmSM sm;
    int row0 = blockIdx.x * 64;
    gemm_stage_rows(&sm, row0, Nn, nullptr);
    float c[8][4];
    czero(c);
    #pragma unroll
    for (int z = 0; z < Kk; z++) {
        __syncthreads();
        gemm_stage_A(&sm, &g_aggX[z][0]);
        gemm_accum(&sm, 15 + z, c);
    }
    gemm_epilogue(&sm, c, nullptr, g_hb, true);
}

__global__ void k_gemm_a(const float* __restrict__ ab) {
    __shared__ GemmSM sm;
    int row0 = blockIdx.x * 64;
    int t = 0;
    if (row0 >= g_offA[1]) t = 1;
    if (row0 >= g_offA[2]) t = 2;
    gemm_stage_rows(&sm, row0, NPAD, g_perm);
    __syncthreads();
    gemm_stage_A(&sm, g_hb);
    float c[8][4];
    czero(c);
    gemm_accum(&sm, 9 + t, c);
    gemm_epilogue(&sm, c, ab + t*Dd, g_trans, false);
}

// ---------------- edge phase ----------------
__global__ void k_edge_logits(const int* __restrict__ ei, const int* __restrict__ et,
                              const float* __restrict__ ratt, const float* __restrict__ rpri)
{
    __shared__ float sk[4][128];
    int warp = threadIdx.x >> 5, lane = threadIdx.x & 31;
    int e = blockIdx.x*4 + warp;
    if (e >= Ee) return;
    int s = ei[e], tg = ei[Ee + e], r = et[e];
    *(float4*)&sk[warp][lane*4] = ((const float4*)(g_kn + s*Dd))[lane];
    __syncwarp();
    int h = lane >> 3, m0 = (lane & 7) * 4;
    const float* A = ratt + (r*Hh + h)*(DKk*DKk) + m0;
    float ax = 0.f, ay = 0.f, az = 0.f, aw = 0.f;
    const float* kh = &sk[warp][h*32];
    #pragma unroll
    for (int d = 0; d < DKk; d++) {
        float kv = kh[d];
        float4 a = *(const float4*)(A + d*DKk);
        ax += kv*a.x; ay += kv*a.y; az += kv*a.z; aw += kv*a.w;
    }
    float4 qv = *(const float4*)(g_qn + tg*Dd + h*32 + m0);
    float p = ax*qv.x + ay*qv.y + az*qv.z + aw*qv.w;
    p += __shfl_xor_sync(0xffffffffu, p, 1);
    p += __shfl_xor_sync(0xffffffffu, p, 2);
    p += __shfl_xor_sync(0xffffffffu, p, 4);
    if ((lane & 7) == 0) {
        float logit = p * rpri[r*Hh + h] * 0.17677669529663687f;
        g_ebuf[e*Hh + h] = logit;
        atomicMaxFloat(&g_nmax[tg*Hh + h], logit);
    }
    if (lane == 0) atomicAdd(&g_deg[tg], 1);
}

__global__ void k_edge_exp(const int* __restrict__ ei) {
    int idx = blockIdx.x * blockDim.x + threadIdx.x;
    if (idx >= Ee*Hh) return;
    int e = idx >> 2, h = idx & 3;
    int tg = ei[Ee + e];
    float ex = expf(g_ebuf[idx] - g_nmax[tg*Hh + h]);
    g_ebuf[idx] = ex;
    atomicAdd(&g_nsum[tg*Hh + h], ex);
}

__global__ void k_msg(const int* __restrict__ ei, const int* __restrict__ et,
                      const float* __restrict__ rmsg)
{
    __shared__ float sv[4][128];
    int warp = threadIdx.x >> 5, lane = threadIdx.x & 31;
    int n = blockIdx.x*4 + warp;
    if (n >= Nn) return;
    int s = ei[n], tg = ei[Ee + n], r = et[n];
    *(float4*)&sv[warp][lane*4] = ((const float4*)(g_vn + s*Dd))[lane];
    __syncwarp();
    int h = lane >> 3, m0 = (lane & 7) * 4;
    const float* A = rmsg + (r*Hh + h)*(DKk*DKk) + m0;
    float ax = 0.f, ay = 0.f, az = 0.f, aw = 0.f;
    const float* vh = &sv[warp][h*32];
    #pragma unroll
    for (int d = 0; d < DKk; d++) {
        float vv = vh[d];
        float4 a = *(const float4*)(A + d*DKk);
        ax += vv*a.x; ay += vv*a.y; az += vv*a.z; aw += vv*a.w;
    }
    float att = g_ebuf[n*Hh + h] / (g_nsum[tg*Hh + h] + 1e-16f);
    float c1 = (float)g_deg[n] * att;
    int base = n*Dd + lane*4;
    float4 o1, o2, o3;
    o1.x = c1*ax;       o1.y = c1*ay;       o1.z = c1*az;       o1.w = c1*aw;
    o2.x = c1*ax*ax;    o2.y = c1*ay*ay;    o2.z = c1*az*az;    o2.w = c1*aw*aw;
    o3.x = signed_cbrt(c1*ax*ax*ax);
    o3.y = signed_cbrt(c1*ay*ay*ay);
    o3.z = signed_cbrt(c1*az*az*az);
    o3.w = signed_cbrt(c1*aw*aw*aw);
    *(float4*)(&g_aggX[0][0] + base) = o1;
    *(float4*)(&g_aggX[1][0] + base) = o2;
    *(float4*)(&g_aggX[2][0] + base) = o3;
}

// ---------------- gate ----------------
__global__ void k_gate(const float* __restrict__ X) {
    int warp = threadIdx.x >> 5, lane = threadIdx.x & 31;
    int n = blockIdx.x*4 + warp;
    if (n >= Nn) return;
    int base = n*Dd + lane*4;
    float4 xv = *(const float4*)(X + base);
    #pragma unroll
    for (int k = 0; k < Kk; k++) {
        float4 vv = *(const float4*)(&g_V[k][0] + base);
        float4 ax = *(const float4*)(&g_aggX[k][0] + base);
        float4 uu = *(const float4*)(&g_u[k][0] + lane*4);
        float4 ww = *(const float4*)(&g_w[k][0] + lane*4);
        float p = vv.x*ax.x + vv.y*ax.y + vv.z*ax.z + vv.w*ax.w
                + xv.x*uu.x + xv.y*uu.y + xv.z*uu.z + xv.w*uu.w
                + ax.x*ww.x + ax.y*ww.y + ax.z*ww.z + ax.w*ww.w;
        p = warp_sum(p) + g_s[k];
        float tk = 1.f / (1.f + expf(-p));
        float4 o = make_float4(tk*ax.x, tk*ax.y, tk*ax.z, tk*ax.w);
        *(float4*)(&g_aggX[k][0] + base) = o;
    }
}

// ---------------- skip + layernorm ----------------
__global__ void k_final(const float* __restrict__ X, const int* __restrict__ ntype,
                        const float* __restrict__ skip, const float* __restrict__ lng,
                        const float* __restrict__ lnb, float* __restrict__ out)
{
    int warp = threadIdx.x >> 5, lane = threadIdx.x & 31;
    int n = blockIdx.x*4 + warp;
    if (n >= Nn) return;
    int t = ntype[n];
    float alpha = 1.f / (1.f + expf(-skip[t]));
    int base = n*Dd + lane*4;
    float4 x  = *(const float4*)(X + base);
    float4 tr = *(const float4*)(g_trans + base);
    float4 y;
    y.x = tr.x*alpha + x.x*(1.f - alpha);
    y.y = tr.y*alpha + x.y*(1.f - alpha);
    y.z = tr.z*alpha + x.z*(1.f - alpha);
    y.w = tr.w*alpha + x.w*(1.f - alpha);
    float mu = warp_sum(y.x + y.y + y.z + y.w) * (1.f/128.f);
    float4 d = make_float4(y.x - mu, y.y - mu, y.z - mu, y.w - mu);
    float var = warp_sum(d.x*d.x + d.y*d.y + d.z*d.z + d.w*d.w) * (1.f/128.f);
    float rstd = rsqrtf(var + 1e-5f);
    int gi = t*Dd + lane*4;
    float4 g = *(const float4*)(lng + gi);
    float4 b = *(const float4*)(lnb + gi);
    float4 o;
    o.x = d.x*rstd*g.x + b.x;
    o.y = d.y*rstd*g.y + b.y;
    o.z = d.z*rstd*g.z + b.z;
    o.w = d.w*rstd*g.w + b.w;
    *(float4*)(out + base) = o;
}

// ---------------- launch ----------------
extern "C" void kernel_launch(void* const* d_in, const int* in_sizes, int n_in,
                              void* d_out, int out_size)
{
    const float* meta = (const float*)d_in[0];
    const int*   ntype = (const int*)d_in[1];
    const int*   ei    = (const int*)d_in[2];
    const int*   et    = (const int*)d_in[3];
    // d_in[4] = edge_time (unused)
    const float* qw = (const float*)d_in[5],  *qb = (const float*)d_in[6];
    const float* kw = (const float*)d_in[7],  *kb = (const float*)d_in[8];
    const float* vw = (const float*)d_in[9],  *vb = (const float*)d_in[10];
    const float* aw = (const float*)d_in[11], *ab = (const float*)d_in[12];
    const float* rpri = (const float*)d_in[13];
    const float* ratt = (const float*)d_in[14];
    const float* rmsg = (const float*)d_in[15];
    const float* WMk  = (const float*)d_in[16];
    const float* Wak  = (const float*)d_in[17];
    const float* Wq   = (const float*)d_in[18], *bq  = (const float*)d_in[19];
    const float* Wkl  = (const float*)d_in[20], *bkl = (const float*)d_in[21];
    const float* skp  = (const float*)d_in[22];
    const float* lng  = (const float*)d_in[23], *lnb = (const float*)d_in[24];
    float* out = (float*)d_out;

    float* WcP = nullptr; float* T1P = nullptr; float* PP = nullptr;
    cudaGetSymbolAddress((void**)&WcP, g_Wc);
    cudaGetSymbolAddress((void**)&T1P, g_T1);
    cudaGetSymbolAddress((void**)&PP,  g_P);

    k_init<<<(Nn*Hh + 255)/256, 256>>>(ntype, qw, kw, vw, aw, WMk);  // 1
    k_offsets<<<1, 1>>>();                                           // 2
    k_scatter<<<(Nn + 255)/256, 256>>>(ntype);                       // 3
    k_gemm_qkv<<<NPAD/64, 256>>>(meta, qb, kb, vb);                  // 4 <- ncu slot

    k_ab<<<dim3(Dd,1,Kk), Dd>>>(WcP, Wq, Wak, 0, Dd*Dd);       // Wc_k = Wq @ Wak_k
    k_bc<<<Kk, Dd>>>(bq, Wak);                                  // bc_k = bq @ Wak_k
    k_abT<<<dim3(Dd,1,Kk), Dd>>>(T1P, WcP, Wkl, Dd*Dd, 0);     // T1_k = Wc_k @ Wkl^T
    k_abT<<<dim3(Dd,1,Kk), Dd>>>(PP, T1P, WMk, Dd*Dd, Dd*Dd);  // P_k  = T1_k @ WMk_k^T
    k_wprep<<<dim3(8,1,Kk), 256>>>(PP, 12);                     // P -> bf16 word layout
    k_vecs<<<Kk, Dd>>>(Wkl, bkl, WMk);                          // u, w, s

    k_edge_logits<<<Ee/4, 128>>>(ei, et, ratt, rpri);
    k_edge_exp<<<(Ee*Hh + 255)/256, 256>>>(ei);
    k_msg<<<Nn/4, 128>>>(ei, et, rmsg);

    k_gemm_V<<<Nn/64, 256>>>(meta);
    k_gate<<<Nn/4, 128>>>(meta);
    k_gemm_res<<<Nn/64, 256>>>();
    k_gemm_a<<<NPAD/64, 256>>>(ab);
    k_final<<<Nn/4, 128>>>(meta, ntype, skp, lng, lnb, out);
}

// round 10
// speedup vs baseline: 1.2590x; 1.0372x over previous
#include <cuda_runtime.h>
#include <cuda_bf16.h>
#include <stdint.h>
#include <math.h>

#define Nn 40000
#define Ee 320000
#define Dd 128
#define Hh 4
#define Tt 3
#define Rr 5
#define Kk 3
#define DKk 32
#define NPAD (Nn + 64*Tt)
#define ND (Nn*Dd)

// ---------------- scratch (static device globals; no allocation) ----------------
__device__ float g_qn[ND], g_kn[ND], g_vn[ND];
__device__ float g_ebuf[Ee*Hh];
__device__ float g_nmax[Nn*Hh], g_nsum[Nn*Hh];
__device__ int   g_deg[Nn];
__device__ float g_aggX[Kk][ND];     // moments; overwritten in-place with t*aggX by k_gate
__device__ float g_V[Kk][ND];        // V_k = X @ P_k
__device__ float g_hb[ND];           // gelu(res)
__device__ float g_trans[ND];
__device__ int   g_perm[NPAD], g_hist[Tt], g_cursor[Tt], g_offA[Tt+1];
__device__ float g_Wc[Kk][Dd*Dd], g_bc[Kk][Dd];
__device__ float g_T1[Kk][Dd*Dd], g_P[Kk][Dd*Dd];
__device__ float g_u[Kk][Dd], g_w[Kk][Dd], g_s[Kk];

// Prepped weights: bf16 hi/lo in MMA word layout.
// Per matrix: [8 kchunks][128 n][8 kpair-words] = 8192 uint32 (32 KB).
// Matrix ids: 0-2 qw_t, 3-5 kw_t, 6-8 vw_t, 9-11 aw_t, 12-14 P_k, 15-17 WMk_k.
#define NMAT 18
__device__ uint32_t g_Wbh[NMAT*8192];
__device__ uint32_t g_Wbl[NMAT*8192];

// ---------------- helpers ----------------
__device__ __forceinline__ void atomicMaxFloat(float* addr, float v) {
    if (v >= 0.f) atomicMax((int*)addr, __float_as_int(v));
    else          atomicMin((unsigned int*)addr, __float_as_uint(v));
}

__device__ __forceinline__ float warp_sum(float v) {
    v += __shfl_xor_sync(0xffffffffu, v, 16);
    v += __shfl_xor_sync(0xffffffffu, v, 8);
    v += __shfl_xor_sync(0xffffffffu, v, 4);
    v += __shfl_xor_sync(0xffffffffu, v, 2);
    v += __shfl_xor_sync(0xffffffffu, v, 1);
    return v;
}

__device__ __forceinline__ float signed_cbrt(float z) {
    return (z == 0.f) ? 0.f : copysignf(cbrtf(fabsf(z) + 1e-18f), z);
}

__device__ __forceinline__ void split_bf16(float x, __nv_bfloat16& h, __nv_bfloat16& l) {
    h = __float2bfloat16(x);
    l = __float2bfloat16(x - __bfloat162float(h));
}

__device__ __forceinline__ uint32_t pack_bf16x2(__nv_bfloat16 lo16, __nv_bfloat16 hi16) {
    return (uint32_t)__bfloat16_as_ushort(lo16) | ((uint32_t)__bfloat16_as_ushort(hi16) << 16);
}

#define MMA_BF16(c, a0, a1, a2, a3, b0, b1) \
    asm volatile("mma.sync.aligned.m16n8k16.row.col.f32.bf16.bf16.f32 " \
        "{%0,%1,%2,%3}, {%4,%5,%6,%7}, {%8,%9}, {%0,%1,%2,%3};" \
        : "+f"((c)[0]), "+f"((c)[1]), "+f"((c)[2]), "+f"((c)[3]) \
        : "r"(a0), "r"(a1), "r"(a2), "r"(a3), "r"(b0), "r"(b1))

__device__ __forceinline__ void ldsm_x4(uint32_t& r0, uint32_t& r1, uint32_t& r2,
                                        uint32_t& r3, uint32_t saddr) {
    asm volatile("ldmatrix.sync.aligned.m8n8.x4.shared.b16 {%0,%1,%2,%3}, [%4];"
                 : "=r"(r0), "=r"(r1), "=r"(r2), "=r"(r3) : "r"(saddr));
}

// ---------------- weight prep: fp32 [128k][128n] -> word layout hi/lo ----------------
// Chunk ks: word(n, j) = bf16x2( W[ks*16+2j][n], W[ks*16+2j+1][n] ), j=0..7.
__device__ __forceinline__ void wprep_chunk(const float* __restrict__ W, int mat, int ks) {
    int tid = threadIdx.x;
    int n = tid >> 1, half = tid & 1;
    uint32_t outh[4], outl[4];
    #pragma unroll
    for (int jj = 0; jj < 4; jj++) {
        int j = half*4 + jj;
        int k0 = ks*16 + 2*j;
        float a = W[k0*Dd + n], b = W[(k0+1)*Dd + n];
        __nv_bfloat16 ha, la, hb, lb;
        split_bf16(a, ha, la);
        split_bf16(b, hb, lb);
        outh[jj] = pack_bf16x2(ha, hb);
        outl[jj] = pack_bf16x2(la, lb);
    }
    int base = mat*8192 + ks*1024 + n*8 + half*4;
    *(uint4*)(g_Wbh + base) = make_uint4(outh[0], outh[1], outh[2], outh[3]);
    *(uint4*)(g_Wbl + base) = make_uint4(outl[0], outl[1], outl[2], outl[3]);
}

// ---------------- setup (init + hist + input-weight prep, one launch) ----------------
__global__ void k_init(const int* __restrict__ ntype,
                       const float* __restrict__ qw, const float* __restrict__ kw,
                       const float* __restrict__ vw, const float* __restrict__ aw,
                       const float* __restrict__ WMk) {
    int i = blockIdx.x * blockDim.x + threadIdx.x;
    if (i < Nn*Hh) { g_nmax[i] = __int_as_float(0xff800000); g_nsum[i] = 0.f; }
    if (i < Nn) { g_deg[i] = 0; atomicAdd(&g_hist[ntype[i]], 1); }
    if (i < NPAD) g_perm[i] = -1;
    if (i < Tt)   g_cursor[i] = 0;
    if (blockIdx.x < 120) {
        int m = blockIdx.x >> 3, ks = blockIdx.x & 7;
        const float* srcs[5] = {qw, kw, vw, aw, WMk};
        const float* src = srcs[m/3] + (m%3)*Dd*Dd;
        int dstMat = (m < 12) ? m : (15 + m - 12);
        wprep_chunk(src, dstMat, ks);
    }
}

__global__ void k_offsets() {
    int off = 0;
    for (int t = 0; t < Tt; t++) { g_offA[t] = off; off += ((g_hist[t] + 63) & ~63); g_hist[t] = 0; }
    g_offA[Tt] = off;
}

__global__ void k_scatter(const int* __restrict__ ntype) {
    int n = blockIdx.x * blockDim.x + threadIdx.x;
    if (n < Nn) {
        int t = ntype[n];
        int p = atomicAdd(&g_cursor[t], 1);
        g_perm[g_offA[t] + p] = n;
    }
}

__global__ void k_wprep(const float* __restrict__ W, int dstBase) {
    wprep_chunk(W + blockIdx.z*Dd*Dd, dstBase + blockIdx.z, blockIdx.x);
}

// ---------------- small prep kernels (fp32 exact) ----------------
__global__ void k_ab(float* __restrict__ C, const float* __restrict__ A,
                     const float* __restrict__ B, int aStrideZ, int bStrideZ) {
    int i = blockIdx.x, z = blockIdx.z, j = threadIdx.x;
    const float* a = A + z*aStrideZ + i*Dd;
    const float* b = B + z*bStrideZ;
    float s = 0.f;
    #pragma unroll 8
    for (int d = 0; d < Dd; d++) s += a[d] * b[d*Dd + j];
    C[z*Dd*Dd + i*Dd + j] = s;
}

__global__ void k_abT(float* __restrict__ C, const float* __restrict__ A,
                      const float* __restrict__ B, int aStrideZ, int bStrideZ) {
    int i = blockIdx.x, z = blockIdx.z, j = threadIdx.x;
    const float* a = A + z*aStrideZ + i*Dd;
    const float* b = B + z*bStrideZ + j*Dd;
    float s = 0.f;
    #pragma unroll 8
    for (int d = 0; d < Dd; d++) s += a[d] * b[d];
    C[z*Dd*Dd + i*Dd + j] = s;
}

__global__ void k_bc(const float* __restrict__ bq, const float* __restrict__ Wak) {
    int k = blockIdx.x, o = threadIdx.x;
    float s = 0.f;
    for (int j = 0; j < Dd; j++) s += bq[j] * Wak[k*Dd*Dd + j*Dd + o];
    g_bc[k][o] = s;
}

__global__ void k_vecs(const float* __restrict__ Wkl, const float* __restrict__ bkl,
                       const float* __restrict__ WMk) {
    __shared__ float y[Dd];
    int k = blockIdx.x, i = threadIdx.x;
    float u = 0.f, yy = 0.f;
    for (int d = 0; d < Dd; d++) {
        u  += g_Wc[k][i*Dd + d] * bkl[d];
        yy += Wkl[i*Dd + d] * g_bc[k][d];
    }
    g_u[k][i] = u;
    y[i] = yy;
    __syncthreads();
    float w = 0.f;
    for (int j = 0; j < Dd; j++) w += WMk[k*Dd*Dd + i*Dd + j] * y[j];
    g_w[k][i] = w;
    if (i == 0) {
        float s = 0.f;
        for (int d = 0; d < Dd; d++) s += g_bc[k][d] * bkl[d];
        g_s[k] = s;
    }
}

// ---------- bf16 3-term tensor-core GEMM core: [64 rows] x [128 out], K=128 ----------
// 256 threads = 8 warps (4 M x 2 N). Warp tile 16x64. mma m16n8k16 bf16, fp32 acc.
// Fragments loaded via ldmatrix.x4 (conflict-free strides: A 68 words, B 12 words).
#define AS 136

struct GemmSM {
    __nv_bfloat16 Ah[64*AS], Al[64*AS];     // 17408 B each
    uint32_t Bh[128*12], Bl[128*12];        // 6144 B each
    int rowNode[64];
};

__device__ __forceinline__ void gemm_stage_rows(GemmSM* s, int row0, int rowlimit,
                                                const int* perm) {
    int tid = threadIdx.x;
    if (tid < 64) {
        int gr = row0 + tid;
        int nd = (gr < rowlimit) ? (perm ? perm[gr] : gr) : -1;
        s->rowNode[tid] = nd;
    }
}

__device__ __forceinline__ void gemm_stage_A(GemmSM* s, const float* __restrict__ X) {
    int tid = threadIdx.x;
    int m = tid & 63, q = tid >> 6;
    int node = s->rowNode[m];
    __nv_bfloat162* Ah2 = (__nv_bfloat162*)s->Ah;
    __nv_bfloat162* Al2 = (__nv_bfloat162*)s->Al;
    int wbase = m*(AS/2) + q*16;
    if (node >= 0) {
        const float4* src = (const float4*)(X + node*Dd + q*32);
        #pragma unroll
        for (int j = 0; j < 8; j++) {
            float4 v = src[j];
            __nv_bfloat16 h0,l0,h1,l1,h2,l2,h3,l3;
            split_bf16(v.x, h0, l0); split_bf16(v.y, h1, l1);
            split_bf16(v.z, h2, l2); split_bf16(v.w, h3, l3);
            Ah2[wbase + j*2]     = __nv_bfloat162(h0, h1);
            Ah2[wbase + j*2 + 1] = __nv_bfloat162(h2, h3);
            Al2[wbase + j*2]     = __nv_bfloat162(l0, l1);
            Al2[wbase + j*2 + 1] = __nv_bfloat162(l2, l3);
        }
    } else {
        __nv_bfloat162 z2 = __nv_bfloat162(__nv_bfloat16(0.f), __nv_bfloat16(0.f));
        #pragma unroll
        for (int j = 0; j < 8; j++) {
            Ah2[wbase + j*2] = z2; Ah2[wbase + j*2 + 1] = z2;
            Al2[wbase + j*2] = z2; Al2[wbase + j*2 + 1] = z2;
        }
    }
}

// Accumulate C += A_tile @ W_mat into c[8][4], W from prepped gmem (matrix id).
__device__ __forceinline__ void gemm_accum(GemmSM* s, int mat, float c[8][4]) {
    int tid = threadIdx.x;
    int lane = tid & 31, wid = tid >> 5;
    int mw = wid >> 1, nw = wid & 1;
    int lt = lane >> 3, lrow = lane & 7;
    int n = tid >> 1, half = tid & 1;
    const uint4* srcH = (const uint4*)(g_Wbh + mat*8192);
    const uint4* srcL = (const uint4*)(g_Wbl + mat*8192);
    int cpSrc = n*2 + half;
    int cpDst = n*12 + half*4;

    uint32_t aBaseH = (uint32_t)__cvta_generic_to_shared(s->Ah);
    uint32_t aBaseL = (uint32_t)__cvta_generic_to_shared(s->Al);
    uint32_t bBaseH = (uint32_t)__cvta_generic_to_shared(s->Bh);
    uint32_t bBaseL = (uint32_t)__cvta_generic_to_shared(s->Bl);

    // ldmatrix addresses: A tiles (a0: m+0/klo, a1: m+8/klo, a2: m+0/khi, a3: m+8/khi)
    int mrow = mw*16 + (lt & 1)*8 + lrow;
    uint32_t aOff = (uint32_t)((mrow*(AS/2) + (lt >> 1)*4) * 4);
    // B tiles per pair p: (b0(2p), b1(2p), b0(2p+1), b1(2p+1))
    uint32_t bOff[4];
    #pragma unroll
    for (int p = 0; p < 4; p++) {
        int ncol = nw*64 + (2*p + (lt >> 1))*8 + lrow;
        bOff[p] = (uint32_t)((ncol*12 + (lt & 1)*4) * 4);
    }

    for (int ks = 0; ks < 8; ks++) {
        __syncthreads();
        *(uint4*)(s->Bh + cpDst) = srcH[ks*256 + cpSrc];
        *(uint4*)(s->Bl + cpDst) = srcL[ks*256 + cpSrc];
        __syncthreads();

        uint32_t ah0,ah1,ah2,ah3, al0,al1,al2,al3;
        ldsm_x4(ah0, ah1, ah2, ah3, aBaseH + aOff + ks*32);
        ldsm_x4(al0, al1, al2, al3, aBaseL + aOff + ks*32);
        #pragma unroll
        for (int p = 0; p < 4; p++) {
            uint32_t bh0,bh1,bh2,bh3, bl0,bl1,bl2,bl3;
            ldsm_x4(bh0, bh1, bh2, bh3, bBaseH + bOff[p]);
            ldsm_x4(bl0, bl1, bl2, bl3, bBaseL + bOff[p]);
            MMA_BF16(c[2*p],   ah0,ah1,ah2,ah3, bh0, bh1);
            MMA_BF16(c[2*p],   al0,al1,al2,al3, bh0, bh1);
            MMA_BF16(c[2*p],   ah0,ah1,ah2,ah3, bl0, bl1);
            MMA_BF16(c[2*p+1], ah0,ah1,ah2,ah3, bh2, bh3);
            MMA_BF16(c[2*p+1], al0,al1,al2,al3, bh2, bh3);
            MMA_BF16(c[2*p+1], ah0,ah1,ah2,ah3, bl2, bl3);
        }
    }
}

__device__ __forceinline__ void gemm_epilogue(GemmSM* s, float c[8][4],
                                              const float* bias, float* __restrict__ Y,
                                              bool gelu) {
    int tid = threadIdx.x;
    int lane = tid & 31, wid = tid >> 5;
    int mw = wid >> 1, nw = wid & 1;
    int qr = lane >> 2, qt = lane & 3;
    int nd0 = s->rowNode[mw*16 + qr];
    int nd1 = s->rowNode[mw*16 + qr + 8];
    #pragma unroll
    for (int nb = 0; nb < 8; nb++) {
        int col = nw*64 + nb*8 + 2*qt;
        float2 bv = make_float2(0.f, 0.f);
        if (bias) bv = *(const float2*)(bias + col);
        float o0 = c[nb][0] + bv.x, o1 = c[nb][1] + bv.y;
        float o2 = c[nb][2] + bv.x, o3 = c[nb][3] + bv.y;
        if (gelu) {
            o0 = 0.5f*o0*(1.f + erff(o0*0.7071067811865475f));
            o1 = 0.5f*o1*(1.f + erff(o1*0.7071067811865475f));
            o2 = 0.5f*o2*(1.f + erff(o2*0.7071067811865475f));
            o3 = 0.5f*o3*(1.f + erff(o3*0.7071067811865475f));
        }
        if (nd0 >= 0) *(float2*)(Y + nd0*Dd + col) = make_float2(o0, o1);
        if (nd1 >= 0) *(float2*)(Y + nd1*Dd + col) = make_float2(o2, o3);
    }
}

__device__ __forceinline__ void czero(float c[8][4]) {
    #pragma unroll
    for (int nb = 0; nb < 8; nb++) { c[nb][0]=0.f; c[nb][1]=0.f; c[nb][2]=0.f; c[nb][3]=0.f; }
}

// ---------------- GEMM kernels ----------------
__global__ void k_gemm_qkv(const float* __restrict__ X,
                           const float* __restrict__ qb, const float* __restrict__ kb,
                           const float* __restrict__ vb)
{
    __shared__ GemmSM sm;
    int row0 = blockIdx.x * 64;
    int t = 0;
    if (row0 >= g_offA[1]) t = 1;
    if (row0 >= g_offA[2]) t = 2;
    gemm_stage_rows(&sm, row0, NPAD, g_perm);
    __syncthreads();
    gemm_stage_A(&sm, X);
    float c[8][4];
    czero(c); gemm_accum(&sm, 0 + t, c); gemm_epilogue(&sm, c, qb + t*Dd, g_qn, false);
    czero(c); gemm_accum(&sm, 3 + t, c); gemm_epilogue(&sm, c, kb + t*Dd, g_kn, false);
    czero(c); gemm_accum(&sm, 6 + t, c); gemm_epilogue(&sm, c, vb + t*Dd, g_vn, false);
}

__global__ void k_gemm_V(const float* __restrict__ X) {
    __shared__ GemmSM sm;
    int row0 = blockIdx.x * 64;
    gemm_stage_rows(&sm, row0, Nn, nullptr);
    __syncthreads();
    gemm_stage_A(&sm, X);
    float c[8][4];
    #pragma unroll
    for (int z = 0; z < Kk; z++) {
        czero(c);
        gemm_accum(&sm, 12 + z, c);
        gemm_epilogue(&sm, c, nullptr, &g_V[z][0], false);
    }
}

__global__ void k_gemm_res() {
    __shared__ GemmSM sm;
    int row0 = blockIdx.x * 64;
    gemm_stage_rows(&sm, row0, Nn, nullptr);
    float c[8][4];
    czero(c);
    #pragma unroll
    for (int z = 0; z < Kk; z++) {
        __syncthreads();
        gemm_stage_A(&sm, &g_aggX[z][0]);
        gemm_accum(&sm, 15 + z, c);
    }
    gemm_epilogue(&sm, c, nullptr, g_hb, true);
}

__global__ void k_gemm_a(const float* __restrict__ ab) {
    __shared__ GemmSM sm;
    int row0 = blockIdx.x * 64;
    int t = 0;
    if (row0 >= g_offA[1]) t = 1;
    if (row0 >= g_offA[2]) t = 2;
    gemm_stage_rows(&sm, row0, NPAD, g_perm);
    __syncthreads();
    gemm_stage_A(&sm, g_hb);
    float c[8][4];
    czero(c);
    gemm_accum(&sm, 9 + t, c);
    gemm_epilogue(&sm, c, ab + t*Dd, g_trans, false);
}

// ---------------- edge phase ----------------
__global__ void k_edge_logits(const int* __restrict__ ei, const int* __restrict__ et,
                              const float* __restrict__ ratt, const float* __restrict__ rpri)
{
    __shared__ float sk[4][128];
    int warp = threadIdx.x >> 5, lane = threadIdx.x & 31;
    int e = blockIdx.x*4 + warp;
    if (e >= Ee) return;
    int s = ei[e], tg = ei[Ee + e], r = et[e];
    *(float4*)&sk[warp][lane*4] = ((const float4*)(g_kn + s*Dd))[lane];
    __syncwarp();
    int h = lane >> 3, m0 = (lane & 7) * 4;
    const float* A = ratt + (r*Hh + h)*(DKk*DKk) + m0;
    float ax = 0.f, ay = 0.f, az = 0.f, aw = 0.f;
    const float* kh = &sk[warp][h*32];
    #pragma unroll
    for (int d = 0; d < DKk; d++) {
        float kv = kh[d];
        float4 a = *(const float4*)(A + d*DKk);
        ax += kv*a.x; ay += kv*a.y; az += kv*a.z; aw += kv*a.w;
    }
    float4 qv = *(const float4*)(g_qn + tg*Dd + h*32 + m0);
    float p = ax*qv.x + ay*qv.y + az*qv.z + aw*qv.w;
    p += __shfl_xor_sync(0xffffffffu, p, 1);
    p += __shfl_xor_sync(0xffffffffu, p, 2);
    p += __shfl_xor_sync(0xffffffffu, p, 4);
    if ((lane & 7) == 0) {
        float logit = p * rpri[r*Hh + h] * 0.17677669529663687f;
        g_ebuf[e*Hh + h] = logit;
        atomicMaxFloat(&g_nmax[tg*Hh + h], logit);
    }
    if (lane == 0) atomicAdd(&g_deg[tg], 1);
}

__global__ void k_edge_exp(const int* __restrict__ ei) {
    int idx = blockIdx.x * blockDim.x + threadIdx.x;
    if (idx >= Ee*Hh) return;
    int e = idx >> 2, h = idx & 3;
    int tg = ei[Ee + e];
    float ex = expf(g_ebuf[idx] - g_nmax[tg*Hh + h]);
    g_ebuf[idx] = ex;
    atomicAdd(&g_nsum[tg*Hh + h], ex);
}

__global__ void k_msg(const int* __restrict__ ei, const int* __restrict__ et,
                      const float* __restrict__ rmsg)
{
    __shared__ float sv[4][128];
    int warp = threadIdx.x >> 5, lane = threadIdx.x & 31;
    int n = blockIdx.x*4 + warp;
    if (n >= Nn) return;
    int s = ei[n], tg = ei[Ee + n], r = et[n];
    *(float4*)&sv[warp][lane*4] = ((const float4*)(g_vn + s*Dd))[lane];
    __syncwarp();
    int h = lane >> 3, m0 = (lane & 7) * 4;
    const float* A = rmsg + (r*Hh + h)*(DKk*DKk) + m0;
    float ax = 0.f, ay = 0.f, az = 0.f, aw = 0.f;
    const float* vh = &sv[warp][h*32];
    #pragma unroll
    for (int d = 0; d < DKk; d++) {
        float vv = vh[d];
        float4 a = *(const float4*)(A + d*DKk);
        ax += vv*a.x; ay += vv*a.y; az += vv*a.z; aw += vv*a.w;
    }
    float att = g_ebuf[n*Hh + h] / (g_nsum[tg*Hh + h] + 1e-16f);
    float c1 = (float)g_deg[n] * att;
    int base = n*Dd + lane*4;
    float4 o1, o2, o3;
    o1.x = c1*ax;       o1.y = c1*ay;       o1.z = c1*az;       o1.w = c1*aw;
    o2.x = c1*ax*ax;    o2.y = c1*ay*ay;    o2.z = c1*az*az;    o2.w = c1*aw*aw;
    o3.x = signed_cbrt(c1*ax*ax*ax);
    o3.y = signed_cbrt(c1*ay*ay*ay);
    o3.z = signed_cbrt(c1*az*az*az);
    o3.w = signed_cbrt(c1*aw*aw*aw);
    *(float4*)(&g_aggX[0][0] + base) = o1;
    *(float4*)(&g_aggX[1][0] + base) = o2;
    *(float4*)(&g_aggX[2][0] + base) = o3;
}

// ---------------- gate ----------------
__global__ void k_gate(const float* __restrict__ X) {
    int warp = threadIdx.x >> 5, lane = threadIdx.x & 31;
    int n = blockIdx.x*4 + warp;
    if (n >= Nn) return;
    int base = n*Dd + lane*4;
    float4 xv = *(const float4*)(X + base);
    #pragma unroll
    for (int k = 0; k < Kk; k++) {
        float4 vv = *(const float4*)(&g_V[k][0] + base);
        float4 ax = *(const float4*)(&g_aggX[k][0] + base);
        float4 uu = *(const float4*)(&g_u[k][0] + lane*4);
        float4 ww = *(const float4*)(&g_w[k][0] + lane*4);
        float p = vv.x*ax.x + vv.y*ax.y + vv.z*ax.z + vv.w*ax.w
                + xv.x*uu.x + xv.y*uu.y + xv.z*uu.z + xv.w*uu.w
                + ax.x*ww.x + ax.y*ww.y + ax.z*ww.z + ax.w*ww.w;
        p = warp_sum(p) + g_s[k];
        float tk = 1.f / (1.f + expf(-p));
        float4 o = make_float4(tk*ax.x, tk*ax.y, tk*ax.z, tk*ax.w);
        *(float4*)(&g_aggX[k][0] + base) = o;
    }
}

// ---------------- skip + layernorm ----------------
__global__ void k_final(const float* __restrict__ X, const int* __restrict__ ntype,
                        const float* __restrict__ skip, const float* __restrict__ lng,
                        const float* __restrict__ lnb, float* __restrict__ out)
{
    int warp = threadIdx.x >> 5, lane = threadIdx.x & 31;
    int n = blockIdx.x*4 + warp;
    if (n >= Nn) return;
    int t = ntype[n];
    float alpha = 1.f / (1.f + expf(-skip[t]));
    int base = n*Dd + lane*4;
    float4 x  = *(const float4*)(X + base);
    float4 tr = *(const float4*)(g_trans + base);
    float4 y;
    y.x = tr.x*alpha + x.x*(1.f - alpha);
    y.y = tr.y*alpha + x.y*(1.f - alpha);
    y.z = tr.z*alpha + x.z*(1.f - alpha);
    y.w = tr.w*alpha + x.w*(1.f - alpha);
    float mu = warp_sum(y.x + y.y + y.z + y.w) * (1.f/128.f);
    float4 d = make_float4(y.x - mu, y.y - mu, y.z - mu, y.w - mu);
    float var = warp_sum(d.x*d.x + d.y*d.y + d.z*d.z + d.w*d.w) * (1.f/128.f);
    float rstd = rsqrtf(var + 1e-5f);
    int gi = t*Dd + lane*4;
    float4 g = *(const float4*)(lng + gi);
    float4 b = *(const float4*)(lnb + gi);
    float4 o;
    o.x = d.x*rstd*g.x + b.x;
    o.y = d.y*rstd*g.y + b.y;
    o.z = d.z*rstd*g.z + b.z;
    o.w = d.w*rstd*g.w + b.w;
    *(float4*)(out + base) = o;
}

// ---------------- launch ----------------
extern "C" void kernel_launch(void* const* d_in, const int* in_sizes, int n_in,
                              void* d_out, int out_size)
{
    const float* meta = (const float*)d_in[0];
    const int*   ntype = (const int*)d_in[1];
    const int*   ei    = (const int*)d_in[2];
    const int*   et    = (const int*)d_in[3];
    // d_in[4] = edge_time (unused)
    const float* qw = (const float*)d_in[5],  *qb = (const float*)d_in[6];
    const float* kw = (const float*)d_in[7],  *kb = (const float*)d_in[8];
    const float* vw = (const float*)d_in[9],  *vb = (const float*)d_in[10];
    const float* aw = (const float*)d_in[11], *ab = (const float*)d_in[12];
    const float* rpri = (const float*)d_in[13];
    const float* ratt = (const float*)d_in[14];
    const float* rmsg = (const float*)d_in[15];
    const float* WMk  = (const float*)d_in[16];
    const float* Wak  = (const float*)d_in[17];
    const float* Wq   = (const float*)d_in[18], *bq  = (const float*)d_in[19];
    const float* Wkl  = (const float*)d_in[20], *bkl = (const float*)d_in[21];
    const float* skp  = (const float*)d_in[22];
    const float* lng  = (const float*)d_in[23], *lnb = (const float*)d_in[24];
    float* out = (float*)d_out;

    float* WcP = nullptr; float* T1P = nullptr; float* PP = nullptr;
    cudaGetSymbolAddress((void**)&WcP, g_Wc);
    cudaGetSymbolAddress((void**)&T1P, g_T1);
    cudaGetSymbolAddress((void**)&PP,  g_P);

    k_init<<<(Nn*Hh + 255)/256, 256>>>(ntype, qw, kw, vw, aw, WMk);  // 1
    k_offsets<<<1, 1>>>();                                           // 2
    k_scatter<<<(Nn + 255)/256, 256>>>(ntype);                       // 3
    k_gemm_qkv<<<NPAD/64, 256>>>(meta, qb, kb, vb);                  // 4 <- ncu slot

    k_ab<<<dim3(Dd,1,Kk), Dd>>>(WcP, Wq, Wak, 0, Dd*Dd);       // Wc_k = Wq @ Wak_k
    k_bc<<<Kk, Dd>>>(bq, Wak);                                  // bc_k = bq @ Wak_k
    k_abT<<<dim3(Dd,1,Kk), Dd>>>(T1P, WcP, Wkl, Dd*Dd, 0);     // T1_k = Wc_k @ Wkl^T
    k_abT<<<dim3(Dd,1,Kk), Dd>>>(PP, T1P, WMk, Dd*Dd, Dd*Dd);  // P_k  = T1_k @ WMk_k^T
    k_wprep<<<dim3(8,1,Kk), 256>>>(PP, 12);                     // P -> bf16 word layout
    k_vecs<<<Kk, Dd>>>(Wkl, bkl, WMk);                          // u, w, s

    k_edge_logits<<<Ee/4, 128>>>(ei, et, ratt, rpri);
    k_edge_exp<<<(Ee*Hh + 255)/256, 256>>>(ei);
    k_msg<<<Nn/4, 128>>>(ei, et, rmsg);

    k_gemm_V<<<Nn/64, 256>>>(meta);
    k_gate<<<Nn/4, 128>>>(meta);
    k_gemm_res<<<Nn/64, 256>>>();
    k_gemm_a<<<NPAD/64, 256>>>(ab);
    k_final<<<Nn/4, 128>>>(meta, ntype, skp, lng, lnb, out);
}

// round 11
// speedup vs baseline: 1.3018x; 1.0340x over previous
#include <cuda_runtime.h>
#include <cuda_bf16.h>
#include <stdint.h>
#include <math.h>

#define Nn 40000
#define Ee 320000
#define Dd 128
#define Hh 4
#define Tt 3
#define Rr 5
#define Kk 3
#define DKk 32
#define NPAD (Nn + 64*Tt)
#define ND (Nn*Dd)

// ---------------- scratch (static device globals; no allocation) ----------------
__device__ float g_qn[ND], g_kn[ND], g_vn[ND];
__device__ float g_ebuf[Ee*Hh];
__device__ float g_nmax[Nn*Hh], g_nsum[Nn*Hh];
__device__ int   g_deg[Nn];
__device__ float g_aggX[Kk][ND];     // moments; overwritten in-place with t*aggX by k_gate
__device__ float g_V[Kk][ND];        // V_k = X @ P_k
__device__ float g_hb[ND];           // gelu(res)
__device__ float g_trans[ND];
__device__ int   g_perm[NPAD], g_hist[Tt], g_cursor[Tt], g_offA[Tt+1];
__device__ float g_Wc[Kk][Dd*Dd], g_bc[Kk][Dd];
__device__ float g_T1[Kk][Dd*Dd], g_P[Kk][Dd*Dd];
__device__ float g_u[Kk][Dd], g_w[Kk][Dd], g_s[Kk];

// Prepped weights: bf16 hi/lo in MMA word layout.
// Per matrix: [8 kchunks][128 n][8 kpair-words] = 8192 uint32 (32 KB).
// Matrix ids: 0-2 qw_t, 3-5 kw_t, 6-8 vw_t, 9-11 aw_t, 12-14 P_k, 15-17 WMk_k.
#define NMAT 18
__device__ uint32_t g_Wbh[NMAT*8192];
__device__ uint32_t g_Wbl[NMAT*8192];

// ---------------- helpers ----------------
__device__ __forceinline__ void atomicMaxFloat(float* addr, float v) {
    if (v >= 0.f) atomicMax((int*)addr, __float_as_int(v));
    else          atomicMin((unsigned int*)addr, __float_as_uint(v));
}

__device__ __forceinline__ float warp_sum(float v) {
    v += __shfl_xor_sync(0xffffffffu, v, 16);
    v += __shfl_xor_sync(0xffffffffu, v, 8);
    v += __shfl_xor_sync(0xffffffffu, v, 4);
    v += __shfl_xor_sync(0xffffffffu, v, 2);
    v += __shfl_xor_sync(0xffffffffu, v, 1);
    return v;
}

__device__ __forceinline__ float signed_cbrt(float z) {
    return (z == 0.f) ? 0.f : copysignf(cbrtf(fabsf(z) + 1e-18f), z);
}

__device__ __forceinline__ void split_bf16(float x, __nv_bfloat16& h, __nv_bfloat16& l) {
    h = __float2bfloat16(x);
    l = __float2bfloat16(x - __bfloat162float(h));
}

__device__ __forceinline__ uint32_t pack_bf16x2(__nv_bfloat16 lo16, __nv_bfloat16 hi16) {
    return (uint32_t)__bfloat16_as_ushort(lo16) | ((uint32_t)__bfloat16_as_ushort(hi16) << 16);
}

#define MMA_BF16(c, a0, a1, a2, a3, b0, b1) \
    asm volatile("mma.sync.aligned.m16n8k16.row.col.f32.bf16.bf16.f32 " \
        "{%0,%1,%2,%3}, {%4,%5,%6,%7}, {%8,%9}, {%0,%1,%2,%3};" \
        : "+f"((c)[0]), "+f"((c)[1]), "+f"((c)[2]), "+f"((c)[3]) \
        : "r"(a0), "r"(a1), "r"(a2), "r"(a3), "r"(b0), "r"(b1))

__device__ __forceinline__ void ldsm_x4(uint32_t& r0, uint32_t& r1, uint32_t& r2,
                                        uint32_t& r3, uint32_t saddr) {
    asm volatile("ldmatrix.sync.aligned.m8n8.x4.shared.b16 {%0,%1,%2,%3}, [%4];"
                 : "=r"(r0), "=r"(r1), "=r"(r2), "=r"(r3) : "r"(saddr));
}

// ---------------- weight prep: fp32 [128k][128n] -> word layout hi/lo ----------------
__device__ __forceinline__ void wprep_chunk(const float* __restrict__ W, int mat, int ks) {
    int tid = threadIdx.x;
    int n = tid >> 1, half = tid & 1;
    uint32_t outh[4], outl[4];
    #pragma unroll
    for (int jj = 0; jj < 4; jj++) {
        int j = half*4 + jj;
        int k0 = ks*16 + 2*j;
        float a = W[k0*Dd + n], b = W[(k0+1)*Dd + n];
        __nv_bfloat16 ha, la, hb, lb;
        split_bf16(a, ha, la);
        split_bf16(b, hb, lb);
        outh[jj] = pack_bf16x2(ha, hb);
        outl[jj] = pack_bf16x2(la, lb);
    }
    int base = mat*8192 + ks*1024 + n*8 + half*4;
    *(uint4*)(g_Wbh + base) = make_uint4(outh[0], outh[1], outh[2], outh[3]);
    *(uint4*)(g_Wbl + base) = make_uint4(outl[0], outl[1], outl[2], outl[3]);
}

// ---------------- setup ----------------
__global__ void k_init(const int* __restrict__ ntype,
                       const float* __restrict__ qw, const float* __restrict__ kw,
                       const float* __restrict__ vw, const float* __restrict__ aw,
                       const float* __restrict__ WMk) {
    int i = blockIdx.x * blockDim.x + threadIdx.x;
    if (i < Nn*Hh) { g_nmax[i] = __int_as_float(0xff800000); g_nsum[i] = 0.f; }
    if (i < Nn) { g_deg[i] = 0; atomicAdd(&g_hist[ntype[i]], 1); }
    if (i < NPAD) g_perm[i] = -1;
    if (i < Tt)   g_cursor[i] = 0;
    if (blockIdx.x < 120) {
        int m = blockIdx.x >> 3, ks = blockIdx.x & 7;
        const float* srcs[5] = {qw, kw, vw, aw, WMk};
        const float* src = srcs[m/3] + (m%3)*Dd*Dd;
        int dstMat = (m < 12) ? m : (15 + m - 12);
        wprep_chunk(src, dstMat, ks);
    }
}

__global__ void k_offsets() {
    int off = 0;
    for (int t = 0; t < Tt; t++) { g_offA[t] = off; off += ((g_hist[t] + 63) & ~63); g_hist[t] = 0; }
    g_offA[Tt] = off;
}

__global__ void k_scatter(const int* __restrict__ ntype) {
    int n = blockIdx.x * blockDim.x + threadIdx.x;
    if (n < Nn) {
        int t = ntype[n];
        int p = atomicAdd(&g_cursor[t], 1);
        g_perm[g_offA[t] + p] = n;
    }
}

__global__ void k_wprep(const float* __restrict__ W, int dstBase) {
    wprep_chunk(W + blockIdx.z*Dd*Dd, dstBase + blockIdx.z, blockIdx.x);
}

// ---------------- small prep kernels (fp32 exact) ----------------
__global__ void k_ab(float* __restrict__ C, const float* __restrict__ A,
                     const float* __restrict__ B, int aStrideZ, int bStrideZ) {
    int i = blockIdx.x, z = blockIdx.z, j = threadIdx.x;
    const float* a = A + z*aStrideZ + i*Dd;
    const float* b = B + z*bStrideZ;
    float s = 0.f;
    #pragma unroll 8
    for (int d = 0; d < Dd; d++) s += a[d] * b[d*Dd + j];
    C[z*Dd*Dd + i*Dd + j] = s;
}

__global__ void k_abT(float* __restrict__ C, const float* __restrict__ A,
                      const float* __restrict__ B, int aStrideZ, int bStrideZ) {
    int i = blockIdx.x, z = blockIdx.z, j = threadIdx.x;
    const float* a = A + z*aStrideZ + i*Dd;
    const float* b = B + z*bStrideZ + j*Dd;
    float s = 0.f;
    #pragma unroll 8
    for (int d = 0; d < Dd; d++) s += a[d] * b[d];
    C[z*Dd*Dd + i*Dd + j] = s;
}

__global__ void k_bc(const float* __restrict__ bq, const float* __restrict__ Wak) {
    int k = blockIdx.x, o = threadIdx.x;
    float s = 0.f;
    for (int j = 0; j < Dd; j++) s += bq[j] * Wak[k*Dd*Dd + j*Dd + o];
    g_bc[k][o] = s;
}

__global__ void k_vecs(const float* __restrict__ Wkl, const float* __restrict__ bkl,
                       const float* __restrict__ WMk) {
    __shared__ float y[Dd];
    int k = blockIdx.x, i = threadIdx.x;
    float u = 0.f, yy = 0.f;
    for (int d = 0; d < Dd; d++) {
        u  += g_Wc[k][i*Dd + d] * bkl[d];
        yy += Wkl[i*Dd + d] * g_bc[k][d];
    }
    g_u[k][i] = u;
    y[i] = yy;
    __syncthreads();
    float w = 0.f;
    for (int j = 0; j < Dd; j++) w += WMk[k*Dd*Dd + i*Dd + j] * y[j];
    g_w[k][i] = w;
    if (i == 0) {
        float s = 0.f;
        for (int d = 0; d < Dd; d++) s += g_bc[k][d] * bkl[d];
        g_s[k] = s;
    }
}

// ---------- bf16 3-term tensor-core GEMM core: [64 rows] x [128 out], K=128 ----------
// 256 threads = 8 warps (4 M x 2 N). Warp tile 16x64. mma m16n8k16 bf16, fp32 acc.
// ldmatrix fragment loads; B double-buffered with register prefetch (1 sync/chunk).
#define AS 136
#define BCH 1536   // words per B chunk buffer (128 n x 12 padded)

struct alignas(16) GemmSM {
    __nv_bfloat16 Ah[64*AS], Al[64*AS];     // 17408 B each
    uint32_t Bh[2][BCH], Bl[2][BCH];        // 6144 B per buffer
    int rowNode[64];
};
#define GEMM_SMEM ((int)sizeof(GemmSM))

__device__ __forceinline__ void gemm_stage_rows(GemmSM* s, int row0, int rowlimit,
                                                const int* perm) {
    int tid = threadIdx.x;
    if (tid < 64) {
        int gr = row0 + tid;
        int nd = (gr < rowlimit) ? (perm ? perm[gr] : gr) : -1;
        s->rowNode[tid] = nd;
    }
}

__device__ __forceinline__ void gemm_stage_A(GemmSM* s, const float* __restrict__ X) {
    int tid = threadIdx.x;
    int m = tid & 63, q = tid >> 6;
    int node = s->rowNode[m];
    __nv_bfloat162* Ah2 = (__nv_bfloat162*)s->Ah;
    __nv_bfloat162* Al2 = (__nv_bfloat162*)s->Al;
    int wbase = m*(AS/2) + q*16;
    if (node >= 0) {
        const float4* src = (const float4*)(X + node*Dd + q*32);
        #pragma unroll
        for (int j = 0; j < 8; j++) {
            float4 v = src[j];
            __nv_bfloat16 h0,l0,h1,l1,h2,l2,h3,l3;
            split_bf16(v.x, h0, l0); split_bf16(v.y, h1, l1);
            split_bf16(v.z, h2, l2); split_bf16(v.w, h3, l3);
            Ah2[wbase + j*2]     = __nv_bfloat162(h0, h1);
            Ah2[wbase + j*2 + 1] = __nv_bfloat162(h2, h3);
            Al2[wbase + j*2]     = __nv_bfloat162(l0, l1);
            Al2[wbase + j*2 + 1] = __nv_bfloat162(l2, l3);
        }
    } else {
        __nv_bfloat162 z2 = __nv_bfloat162(__nv_bfloat16(0.f), __nv_bfloat16(0.f));
        #pragma unroll
        for (int j = 0; j < 8; j++) {
            Ah2[wbase + j*2] = z2; Ah2[wbase + j*2 + 1] = z2;
            Al2[wbase + j*2] = z2; Al2[wbase + j*2 + 1] = z2;
        }
    }
}

// Accumulate C += A_tile @ W_mat into c[8][4]; B pipelined gmem->reg->smem.
__device__ __forceinline__ void gemm_accum(GemmSM* s, int mat, float c[8][4]) {
    int tid = threadIdx.x;
    int lane = tid & 31, wid = tid >> 5;
    int mw = wid >> 1, nw = wid & 1;
    int lt = lane >> 3, lrow = lane & 7;
    int n = tid >> 1, half = tid & 1;
    const uint4* srcH = (const uint4*)(g_Wbh + mat*8192);
    const uint4* srcL = (const uint4*)(g_Wbl + mat*8192);
    int cpSrc = n*2 + half;          // uint4 index within chunk (256/chunk)
    int cpDst = n*12 + half*4;       // word offset in buffer

    uint32_t aBaseH = (uint32_t)__cvta_generic_to_shared(s->Ah);
    uint32_t aBaseL = (uint32_t)__cvta_generic_to_shared(s->Al);
    uint32_t bBaseH = (uint32_t)__cvta_generic_to_shared(&s->Bh[0][0]);
    uint32_t bBaseL = (uint32_t)__cvta_generic_to_shared(&s->Bl[0][0]);

    int mrow = mw*16 + (lt & 1)*8 + lrow;
    uint32_t aOff = (uint32_t)((mrow*(AS/2) + (lt >> 1)*4) * 4);
    uint32_t bOff[4];
    #pragma unroll
    for (int p = 0; p < 4; p++) {
        int ncol = nw*64 + (2*p + (lt >> 1))*8 + lrow;
        bOff[p] = (uint32_t)((ncol*12 + (lt & 1)*4) * 4);
    }

    // prologue: chunk0 -> buf0, prefetch chunk1 -> regs
    uint4 rh = srcH[cpSrc], rl = srcL[cpSrc];
    *(uint4*)(&s->Bh[0][cpDst]) = rh;
    *(uint4*)(&s->Bl[0][cpDst]) = rl;
    rh = srcH[256 + cpSrc];
    rl = srcL[256 + cpSrc];

    #pragma unroll
    for (int ks = 0; ks < 8; ks++) {
        __syncthreads();   // buf[ks&1] staged & prior readers of buf[(ks+1)&1] done

        uint32_t bufH = bBaseH + (uint32_t)((ks & 1) * 6144);
        uint32_t bufL = bBaseL + (uint32_t)((ks & 1) * 6144);
        uint32_t ah0,ah1,ah2,ah3, al0,al1,al2,al3;
        ldsm_x4(ah0, ah1, ah2, ah3, aBaseH + aOff + ks*32);
        ldsm_x4(al0, al1, al2, al3, aBaseL + aOff + ks*32);
        #pragma unroll
        for (int p = 0; p < 4; p++) {
            uint32_t bh0,bh1,bh2,bh3, bl0,bl1,bl2,bl3;
            ldsm_x4(bh0, bh1, bh2, bh3, bufH + bOff[p]);
            ldsm_x4(bl0, bl1, bl2, bl3, bufL + bOff[p]);
            MMA_BF16(c[2*p],   ah0,ah1,ah2,ah3, bh0, bh1);
            MMA_BF16(c[2*p],   al0,al1,al2,al3, bh0, bh1);
            MMA_BF16(c[2*p],   ah0,ah1,ah2,ah3, bl0, bl1);
            MMA_BF16(c[2*p+1], ah0,ah1,ah2,ah3, bh2, bh3);
            MMA_BF16(c[2*p+1], al0,al1,al2,al3, bh2, bh3);
            MMA_BF16(c[2*p+1], ah0,ah1,ah2,ah3, bl2, bl3);
        }

        if (ks < 7) {
            int nb2 = (ks + 1) & 1;
            *(uint4*)(&s->Bh[nb2][cpDst]) = rh;
            *(uint4*)(&s->Bl[nb2][cpDst]) = rl;
            if (ks < 6) {
                rh = srcH[(ks + 2)*256 + cpSrc];
                rl = srcL[(ks + 2)*256 + cpSrc];
            }
        }
    }
}

__device__ __forceinline__ void gemm_epilogue(GemmSM* s, float c[8][4],
                                              const float* bias, float* __restrict__ Y,
                                              bool gelu) {
    int tid = threadIdx.x;
    int lane = tid & 31, wid = tid >> 5;
    int mw = wid >> 1, nw = wid & 1;
    int qr = lane >> 2, qt = lane & 3;
    int nd0 = s->rowNode[mw*16 + qr];
    int nd1 = s->rowNode[mw*16 + qr + 8];
    #pragma unroll
    for (int nb = 0; nb < 8; nb++) {
        int col = nw*64 + nb*8 + 2*qt;
        float2 bv = make_float2(0.f, 0.f);
        if (bias) bv = *(const float2*)(bias + col);
        float o0 = c[nb][0] + bv.x, o1 = c[nb][1] + bv.y;
        float o2 = c[nb][2] + bv.x, o3 = c[nb][3] + bv.y;
        if (gelu) {
            o0 = 0.5f*o0*(1.f + erff(o0*0.7071067811865475f));
            o1 = 0.5f*o1*(1.f + erff(o1*0.7071067811865475f));
            o2 = 0.5f*o2*(1.f + erff(o2*0.7071067811865475f));
            o3 = 0.5f*o3*(1.f + erff(o3*0.7071067811865475f));
        }
        if (nd0 >= 0) *(float2*)(Y + nd0*Dd + col) = make_float2(o0, o1);
        if (nd1 >= 0) *(float2*)(Y + nd1*Dd + col) = make_float2(o2, o3);
    }
}

__device__ __forceinline__ void czero(float c[8][4]) {
    #pragma unroll
    for (int nb = 0; nb < 8; nb++) { c[nb][0]=0.f; c[nb][1]=0.f; c[nb][2]=0.f; c[nb][3]=0.f; }
}

// ---------------- GEMM kernels (dynamic smem) ----------------
__global__ void k_gemm_qkv(const float* __restrict__ X,
                           const float* __restrict__ qb, const float* __restrict__ kb,
                           const float* __restrict__ vb)
{
    extern __shared__ char smraw[];
    GemmSM* sm = (GemmSM*)smraw;
    int row0 = blockIdx.x * 64;
    int t = 0;
    if (row0 >= g_offA[1]) t = 1;
    if (row0 >= g_offA[2]) t = 2;
    gemm_stage_rows(sm, row0, NPAD, g_perm);
    __syncthreads();
    gemm_stage_A(sm, X);
    float c[8][4];
    czero(c); gemm_accum(sm, 0 + t, c); gemm_epilogue(sm, c, qb + t*Dd, g_qn, false);
    czero(c); gemm_accum(sm, 3 + t, c); gemm_epilogue(sm, c, kb + t*Dd, g_kn, false);
    czero(c); gemm_accum(sm, 6 + t, c); gemm_epilogue(sm, c, vb + t*Dd, g_vn, false);
}

__global__ void k_gemm_V(const float* __restrict__ X) {
    extern __shared__ char smraw[];
    GemmSM* sm = (GemmSM*)smraw;
    int row0 = blockIdx.x * 64;
    gemm_stage_rows(sm, row0, Nn, nullptr);
    __syncthreads();
    gemm_stage_A(sm, X);
    float c[8][4];
    #pragma unroll
    for (int z = 0; z < Kk; z++) {
        czero(c);
        gemm_accum(sm, 12 + z, c);
        gemm_epilogue(sm, c, nullptr, &g_V[z][0], false);
    }
}

__global__ void k_gemm_res() {
    extern __shared__ char smraw[];
    GemmSM* sm = (GemmSM*)smraw;
    int row0 = blockIdx.x * 64;
    gemm_stage_rows(sm, row0, Nn, nullptr);
    float c[8][4];
    czero(c);
    #pragma unroll
    for (int z = 0; z < Kk; z++) {
        __syncthreads();
        gemm_stage_A(sm, &g_aggX[z][0]);
        gemm_accum(sm, 15 + z, c);
    }
    gemm_epilogue(sm, c, nullptr, g_hb, true);
}

__global__ void k_gemm_a(const float* __restrict__ ab) {
    extern __shared__ char smraw[];
    GemmSM* sm = (GemmSM*)smraw;
    int row0 = blockIdx.x * 64;
    int t = 0;
    if (row0 >= g_offA[1]) t = 1;
    if (row0 >= g_offA[2]) t = 2;
    gemm_stage_rows(sm, row0, NPAD, g_perm);
    __syncthreads();
    gemm_stage_A(sm, g_hb);
    float c[8][4];
    czero(c);
    gemm_accum(sm, 9 + t, c);
    gemm_epilogue(sm, c, ab + t*Dd, g_trans, false);
}

// ---------------- edge phase ----------------
__global__ void k_edge_logits(const int* __restrict__ ei, const int* __restrict__ et,
                              const float* __restrict__ ratt, const float* __restrict__ rpri)
{
    __shared__ float sk[4][128];
    int warp = threadIdx.x >> 5, lane = threadIdx.x & 31;
    int e = blockIdx.x*4 + warp;
    if (e >= Ee) return;
    int s = ei[e], tg = ei[Ee + e], r = et[e];
    *(float4*)&sk[warp][lane*4] = ((const float4*)(g_kn + s*Dd))[lane];
    __syncwarp();
    int h = lane >> 3, m0 = (lane & 7) * 4;
    const float* A = ratt + (r*Hh + h)*(DKk*DKk) + m0;
    float ax = 0.f, ay = 0.f, az = 0.f, aw = 0.f;
    const float* kh = &sk[warp][h*32];
    #pragma unroll
    for (int d = 0; d < DKk; d++) {
        float kv = kh[d];
        float4 a = *(const float4*)(A + d*DKk);
        ax += kv*a.x; ay += kv*a.y; az += kv*a.z; aw += kv*a.w;
    }
    float4 qv = *(const float4*)(g_qn + tg*Dd + h*32 + m0);
    float p = ax*qv.x + ay*qv.y + az*qv.z + aw*qv.w;
    p += __shfl_xor_sync(0xffffffffu, p, 1);
    p += __shfl_xor_sync(0xffffffffu, p, 2);
    p += __shfl_xor_sync(0xffffffffu, p, 4);
    if ((lane & 7) == 0) {
        float logit = p * rpri[r*Hh + h] * 0.17677669529663687f;
        g_ebuf[e*Hh + h] = logit;
        atomicMaxFloat(&g_nmax[tg*Hh + h], logit);
    }
    if (lane == 0) atomicAdd(&g_deg[tg], 1);
}

__global__ void k_edge_exp(const int* __restrict__ ei) {
    int idx = blockIdx.x * blockDim.x + threadIdx.x;
    if (idx >= Ee*Hh) return;
    int e = idx >> 2, h = idx & 3;
    int tg = ei[Ee + e];
    float ex = expf(g_ebuf[idx] - g_nmax[tg*Hh + h]);
    g_ebuf[idx] = ex;
    atomicAdd(&g_nsum[tg*Hh + h], ex);
}

__global__ void k_msg(const int* __restrict__ ei, const int* __restrict__ et,
                      const float* __restrict__ rmsg)
{
    __shared__ float sv[4][128];
    int warp = threadIdx.x >> 5, lane = threadIdx.x & 31;
    int n = blockIdx.x*4 + warp;
    if (n >= Nn) return;
    int s = ei[n], tg = ei[Ee + n], r = et[n];
    *(float4*)&sv[warp][lane*4] = ((const float4*)(g_vn + s*Dd))[lane];
    __syncwarp();
    int h = lane >> 3, m0 = (lane & 7) * 4;
    const float* A = rmsg + (r*Hh + h)*(DKk*DKk) + m0;
    float ax = 0.f, ay = 0.f, az = 0.f, aw = 0.f;
    const float* vh = &sv[warp][h*32];
    #pragma unroll
    for (int d = 0; d < DKk; d++) {
        float vv = vh[d];
        float4 a = *(const float4*)(A + d*DKk);
        ax += vv*a.x; ay += vv*a.y; az += vv*a.z; aw += vv*a.w;
    }
    float att = g_ebuf[n*Hh + h] / (g_nsum[tg*Hh + h] + 1e-16f);
    float c1 = (float)g_deg[n] * att;
    int base = n*Dd + lane*4;
    float4 o1, o2, o3;
    o1.x = c1*ax;       o1.y = c1*ay;       o1.z = c1*az;       o1.w = c1*aw;
    o2.x = c1*ax*ax;    o2.y = c1*ay*ay;    o2.z = c1*az*az;    o2.w = c1*aw*aw;
    o3.x = signed_cbrt(c1*ax*ax*ax);
    o3.y = signed_cbrt(c1*ay*ay*ay);
    o3.z = signed_cbrt(c1*az*az*az);
    o3.w = signed_cbrt(c1*aw*aw*aw);
    *(float4*)(&g_aggX[0][0] + base) = o1;
    *(float4*)(&g_aggX[1][0] + base) = o2;
    *(float4*)(&g_aggX[2][0] + base) = o3;
}

// ---------------- gate ----------------
__global__ void k_gate(const float* __restrict__ X) {
    int warp = threadIdx.x >> 5, lane = threadIdx.x & 31;
    int n = blockIdx.x*4 + warp;
    if (n >= Nn) return;
    int base = n*Dd + lane*4;
    float4 xv = *(const float4*)(X + base);
    #pragma unroll
    for (int k = 0; k < Kk; k++) {
        float4 vv = *(const float4*)(&g_V[k][0] + base);
        float4 ax = *(const float4*)(&g_aggX[k][0] + base);
        float4 uu = *(const float4*)(&g_u[k][0] + lane*4);
        float4 ww = *(const float4*)(&g_w[k][0] + lane*4);
        float p = vv.x*ax.x + vv.y*ax.y + vv.z*ax.z + vv.w*ax.w
                + xv.x*uu.x + xv.y*uu.y + xv.z*uu.z + xv.w*uu.w
                + ax.x*ww.x + ax.y*ww.y + ax.z*ww.z + ax.w*ww.w;
        p = warp_sum(p) + g_s[k];
        float tk = 1.f / (1.f + expf(-p));
        float4 o = make_float4(tk*ax.x, tk*ax.y, tk*ax.z, tk*ax.w);
        *(float4*)(&g_aggX[k][0] + base) = o;
    }
}

// ---------------- skip + layernorm ----------------
__global__ void k_final(const float* __restrict__ X, const int* __restrict__ ntype,
                        const float* __restrict__ skip, const float* __restrict__ lng,
                        const float* __restrict__ lnb, float* __restrict__ out)
{
    int warp = threadIdx.x >> 5, lane = threadIdx.x & 31;
    int n = blockIdx.x*4 + warp;
    if (n >= Nn) return;
    int t = ntype[n];
    float alpha = 1.f / (1.f + expf(-skip[t]));
    int base = n*Dd + lane*4;
    float4 x  = *(const float4*)(X + base);
    float4 tr = *(const float4*)(g_trans + base);
    float4 y;
    y.x = tr.x*alpha + x.x*(1.f - alpha);
    y.y = tr.y*alpha + x.y*(1.f - alpha);
    y.z = tr.z*alpha + x.z*(1.f - alpha);
    y.w = tr.w*alpha + x.w*(1.f - alpha);
    float mu = warp_sum(y.x + y.y + y.z + y.w) * (1.f/128.f);
    float4 d = make_float4(y.x - mu, y.y - mu, y.z - mu, y.w - mu);
    float var = warp_sum(d.x*d.x + d.y*d.y + d.z*d.z + d.w*d.w) * (1.f/128.f);
    float rstd = rsqrtf(var + 1e-5f);
    int gi = t*Dd + lane*4;
    float4 g = *(const float4*)(lng + gi);
    float4 b = *(const float4*)(lnb + gi);
    float4 o;
    o.x = d.x*rstd*g.x + b.x;
    o.y = d.y*rstd*g.y + b.y;
    o.z = d.z*rstd*g.z + b.z;
    o.w = d.w*rstd*g.w + b.w;
    *(float4*)(out + base) = o;
}

// ---------------- launch ----------------
extern "C" void kernel_launch(void* const* d_in, const int* in_sizes, int n_in,
                              void* d_out, int out_size)
{
    const float* meta = (const float*)d_in[0];
    const int*   ntype = (const int*)d_in[1];
    const int*   ei    = (const int*)d_in[2];
    const int*   et    = (const int*)d_in[3];
    // d_in[4] = edge_time (unused)
    const float* qw = (const float*)d_in[5],  *qb = (const float*)d_in[6];
    const float* kw = (const float*)d_in[7],  *kb = (const float*)d_in[8];
    const float* vw = (const float*)d_in[9],  *vb = (const float*)d_in[10];
    const float* aw = (const float*)d_in[11], *ab = (const float*)d_in[12];
    const float* rpri = (const float*)d_in[13];
    const float* ratt = (const float*)d_in[14];
    const float* rmsg = (const float*)d_in[15];
    const float* WMk  = (const float*)d_in[16];
    const float* Wak  = (const float*)d_in[17];
    const float* Wq   = (const float*)d_in[18], *bq  = (const float*)d_in[19];
    const float* Wkl  = (const float*)d_in[20], *bkl = (const float*)d_in[21];
    const float* skp  = (const float*)d_in[22];
    const float* lng  = (const float*)d_in[23], *lnb = (const float*)d_in[24];
    float* out = (float*)d_out;

    static int attrDone = 0;
    if (!attrDone) {
        cudaFuncSetAttribute(k_gemm_qkv, cudaFuncAttributeMaxDynamicSharedMemorySize, GEMM_SMEM);
        cudaFuncSetAttribute(k_gemm_V,   cudaFuncAttributeMaxDynamicSharedMemorySize, GEMM_SMEM);
        cudaFuncSetAttribute(k_gemm_res, cudaFuncAttributeMaxDynamicSharedMemorySize, GEMM_SMEM);
        cudaFuncSetAttribute(k_gemm_a,   cudaFuncAttributeMaxDynamicSharedMemorySize, GEMM_SMEM);
        attrDone = 1;
    }

    float* WcP = nullptr; float* T1P = nullptr; float* PP = nullptr;
    cudaGetSymbolAddress((void**)&WcP, g_Wc);
    cudaGetSymbolAddress((void**)&T1P, g_T1);
    cudaGetSymbolAddress((void**)&PP,  g_P);

    k_init<<<(Nn*Hh + 255)/256, 256>>>(ntype, qw, kw, vw, aw, WMk);  // 1
    k_offsets<<<1, 1>>>();                                           // 2
    k_scatter<<<(Nn + 255)/256, 256>>>(ntype);                       // 3
    k_gemm_qkv<<<NPAD/64, 256, GEMM_SMEM>>>(meta, qb, kb, vb);       // 4 <- ncu slot

    k_ab<<<dim3(Dd,1,Kk), Dd>>>(WcP, Wq, Wak, 0, Dd*Dd);       // Wc_k = Wq @ Wak_k
    k_bc<<<Kk, Dd>>>(bq, Wak);                                  // bc_k = bq @ Wak_k
    k_abT<<<dim3(Dd,1,Kk), Dd>>>(T1P, WcP, Wkl, Dd*Dd, 0);     // T1_k = Wc_k @ Wkl^T
    k_abT<<<dim3(Dd,1,Kk), Dd>>>(PP, T1P, WMk, Dd*Dd, Dd*Dd);  // P_k  = T1_k @ WMk_k^T
    k_wprep<<<dim3(8,1,Kk), 256>>>(PP, 12);                     // P -> bf16 word layout
    k_vecs<<<Kk, Dd>>>(Wkl, bkl, WMk);                          // u, w, s

    k_edge_logits<<<Ee/4, 128>>>(ei, et, ratt, rpri);
    k_edge_exp<<<(Ee*Hh + 255)/256, 256>>>(ei);
    k_msg<<<Nn/4, 128>>>(ei, et, rmsg);

    k_gemm_V<<<Nn/64, 256, GEMM_SMEM>>>(meta);
    k_gate<<<Nn/4, 128>>>(meta);
    k_gemm_res<<<Nn/64, 256, GEMM_SMEM>>>();
    k_gemm_a<<<NPAD/64, 256, GEMM_SMEM>>>(ab);
    k_final<<<Nn/4, 128>>>(meta, ntype, skp, lng, lnb, out);
}

// round 12
// speedup vs baseline: 1.4727x; 1.1313x over previous
#include <cuda_runtime.h>
#include <cuda_bf16.h>
#include <stdint.h>
#include <math.h>

#define Nn 40000
#define Ee 320000
#define Dd 128
#define Hh 4
#define Tt 3
#define Rr 5
#define Kk 3
#define DKk 32
#define NPAD (Nn + 64*Tt)
#define ND (Nn*Dd)

// ---------------- scratch (static device globals; no allocation) ----------------
__device__ float g_qn[ND], g_vn[ND];
__device__ float g_kp[Rr][ND];       // kp[r] = typed_k(x) @ blockdiag(A_r)
__device__ float g_ebuf[Ee*Hh];
__device__ float g_nmax[Nn*Hh], g_nsum[Nn*Hh];
__device__ int   g_deg[Nn];
__device__ float g_aggX[Kk][ND];     // moments; overwritten in-place with t*aggX by k_gate
__device__ float g_V[Kk][ND];        // V_k = X @ P_k
__device__ float g_hb[ND];           // gelu(res)
__device__ float g_trans[ND];
__device__ int   g_perm[NPAD], g_hist[Tt], g_cursor[Tt], g_offA[Tt+1];
__device__ float g_Wc[Kk][Dd*Dd], g_bc[Kk][Dd];
__device__ float g_T1[Kk][Dd*Dd], g_P[Kk][Dd*Dd];
__device__ float g_u[Kk][Dd], g_w[Kk][Dd], g_s[Kk];
__device__ float g_kbr[Tt*Rr*Dd];    // kbr[t,r] = kb_t @ blockdiag(A_r)

// Prepped weights: bf16 hi/lo in MMA word layout.
// Per matrix: [8 kchunks][128 n][8 kpair-words] = 8192 uint32 (32 KB).
// ids: 0-2 qw_t, 3-5 vw_t, 6-8 aw_t, 9-11 P_k, 12-14 WMk_k, 15-29 kwr[t*5+r].
#define NMAT 30
__device__ uint32_t g_Wbh[NMAT*8192];
__device__ uint32_t g_Wbl[NMAT*8192];

// ---------------- helpers ----------------
__device__ __forceinline__ void atomicMaxFloat(float* addr, float v) {
    if (v >= 0.f) atomicMax((int*)addr, __float_as_int(v));
    else          atomicMin((unsigned int*)addr, __float_as_uint(v));
}

__device__ __forceinline__ float warp_sum(float v) {
    v += __shfl_xor_sync(0xffffffffu, v, 16);
    v += __shfl_xor_sync(0xffffffffu, v, 8);
    v += __shfl_xor_sync(0xffffffffu, v, 4);
    v += __shfl_xor_sync(0xffffffffu, v, 2);
    v += __shfl_xor_sync(0xffffffffu, v, 1);
    return v;
}

__device__ __forceinline__ float signed_cbrt(float z) {
    return (z == 0.f) ? 0.f : copysignf(cbrtf(fabsf(z) + 1e-18f), z);
}

__device__ __forceinline__ void split_bf16(float x, __nv_bfloat16& h, __nv_bfloat16& l) {
    h = __float2bfloat16(x);
    l = __float2bfloat16(x - __bfloat162float(h));
}

__device__ __forceinline__ uint32_t pack_bf16x2(__nv_bfloat16 lo16, __nv_bfloat16 hi16) {
    return (uint32_t)__bfloat16_as_ushort(lo16) | ((uint32_t)__bfloat16_as_ushort(hi16) << 16);
}

#define MMA_BF16(c, a0, a1, a2, a3, b0, b1) \
    asm volatile("mma.sync.aligned.m16n8k16.row.col.f32.bf16.bf16.f32 " \
        "{%0,%1,%2,%3}, {%4,%5,%6,%7}, {%8,%9}, {%0,%1,%2,%3};" \
        : "+f"((c)[0]), "+f"((c)[1]), "+f"((c)[2]), "+f"((c)[3]) \
        : "r"(a0), "r"(a1), "r"(a2), "r"(a3), "r"(b0), "r"(b1))

__device__ __forceinline__ void ldsm_x4(uint32_t& r0, uint32_t& r1, uint32_t& r2,
                                        uint32_t& r3, uint32_t saddr) {
    asm volatile("ldmatrix.sync.aligned.m8n8.x4.shared.b16 {%0,%1,%2,%3}, [%4];"
                 : "=r"(r0), "=r"(r1), "=r"(r2), "=r"(r3) : "r"(saddr));
}

// ---------------- weight prep: fp32 [128k][128n] -> word layout hi/lo ----------------
__device__ __forceinline__ void wprep_store(int mat, int ks, int n, int half,
                                            const float* vals /*8*/) {
    uint32_t outh[4], outl[4];
    #pragma unroll
    for (int jj = 0; jj < 4; jj++) {
        __nv_bfloat16 ha, la, hb, lb;
        split_bf16(vals[jj*2],   ha, la);
        split_bf16(vals[jj*2+1], hb, lb);
        outh[jj] = pack_bf16x2(ha, hb);
        outl[jj] = pack_bf16x2(la, lb);
    }
    int base = mat*8192 + ks*1024 + n*8 + half*4;
    *(uint4*)(g_Wbh + base) = make_uint4(outh[0], outh[1], outh[2], outh[3]);
    *(uint4*)(g_Wbl + base) = make_uint4(outl[0], outl[1], outl[2], outl[3]);
}

__device__ __forceinline__ void wprep_chunk(const float* __restrict__ W, int mat, int ks) {
    int tid = threadIdx.x;
    int n = tid >> 1, half = tid & 1;
    float vals[8];
    #pragma unroll
    for (int jj = 0; jj < 4; jj++) {
        int j = half*4 + jj;
        int k0 = ks*16 + 2*j;
        vals[jj*2]   = W[k0*Dd + n];
        vals[jj*2+1] = W[(k0+1)*Dd + n];
    }
    wprep_store(mat, ks, n, half, vals);
}

// kwr[t,r][i][o] = sum_d kw_t[i][h_o*32+d] * A_r[h_o][d][m_o]  (computed fp32, split)
__device__ __forceinline__ void kwr_wprep_chunk(const float* __restrict__ kwt,
                                                const float* __restrict__ Ar,
                                                int mat, int ks) {
    int tid = threadIdx.x;
    int n = tid >> 1, half = tid & 1;
    int hn = n >> 5, mn = n & 31;
    const float* Ah = Ar + hn*DKk*DKk;
    const float* kbase = kwt + hn*32;
    float vals[8];
    #pragma unroll
    for (int jj = 0; jj < 4; jj++) {
        int j = half*4 + jj;
        int k0 = ks*16 + 2*j;
        float e0 = 0.f, e1 = 0.f;
        const float* r0p = kbase + k0*Dd;
        const float* r1p = kbase + (k0+1)*Dd;
        #pragma unroll 8
        for (int d = 0; d < DKk; d++) {
            float a = Ah[d*DKk + mn];
            e0 += r0p[d] * a;
            e1 += r1p[d] * a;
        }
        vals[jj*2] = e0; vals[jj*2+1] = e1;
    }
    wprep_store(mat, ks, n, half, vals);
}

// ---------------- setup ----------------
__global__ void k_init(const int* __restrict__ ntype,
                       const float* __restrict__ qw, const float* __restrict__ vw,
                       const float* __restrict__ aw, const float* __restrict__ WMk,
                       const float* __restrict__ kw, const float* __restrict__ ratt) {
    int i = blockIdx.x * blockDim.x + threadIdx.x;
    if (i < Nn*Hh) { g_nmax[i] = __int_as_float(0xff800000); g_nsum[i] = 0.f; }
    if (i < Nn) { g_deg[i] = 0; atomicAdd(&g_hist[ntype[i]], 1); }
    if (i < NPAD) g_perm[i] = -1;
    if (i < Tt)   g_cursor[i] = 0;
    int b = blockIdx.x;
    if (b < 96) {                 // q, v, a, WMk (12 matrices x 8 chunks)
        int m = b >> 3, ks = b & 7;
        const float* srcs[4] = {qw, vw, aw, WMk};
        const float* src = srcs[m/3] + (m%3)*Dd*Dd;
        int dst = (m < 9) ? m : (12 + m - 9);
        wprep_chunk(src, dst, ks);
    } else if (b < 216) {         // kwr: 15 matrices x 8 chunks
        int bb = b - 96;
        int mi = bb >> 3, ks = bb & 7;
        int t = mi / 5, r = mi % 5;
        kwr_wprep_chunk(kw + t*Dd*Dd, ratt + r*Hh*DKk*DKk, 15 + mi, ks);
    }
}

// block 0: offsets; blocks 1..15: kbr[t,r]
__global__ void k_prep2(const float* __restrict__ kb, const float* __restrict__ ratt) {
    if (blockIdx.x == 0) {
        if (threadIdx.x == 0) {
            int off = 0;
            for (int t = 0; t < Tt; t++) { g_offA[t] = off; off += ((g_hist[t] + 63) & ~63); g_hist[t] = 0; }
            g_offA[Tt] = off;
        }
        return;
    }
    int z = blockIdx.x - 1, t = z / 5, r = z % 5;
    int o = threadIdx.x, ho = o >> 5, mo = o & 31;
    float s = 0.f;
    #pragma unroll 8
    for (int d = 0; d < DKk; d++)
        s += kb[t*Dd + ho*32 + d] * ratt[((r*Hh + ho)*DKk + d)*DKk + mo];
    g_kbr[(t*Rr + r)*Dd + o] = s;
}

__global__ void k_scatter(const int* __restrict__ ntype) {
    int n = blockIdx.x * blockDim.x + threadIdx.x;
    if (n < Nn) {
        int t = ntype[n];
        int p = atomicAdd(&g_cursor[t], 1);
        g_perm[g_offA[t] + p] = n;
    }
}

__global__ void k_wprep(const float* __restrict__ W, int dstBase) {
    wprep_chunk(W + blockIdx.z*Dd*Dd, dstBase + blockIdx.z, blockIdx.x);
}

// ---------------- small prep kernels (fp32 exact) ----------------
__global__ void k_ab(float* __restrict__ C, const float* __restrict__ A,
                     const float* __restrict__ B, int aStrideZ, int bStrideZ) {
    int i = blockIdx.x, z = blockIdx.z, j = threadIdx.x;
    const float* a = A + z*aStrideZ + i*Dd;
    const float* b = B + z*bStrideZ;
    float s = 0.f;
    #pragma unroll 8
    for (int d = 0; d < Dd; d++) s += a[d] * b[d*Dd + j];
    C[z*Dd*Dd + i*Dd + j] = s;
}

__global__ void k_abT(float* __restrict__ C, const float* __restrict__ A,
                      const float* __restrict__ B, int aStrideZ, int bStrideZ) {
    int i = blockIdx.x, z = blockIdx.z, j = threadIdx.x;
    const float* a = A + z*aStrideZ + i*Dd;
    const float* b = B + z*bStrideZ + j*Dd;
    float s = 0.f;
    #pragma unroll 8
    for (int d = 0; d < Dd; d++) s += a[d] * b[d];
    C[z*Dd*Dd + i*Dd + j] = s;
}

__global__ void k_bc(const float* __restrict__ bq, const float* __restrict__ Wak) {
    int k = blockIdx.x, o = threadIdx.x;
    float s = 0.f;
    for (int j = 0; j < Dd; j++) s += bq[j] * Wak[k*Dd*Dd + j*Dd + o];
    g_bc[k][o] = s;
}

__global__ void k_vecs(const float* __restrict__ Wkl, const float* __restrict__ bkl,
                       const float* __restrict__ WMk) {
    __shared__ float y[Dd];
    int k = blockIdx.x, i = threadIdx.x;
    float u = 0.f, yy = 0.f;
    for (int d = 0; d < Dd; d++) {
        u  += g_Wc[k][i*Dd + d] * bkl[d];
        yy += Wkl[i*Dd + d] * g_bc[k][d];
    }
    g_u[k][i] = u;
    y[i] = yy;
    __syncthreads();
    float w = 0.f;
    for (int j = 0; j < Dd; j++) w += WMk[k*Dd*Dd + i*Dd + j] * y[j];
    g_w[k][i] = w;
    if (i == 0) {
        float s = 0.f;
        for (int d = 0; d < Dd; d++) s += g_bc[k][d] * bkl[d];
        g_s[k] = s;
    }
}

// ---------- bf16 3-term tensor-core GEMM core: [64 rows] x [128 out], K=128 ----------
#define AS 136
#define BCH 1536

struct alignas(16) GemmSM {
    __nv_bfloat16 Ah[64*AS], Al[64*AS];
    uint32_t Bh[2][BCH], Bl[2][BCH];
    int rowNode[64];
};
#define GEMM_SMEM ((int)sizeof(GemmSM))

__device__ __forceinline__ void gemm_stage_rows(GemmSM* s, int row0, int rowlimit,
                                                const int* perm) {
    int tid = threadIdx.x;
    if (tid < 64) {
        int gr = row0 + tid;
        int nd = (gr < rowlimit) ? (perm ? perm[gr] : gr) : -1;
        s->rowNode[tid] = nd;
    }
}

__device__ __forceinline__ void gemm_stage_A(GemmSM* s, const float* __restrict__ X) {
    int tid = threadIdx.x;
    int m = tid & 63, q = tid >> 6;
    int node = s->rowNode[m];
    __nv_bfloat162* Ah2 = (__nv_bfloat162*)s->Ah;
    __nv_bfloat162* Al2 = (__nv_bfloat162*)s->Al;
    int wbase = m*(AS/2) + q*16;
    if (node >= 0) {
        const float4* src = (const float4*)(X + node*Dd + q*32);
        #pragma unroll
        for (int j = 0; j < 8; j++) {
            float4 v = src[j];
            __nv_bfloat16 h0,l0,h1,l1,h2,l2,h3,l3;
            split_bf16(v.x, h0, l0); split_bf16(v.y, h1, l1);
            split_bf16(v.z, h2, l2); split_bf16(v.w, h3, l3);
            Ah2[wbase + j*2]     = __nv_bfloat162(h0, h1);
            Ah2[wbase + j*2 + 1] = __nv_bfloat162(h2, h3);
            Al2[wbase + j*2]     = __nv_bfloat162(l0, l1);
            Al2[wbase + j*2 + 1] = __nv_bfloat162(l2, l3);
        }
    } else {
        __nv_bfloat162 z2 = __nv_bfloat162(__nv_bfloat16(0.f), __nv_bfloat16(0.f));
        #pragma unroll
        for (int j = 0; j < 8; j++) {
            Ah2[wbase + j*2] = z2; Ah2[wbase + j*2 + 1] = z2;
            Al2[wbase + j*2] = z2; Al2[wbase + j*2 + 1] = z2;
        }
    }
}

__device__ __forceinline__ void gemm_accum(GemmSM* s, int mat, float c[8][4]) {
    int tid = threadIdx.x;
    int lane = tid & 31, wid = tid >> 5;
    int mw = wid >> 1, nw = wid & 1;
    int lt = lane >> 3, lrow = lane & 7;
    int n = tid >> 1, half = tid & 1;
    const uint4* srcH = (const uint4*)(g_Wbh + mat*8192);
    const uint4* srcL = (const uint4*)(g_Wbl + mat*8192);
    int cpSrc = n*2 + half;
    int cpDst = n*12 + half*4;

    uint32_t aBaseH = (uint32_t)__cvta_generic_to_shared(s->Ah);
    uint32_t aBaseL = (uint32_t)__cvta_generic_to_shared(s->Al);
    uint32_t bBaseH = (uint32_t)__cvta_generic_to_shared(&s->Bh[0][0]);
    uint32_t bBaseL = (uint32_t)__cvta_generic_to_shared(&s->Bl[0][0]);

    int mrow = mw*16 + (lt & 1)*8 + lrow;
    uint32_t aOff = (uint32_t)((mrow*(AS/2) + (lt >> 1)*4) * 4);
    uint32_t bOff[4];
    #pragma unroll
    for (int p = 0; p < 4; p++) {
        int ncol = nw*64 + (2*p + (lt >> 1))*8 + lrow;
        bOff[p] = (uint32_t)((ncol*12 + (lt & 1)*4) * 4);
    }

    uint4 rh = srcH[cpSrc], rl = srcL[cpSrc];
    *(uint4*)(&s->Bh[0][cpDst]) = rh;
    *(uint4*)(&s->Bl[0][cpDst]) = rl;
    rh = srcH[256 + cpSrc];
    rl = srcL[256 + cpSrc];

    #pragma unroll
    for (int ks = 0; ks < 8; ks++) {
        __syncthreads();

        uint32_t bufH = bBaseH + (uint32_t)((ks & 1) * 6144);
        uint32_t bufL = bBaseL + (uint32_t)((ks & 1) * 6144);
        uint32_t ah0,ah1,ah2,ah3, al0,al1,al2,al3;
        ldsm_x4(ah0, ah1, ah2, ah3, aBaseH + aOff + ks*32);
        ldsm_x4(al0, al1, al2, al3, aBaseL + aOff + ks*32);
        #pragma unroll
        for (int p = 0; p < 4; p++) {
            uint32_t bh0,bh1,bh2,bh3, bl0,bl1,bl2,bl3;
            ldsm_x4(bh0, bh1, bh2, bh3, bufH + bOff[p]);
            ldsm_x4(bl0, bl1, bl2, bl3, bufL + bOff[p]);
            MMA_BF16(c[2*p],   ah0,ah1,ah2,ah3, bh0, bh1);
            MMA_BF16(c[2*p],   al0,al1,al2,al3, bh0, bh1);
            MMA_BF16(c[2*p],   ah0,ah1,ah2,ah3, bl0, bl1);
            MMA_BF16(c[2*p+1], ah0,ah1,ah2,ah3, bh2, bh3);
            MMA_BF16(c[2*p+1], al0,al1,al2,al3, bh2, bh3);
            MMA_BF16(c[2*p+1], ah0,ah1,ah2,ah3, bl2, bl3);
        }

        if (ks < 7) {
            int nb2 = (ks + 1) & 1;
            *(uint4*)(&s->Bh[nb2][cpDst]) = rh;
            *(uint4*)(&s->Bl[nb2][cpDst]) = rl;
            if (ks < 6) {
                rh = srcH[(ks + 2)*256 + cpSrc];
                rl = srcL[(ks + 2)*256 + cpSrc];
            }
        }
    }
}

__device__ __forceinline__ void gemm_epilogue(GemmSM* s, float c[8][4],
                                              const float* bias, float* __restrict__ Y,
                                              bool gelu) {
    int tid = threadIdx.x;
    int lane = tid & 31, wid = tid >> 5;
    int mw = wid >> 1, nw = wid & 1;
    int qr = lane >> 2, qt = lane & 3;
    int nd0 = s->rowNode[mw*16 + qr];
    int nd1 = s->rowNode[mw*16 + qr + 8];
    #pragma unroll
    for (int nb = 0; nb < 8; nb++) {
        int col = nw*64 + nb*8 + 2*qt;
        float2 bv = make_float2(0.f, 0.f);
        if (bias) bv = *(const float2*)(bias + col);
        float o0 = c[nb][0] + bv.x, o1 = c[nb][1] + bv.y;
        float o2 = c[nb][2] + bv.x, o3 = c[nb][3] + bv.y;
        if (gelu) {
            o0 = 0.5f*o0*(1.f + erff(o0*0.7071067811865475f));
            o1 = 0.5f*o1*(1.f + erff(o1*0.7071067811865475f));
            o2 = 0.5f*o2*(1.f + erff(o2*0.7071067811865475f));
            o3 = 0.5f*o3*(1.f + erff(o3*0.7071067811865475f));
        }
        if (nd0 >= 0) *(float2*)(Y + nd0*Dd + col) = make_float2(o0, o1);
        if (nd1 >= 0) *(float2*)(Y + nd1*Dd + col) = make_float2(o2, o3);
    }
}

__device__ __forceinline__ void czero(float c[8][4]) {
    #pragma unroll
    for (int nb = 0; nb < 8; nb++) { c[nb][0]=0.f; c[nb][1]=0.f; c[nb][2]=0.f; c[nb][3]=0.f; }
}

// ---------------- GEMM kernels (dynamic smem) ----------------
// q, v, and kp[r] for r=0..4: 7 accums sharing one staged A tile.
__global__ void k_gemm_qkv(const float* __restrict__ X,
                           const float* __restrict__ qb, const float* __restrict__ vb)
{
    extern __shared__ char smraw[];
    GemmSM* sm = (GemmSM*)smraw;
    int row0 = blockIdx.x * 64;
    int t = 0;
    if (row0 >= g_offA[1]) t = 1;
    if (row0 >= g_offA[2]) t = 2;
    gemm_stage_rows(sm, row0, NPAD, g_perm);
    __syncthreads();
    gemm_stage_A(sm, X);
    float c[8][4];
    czero(c); gemm_accum(sm, 0 + t, c); gemm_epilogue(sm, c, qb + t*Dd, g_qn, false);
    czero(c); gemm_accum(sm, 3 + t, c); gemm_epilogue(sm, c, vb + t*Dd, g_vn, false);
    #pragma unroll
    for (int r = 0; r < Rr; r++) {
        czero(c);
        gemm_accum(sm, 15 + t*Rr + r, c);
        gemm_epilogue(sm, c, g_kbr + (t*Rr + r)*Dd, &g_kp[r][0], false);
    }
}

__global__ void k_gemm_V(const float* __restrict__ X) {
    extern __shared__ char smraw[];
    GemmSM* sm = (GemmSM*)smraw;
    int row0 = blockIdx.x * 64;
    gemm_stage_rows(sm, row0, Nn, nullptr);
    __syncthreads();
    gemm_stage_A(sm, X);
    float c[8][4];
    #pragma unroll
    for (int z = 0; z < Kk; z++) {
        czero(c);
        gemm_accum(sm, 9 + z, c);
        gemm_epilogue(sm, c, nullptr, &g_V[z][0], false);
    }
}

__global__ void k_gemm_res() {
    extern __shared__ char smraw[];
    GemmSM* sm = (GemmSM*)smraw;
    int row0 = blockIdx.x * 64;
    gemm_stage_rows(sm, row0, Nn, nullptr);
    float c[8][4];
    czero(c);
    #pragma unroll
    for (int z = 0; z < Kk; z++) {
        __syncthreads();
        gemm_stage_A(sm, &g_aggX[z][0]);
        gemm_accum(sm, 12 + z, c);
    }
    gemm_epilogue(sm, c, nullptr, g_hb, true);
}

__global__ void k_gemm_a(const float* __restrict__ ab) {
    extern __shared__ char smraw[];
    GemmSM* sm = (GemmSM*)smraw;
    int row0 = blockIdx.x * 64;
    int t = 0;
    if (row0 >= g_offA[1]) t = 1;
    if (row0 >= g_offA[2]) t = 2;
    gemm_stage_rows(sm, row0, NPAD, g_perm);
    __syncthreads();
    gemm_stage_A(sm, g_hb);
    float c[8][4];
    czero(c);
    gemm_accum(sm, 6 + t, c);
    gemm_epilogue(sm, c, ab + t*Dd, g_trans, false);
}

// ---------------- edge phase: pure gather-dot ----------------
__global__ void k_edge_logits(const int* __restrict__ ei, const int* __restrict__ et,
                              const float* __restrict__ rpri)
{
    int warp = threadIdx.x >> 5, lane = threadIdx.x & 31;
    int e = blockIdx.x*8 + warp;
    if (e >= Ee) return;
    int s = ei[e], tg = ei[Ee + e], r = et[e];
    float4 kv = ((const float4*)(&g_kp[r][0] + s*Dd))[lane];
    float4 qv = ((const float4*)(g_qn + tg*Dd))[lane];
    float p = kv.x*qv.x + kv.y*qv.y + kv.z*qv.z + kv.w*qv.w;
    p += __shfl_xor_sync(0xffffffffu, p, 1);
    p += __shfl_xor_sync(0xffffffffu, p, 2);
    p += __shfl_xor_sync(0xffffffffu, p, 4);
    int h = lane >> 3;
    if ((lane & 7) == 0) {
        float logit = p * rpri[r*Hh + h] * 0.17677669529663687f;
        g_ebuf[e*Hh + h] = logit;
        atomicMaxFloat(&g_nmax[tg*Hh + h], logit);
    }
    if (lane == 0) atomicAdd(&g_deg[tg], 1);
}

__global__ void k_edge_exp(const int* __restrict__ ei) {
    int idx = blockIdx.x * blockDim.x + threadIdx.x;
    if (idx >= Ee*Hh) return;
    int e = idx >> 2, h = idx & 3;
    int tg = ei[Ee + e];
    float ex = expf(g_ebuf[idx] - g_nmax[tg*Hh + h]);
    g_ebuf[idx] = ex;
    atomicAdd(&g_nsum[tg*Hh + h], ex);
}

__global__ void k_msg(const int* __restrict__ ei, const int* __restrict__ et,
                      const float* __restrict__ rmsg)
{
    __shared__ float sv[4][128];
    int warp = threadIdx.x >> 5, lane = threadIdx.x & 31;
    int n = blockIdx.x*4 + warp;
    if (n >= Nn) return;
    int s = ei[n], tg = ei[Ee + n], r = et[n];
    *(float4*)&sv[warp][lane*4] = ((const float4*)(g_vn + s*Dd))[lane];
    __syncwarp();
    int h = lane >> 3, m0 = (lane & 7) * 4;
    const float* A = rmsg + (r*Hh + h)*(DKk*DKk) + m0;
    float ax = 0.f, ay = 0.f, az = 0.f, aw = 0.f;
    const float* vh = &sv[warp][h*32];
    #pragma unroll
    for (int d = 0; d < DKk; d++) {
        float vv = vh[d];
        float4 a = *(const float4*)(A + d*DKk);
        ax += vv*a.x; ay += vv*a.y; az += vv*a.z; aw += vv*a.w;
    }
    float att = g_ebuf[n*Hh + h] / (g_nsum[tg*Hh + h] + 1e-16f);
    float c1 = (float)g_deg[n] * att;
    int base = n*Dd + lane*4;
    float4 o1, o2, o3;
    o1.x = c1*ax;       o1.y = c1*ay;       o1.z = c1*az;       o1.w = c1*aw;
    o2.x = c1*ax*ax;    o2.y = c1*ay*ay;    o2.z = c1*az*az;    o2.w = c1*aw*aw;
    o3.x = signed_cbrt(c1*ax*ax*ax);
    o3.y = signed_cbrt(c1*ay*ay*ay);
    o3.z = signed_cbrt(c1*az*az*az);
    o3.w = signed_cbrt(c1*aw*aw*aw);
    *(float4*)(&g_aggX[0][0] + base) = o1;
    *(float4*)(&g_aggX[1][0] + base) = o2;
    *(float4*)(&g_aggX[2][0] + base) = o3;
}

// ---------------- gate ----------------
__global__ void k_gate(const float* __restrict__ X) {
    int warp = threadIdx.x >> 5, lane = threadIdx.x & 31;
    int n = blockIdx.x*4 + warp;
    if (n >= Nn) return;
    int base = n*Dd + lane*4;
    float4 xv = *(const float4*)(X + base);
    #pragma unroll
    for (int k = 0; k < Kk; k++) {
        float4 vv = *(const float4*)(&g_V[k][0] + base);
        float4 ax = *(const float4*)(&g_aggX[k][0] + base);
        float4 uu = *(const float4*)(&g_u[k][0] + lane*4);
        float4 ww = *(const float4*)(&g_w[k][0] + lane*4);
        float p = vv.x*ax.x + vv.y*ax.y + vv.z*ax.z + vv.w*ax.w
                + xv.x*uu.x + xv.y*uu.y + xv.z*uu.z + xv.w*uu.w
                + ax.x*ww.x + ax.y*ww.y + ax.z*ww.z + ax.w*ww.w;
        p = warp_sum(p) + g_s[k];
        float tk = 1.f / (1.f + expf(-p));
        float4 o = make_float4(tk*ax.x, tk*ax.y, tk*ax.z, tk*ax.w);
        *(float4*)(&g_aggX[k][0] + base) = o;
    }
}

// ---------------- skip + layernorm ----------------
__global__ void k_final(const float* __restrict__ X, const int* __restrict__ ntype,
                        const float* __restrict__ skip, const float* __restrict__ lng,
                        const float* __restrict__ lnb, float* __restrict__ out)
{
    int warp = threadIdx.x >> 5, lane = threadIdx.x & 31;
    int n = blockIdx.x*4 + warp;
    if (n >= Nn) return;
    int t = ntype[n];
    float alpha = 1.f / (1.f + expf(-skip[t]));
    int base = n*Dd + lane*4;
    float4 x  = *(const float4*)(X + base);
    float4 tr = *(const float4*)(g_trans + base);
    float4 y;
    y.x = tr.x*alpha + x.x*(1.f - alpha);
    y.y = tr.y*alpha + x.y*(1.f - alpha);
    y.z = tr.z*alpha + x.z*(1.f - alpha);
    y.w = tr.w*alpha + x.w*(1.f - alpha);
    float mu = warp_sum(y.x + y.y + y.z + y.w) * (1.f/128.f);
    float4 d = make_float4(y.x - mu, y.y - mu, y.z - mu, y.w - mu);
    float var = warp_sum(d.x*d.x + d.y*d.y + d.z*d.z + d.w*d.w) * (1.f/128.f);
    float rstd = rsqrtf(var + 1e-5f);
    int gi = t*Dd + lane*4;
    float4 g = *(const float4*)(lng + gi);
    float4 b = *(const float4*)(lnb + gi);
    float4 o;
    o.x = d.x*rstd*g.x + b.x;
    o.y = d.y*rstd*g.y + b.y;
    o.z = d.z*rstd*g.z + b.z;
    o.w = d.w*rstd*g.w + b.w;
    *(float4*)(out + base) = o;
}

// ---------------- launch ----------------
extern "C" void kernel_launch(void* const* d_in, const int* in_sizes, int n_in,
                              void* d_out, int out_size)
{
    const float* meta = (const float*)d_in[0];
    const int*   ntype = (const int*)d_in[1];
    const int*   ei    = (const int*)d_in[2];
    const int*   et    = (const int*)d_in[3];
    // d_in[4] = edge_time (unused)
    const float* qw = (const float*)d_in[5],  *qb = (const float*)d_in[6];
    const float* kw = (const float*)d_in[7],  *kb = (const float*)d_in[8];
    const float* vw = (const float*)d_in[9],  *vb = (const float*)d_in[10];
    const float* aw = (const float*)d_in[11], *ab = (const float*)d_in[12];
    const float* rpri = (const float*)d_in[13];
    const float* ratt = (const float*)d_in[14];
    const float* rmsg = (const float*)d_in[15];
    const float* WMk  = (const float*)d_in[16];
    const float* Wak  = (const float*)d_in[17];
    const float* Wq   = (const float*)d_in[18], *bq  = (const float*)d_in[19];
    const float* Wkl  = (const float*)d_in[20], *bkl = (const float*)d_in[21];
    const float* skp  = (const float*)d_in[22];
    const float* lng  = (const float*)d_in[23], *lnb = (const float*)d_in[24];
    float* out = (float*)d_out;

    static int attrDone = 0;
    if (!attrDone) {
        cudaFuncSetAttribute(k_gemm_qkv, cudaFuncAttributeMaxDynamicSharedMemorySize, GEMM_SMEM);
        cudaFuncSetAttribute(k_gemm_V,   cudaFuncAttributeMaxDynamicSharedMemorySize, GEMM_SMEM);
        cudaFuncSetAttribute(k_gemm_res, cudaFuncAttributeMaxDynamicSharedMemorySize, GEMM_SMEM);
        cudaFuncSetAttribute(k_gemm_a,   cudaFuncAttributeMaxDynamicSharedMemorySize, GEMM_SMEM);
        attrDone = 1;
    }

    float* WcP = nullptr; float* T1P = nullptr; float* PP = nullptr;
    cudaGetSymbolAddress((void**)&WcP, g_Wc);
    cudaGetSymbolAddress((void**)&T1P, g_T1);
    cudaGetSymbolAddress((void**)&PP,  g_P);

    k_init<<<(Nn*Hh + 255)/256, 256>>>(ntype, qw, vw, aw, WMk, kw, ratt);  // 1
    k_prep2<<<1 + Tt*Rr, 128>>>(kb, ratt);                                 // 2
    k_scatter<<<(Nn + 255)/256, 256>>>(ntype);                             // 3
    k_gemm_qkv<<<NPAD/64, 256, GEMM_SMEM>>>(meta, qb, vb);                 // 4 <- ncu slot

    k_ab<<<dim3(Dd,1,Kk), Dd>>>(WcP, Wq, Wak, 0, Dd*Dd);       // Wc_k = Wq @ Wak_k
    k_bc<<<Kk, Dd>>>(bq, Wak);                                  // bc_k = bq @ Wak_k
    k_abT<<<dim3(Dd,1,Kk), Dd>>>(T1P, WcP, Wkl, Dd*Dd, 0);     // T1_k = Wc_k @ Wkl^T
    k_abT<<<dim3(Dd,1,Kk), Dd>>>(PP, T1P, WMk, Dd*Dd, Dd*Dd);  // P_k  = T1_k @ WMk_k^T
    k_wprep<<<dim3(8,1,Kk), 256>>>(PP, 9);                      // P -> bf16 word layout
    k_vecs<<<Kk, Dd>>>(Wkl, bkl, WMk);                          // u, w, s

    k_edge_logits<<<Ee/8, 256>>>(ei, et, rpri);
    k_edge_exp<<<(Ee*Hh + 255)/256, 256>>>(ei);
    k_msg<<<Nn/4, 128>>>(ei, et, rmsg);

    k_gemm_V<<<Nn/64, 256, GEMM_SMEM>>>(meta);
    k_gate<<<Nn/4, 128>>>(meta);
    k_gemm_res<<<Nn/64, 256, GEMM_SMEM>>>();
    k_gemm_a<<<NPAD/64, 256, GEMM_SMEM>>>(ab);
    k_final<<<Nn/4, 128>>>(meta, ntype, skp, lng, lnb, out);
}

// round 13
// speedup vs baseline: 1.5927x; 1.0815x over previous
#include <cuda_runtime.h>
#include <cuda_bf16.h>
#include <stdint.h>
#include <math.h>

#define Nn 40000
#define Ee 320000
#define Dd 128
#define Hh 4
#define Tt 3
#define Rr 5
#define Kk 3
#define DKk 32
#define NPAD (Nn + 64*Tt)
#define ND (Nn*Dd)

// ---------------- scratch ----------------
__device__ float g_qn[ND], g_vn[ND];
__device__ float g_kp[Rr][ND];
__device__ float g_ebuf[Ee*Hh];
__device__ float g_nmax[Nn*Hh], g_nsum[Nn*Hh];
__device__ int   g_deg[Nn];
__device__ float g_aggX[Kk][ND];
__device__ float g_V[Kk][ND];
__device__ float g_hb[ND];
__device__ float g_trans[ND];
__device__ int   g_perm[NPAD], g_hist[Tt], g_cursor[Tt], g_offA[Tt+1];
__device__ float g_Wc[Kk][Dd*Dd], g_bc[Kk][Dd];
__device__ float g_T1[Kk][Dd*Dd], g_P[Kk][Dd*Dd];
__device__ float g_u[Kk][Dd], g_w[Kk][Dd], g_s[Kk];

// Prepped weights: bf16 hi/lo MMA word layout; 8192 words per matrix.
// ids: 0-2 qw_t, 3-5 vw_t, 6-8 aw_t, 9-11 P_k, 12-14 WMk_k, 15-17 kw_t.
#define NMAT 18
__device__ uint32_t g_Wbh[NMAT*8192];
__device__ uint32_t g_Wbl[NMAT*8192];
// Compact block-diagonal rel_att: per r, [128 n][16 words] (32 k of own head)
__device__ uint32_t g_BDh[Rr*2048];
__device__ uint32_t g_BDl[Rr*2048];

// ---------------- helpers ----------------
__device__ __forceinline__ void atomicMaxFloat(float* addr, float v) {
    if (v >= 0.f) atomicMax((int*)addr, __float_as_int(v));
    else          atomicMin((unsigned int*)addr, __float_as_uint(v));
}

__device__ __forceinline__ float warp_sum(float v) {
    v += __shfl_xor_sync(0xffffffffu, v, 16);
    v += __shfl_xor_sync(0xffffffffu, v, 8);
    v += __shfl_xor_sync(0xffffffffu, v, 4);
    v += __shfl_xor_sync(0xffffffffu, v, 2);
    v += __shfl_xor_sync(0xffffffffu, v, 1);
    return v;
}

__device__ __forceinline__ float signed_cbrt(float z) {
    return (z == 0.f) ? 0.f : copysignf(cbrtf(fabsf(z) + 1e-18f), z);
}

__device__ __forceinline__ void split_bf16(float x, __nv_bfloat16& h, __nv_bfloat16& l) {
    h = __float2bfloat16(x);
    l = __float2bfloat16(x - __bfloat162float(h));
}

__device__ __forceinline__ uint32_t pack_bf16x2(__nv_bfloat16 lo16, __nv_bfloat16 hi16) {
    return (uint32_t)__bfloat16_as_ushort(lo16) | ((uint32_t)__bfloat16_as_ushort(hi16) << 16);
}

#define MMA_BF16(c, a0, a1, a2, a3, b0, b1) \
    asm volatile("mma.sync.aligned.m16n8k16.row.col.f32.bf16.bf16.f32 " \
        "{%0,%1,%2,%3}, {%4,%5,%6,%7}, {%8,%9}, {%0,%1,%2,%3};" \
        : "+f"((c)[0]), "+f"((c)[1]), "+f"((c)[2]), "+f"((c)[3]) \
        : "r"(a0), "r"(a1), "r"(a2), "r"(a3), "r"(b0), "r"(b1))

__device__ __forceinline__ void ldsm_x4(uint32_t& r0, uint32_t& r1, uint32_t& r2,
                                        uint32_t& r3, uint32_t saddr) {
    asm volatile("ldmatrix.sync.aligned.m8n8.x4.shared.b16 {%0,%1,%2,%3}, [%4];"
                 : "=r"(r0), "=r"(r1), "=r"(r2), "=r"(r3) : "r"(saddr));
}

// ---------------- weight prep ----------------
__device__ __forceinline__ void wprep_store(int mat, int ks, int n, int half,
                                            const float* vals) {
    uint32_t outh[4], outl[4];
    #pragma unroll
    for (int jj = 0; jj < 4; jj++) {
        __nv_bfloat16 ha, la, hb, lb;
        split_bf16(vals[jj*2],   ha, la);
        split_bf16(vals[jj*2+1], hb, lb);
        outh[jj] = pack_bf16x2(ha, hb);
        outl[jj] = pack_bf16x2(la, lb);
    }
    int base = mat*8192 + ks*1024 + n*8 + half*4;
    *(uint4*)(g_Wbh + base) = make_uint4(outh[0], outh[1], outh[2], outh[3]);
    *(uint4*)(g_Wbl + base) = make_uint4(outl[0], outl[1], outl[2], outl[3]);
}

__device__ __forceinline__ void wprep_chunk(const float* __restrict__ W, int mat, int ks) {
    int tid = threadIdx.x;
    int n = tid >> 1, half = tid & 1;
    float vals[8];
    #pragma unroll
    for (int jj = 0; jj < 4; jj++) {
        int j = half*4 + jj;
        int k0 = ks*16 + 2*j;
        vals[jj*2]   = W[k0*Dd + n];
        vals[jj*2+1] = W[(k0+1)*Dd + n];
    }
    wprep_store(mat, ks, n, half, vals);
}

// ---------------- setup ----------------
__global__ void k_init(const int* __restrict__ ntype,
                       const float* __restrict__ qw, const float* __restrict__ vw,
                       const float* __restrict__ aw, const float* __restrict__ WMk,
                       const float* __restrict__ kw, const float* __restrict__ ratt) {
    int i = blockIdx.x * blockDim.x + threadIdx.x;
    if (i < Nn*Hh) { g_nmax[i] = __int_as_float(0xff800000); g_nsum[i] = 0.f; }
    if (i < Nn) { g_deg[i] = 0; atomicAdd(&g_hist[ntype[i]], 1); }
    if (i < NPAD) g_perm[i] = -1;
    if (i < Tt)   g_cursor[i] = 0;
    int b = blockIdx.x;
    if (b < 120) {            // 15 dense matrices x 8 chunks
        int m = b >> 3, ks = b & 7;
        const float* src; int dst;
        if (m < 3)       { src = qw  + m*Dd*Dd;      dst = m; }
        else if (m < 6)  { src = vw  + (m-3)*Dd*Dd;  dst = m; }
        else if (m < 9)  { src = aw  + (m-6)*Dd*Dd;  dst = m; }
        else if (m < 12) { src = WMk + (m-9)*Dd*Dd;  dst = 12 + (m-9); }
        else             { src = kw  + (m-12)*Dd*Dd; dst = 15 + (m-12); }
        wprep_chunk(src, dst, ks);
    } else if (b < 125) {     // compact BD_r
        int r = b - 120;
        int n = threadIdx.x >> 1, half = threadIdx.x & 1;
        int h = n >> 5, m2 = n & 31;
        uint32_t oh[8], ol[8];
        #pragma unroll
        for (int jj = 0; jj < 8; jj++) {
            int j = half*8 + jj;
            float v0 = ratt[((r*Hh + h)*DKk + 2*j)*DKk + m2];
            float v1 = ratt[((r*Hh + h)*DKk + 2*j + 1)*DKk + m2];
            __nv_bfloat16 hh0, ll0, hh1, ll1;
            split_bf16(v0, hh0, ll0);
            split_bf16(v1, hh1, ll1);
            oh[jj] = pack_bf16x2(hh0, hh1);
            ol[jj] = pack_bf16x2(ll0, ll1);
        }
        int base = r*2048 + n*16 + half*8;
        *(uint4*)(g_BDh + base)     = make_uint4(oh[0], oh[1], oh[2], oh[3]);
        *(uint4*)(g_BDh + base + 4) = make_uint4(oh[4], oh[5], oh[6], oh[7]);
        *(uint4*)(g_BDl + base)     = make_uint4(ol[0], ol[1], ol[2], ol[3]);
        *(uint4*)(g_BDl + base + 4) = make_uint4(ol[4], ol[5], ol[6], ol[7]);
    }
}

__global__ void k_offsets() {
    int off = 0;
    for (int t = 0; t < Tt; t++) { g_offA[t] = off; off += ((g_hist[t] + 63) & ~63); g_hist[t] = 0; }
    g_offA[Tt] = off;
}

__global__ void k_scatter(const int* __restrict__ ntype) {
    int n = blockIdx.x * blockDim.x + threadIdx.x;
    if (n < Nn) {
        int t = ntype[n];
        int p = atomicAdd(&g_cursor[t], 1);
        g_perm[g_offA[t] + p] = n;
    }
}

__global__ void k_wprep(const float* __restrict__ W, int dstBase) {
    wprep_chunk(W + blockIdx.z*Dd*Dd, dstBase + blockIdx.z, blockIdx.x);
}

// ---------------- small prep kernels (fp32 exact) ----------------
__global__ void k_ab(float* __restrict__ C, const float* __restrict__ A,
                     const float* __restrict__ B, int aStrideZ, int bStrideZ) {
    int i = blockIdx.x, z = blockIdx.z, j = threadIdx.x;
    const float* a = A + z*aStrideZ + i*Dd;
    const float* b = B + z*bStrideZ;
    float s = 0.f;
    #pragma unroll 8
    for (int d = 0; d < Dd; d++) s += a[d] * b[d*Dd + j];
    C[z*Dd*Dd + i*Dd + j] = s;
}

__global__ void k_abT(float* __restrict__ C, const float* __restrict__ A,
                      const float* __restrict__ B, int aStrideZ, int bStrideZ) {
    int i = blockIdx.x, z = blockIdx.z, j = threadIdx.x;
    const float* a = A + z*aStrideZ + i*Dd;
    const float* b = B + z*bStrideZ + j*Dd;
    float s = 0.f;
    #pragma unroll 8
    for (int d = 0; d < Dd; d++) s += a[d] * b[d];
    C[z*Dd*Dd + i*Dd + j] = s;
}

__global__ void k_bc(const float* __restrict__ bq, const float* __restrict__ Wak) {
    int k = blockIdx.x, o = threadIdx.x;
    float s = 0.f;
    for (int j = 0; j < Dd; j++) s += bq[j] * Wak[k*Dd*Dd + j*Dd + o];
    g_bc[k][o] = s;
}

__global__ void k_vecs(const float* __restrict__ Wkl, const float* __restrict__ bkl,
                       const float* __restrict__ WMk) {
    __shared__ float y[Dd];
    int k = blockIdx.x, i = threadIdx.x;
    float u = 0.f, yy = 0.f;
    for (int d = 0; d < Dd; d++) {
        u  += g_Wc[k][i*Dd + d] * bkl[d];
        yy += Wkl[i*Dd + d] * g_bc[k][d];
    }
    g_u[k][i] = u;
    y[i] = yy;
    __syncthreads();
    float w = 0.f;
    for (int j = 0; j < Dd; j++) w += WMk[k*Dd*Dd + i*Dd + j] * y[j];
    g_w[k][i] = w;
    if (i == 0) {
        float s = 0.f;
        for (int d = 0; d < Dd; d++) s += g_bc[k][d] * bkl[d];
        g_s[k] = s;
    }
}

// ---------- bf16 3-term tensor-core GEMM core ----------
#define AS 136
#define BCH 1536

struct alignas(16) GemmSM {
    __nv_bfloat16 Ah[64*AS], Al[64*AS];
    uint32_t Bh[2][BCH], Bl[2][BCH];
    int rowNode[64];
};
#define GEMM_SMEM ((int)sizeof(GemmSM))

__device__ __forceinline__ void gemm_stage_rows(GemmSM* s, int row0, int rowlimit,
                                                const int* perm) {
    int tid = threadIdx.x;
    if (tid < 64) {
        int gr = row0 + tid;
        int nd = (gr < rowlimit) ? (perm ? perm[gr] : gr) : -1;
        s->rowNode[tid] = nd;
    }
}

__device__ __forceinline__ void gemm_stage_A(GemmSM* s, const float* __restrict__ X) {
    int tid = threadIdx.x;
    int m = tid & 63, q = tid >> 6;
    int node = s->rowNode[m];
    __nv_bfloat162* Ah2 = (__nv_bfloat162*)s->Ah;
    __nv_bfloat162* Al2 = (__nv_bfloat162*)s->Al;
    int wbase = m*(AS/2) + q*16;
    if (node >= 0) {
        const float4* src = (const float4*)(X + node*Dd + q*32);
        #pragma unroll
        for (int j = 0; j < 8; j++) {
            float4 v = src[j];
            __nv_bfloat16 h0,l0,h1,l1,h2,l2,h3,l3;
            split_bf16(v.x, h0, l0); split_bf16(v.y, h1, l1);
            split_bf16(v.z, h2, l2); split_bf16(v.w, h3, l3);
            Ah2[wbase + j*2]     = __nv_bfloat162(h0, h1);
            Ah2[wbase + j*2 + 1] = __nv_bfloat162(h2, h3);
            Al2[wbase + j*2]     = __nv_bfloat162(l0, l1);
            Al2[wbase + j*2 + 1] = __nv_bfloat162(l2, l3);
        }
    } else {
        __nv_bfloat162 z2 = __nv_bfloat162(__nv_bfloat16(0.f), __nv_bfloat16(0.f));
        #pragma unroll
        for (int j = 0; j < 8; j++) {
            Ah2[wbase + j*2] = z2; Ah2[wbase + j*2 + 1] = z2;
            Al2[wbase + j*2] = z2; Al2[wbase + j*2 + 1] = z2;
        }
    }
}

__device__ __forceinline__ void gemm_accum(GemmSM* s, int mat, float c[8][4]) {
    int tid = threadIdx.x;
    int lane = tid & 31, wid = tid >> 5;
    int mw = wid >> 1, nw = wid & 1;
    int lt = lane >> 3, lrow = lane & 7;
    int n = tid >> 1, half = tid & 1;
    const uint4* srcH = (const uint4*)(g_Wbh + mat*8192);
    const uint4* srcL = (const uint4*)(g_Wbl + mat*8192);
    int cpSrc = n*2 + half;
    int cpDst = n*12 + half*4;

    uint32_t aBaseH = (uint32_t)__cvta_generic_to_shared(s->Ah);
    uint32_t aBaseL = (uint32_t)__cvta_generic_to_shared(s->Al);
    uint32_t bBaseH = (uint32_t)__cvta_generic_to_shared(&s->Bh[0][0]);
    uint32_t bBaseL = (uint32_t)__cvta_generic_to_shared(&s->Bl[0][0]);

    int mrow = mw*16 + (lt & 1)*8 + lrow;
    uint32_t aOff = (uint32_t)((mrow*(AS/2) + (lt >> 1)*4) * 4);
    uint32_t bOff[4];
    #pragma unroll
    for (int p = 0; p < 4; p++) {
        int ncol = nw*64 + (2*p + (lt >> 1))*8 + lrow;
        bOff[p] = (uint32_t)((ncol*12 + (lt & 1)*4) * 4);
    }

    uint4 rh = srcH[cpSrc], rl = srcL[cpSrc];
    *(uint4*)(&s->Bh[0][cpDst]) = rh;
    *(uint4*)(&s->Bl[0][cpDst]) = rl;
    rh = srcH[256 + cpSrc];
    rl = srcL[256 + cpSrc];

    #pragma unroll
    for (int ks = 0; ks < 8; ks++) {
        __syncthreads();

        uint32_t bufH = bBaseH + (uint32_t)((ks & 1) * 6144);
        uint32_t bufL = bBaseL + (uint32_t)((ks & 1) * 6144);
        uint32_t ah0,ah1,ah2,ah3, al0,al1,al2,al3;
        ldsm_x4(ah0, ah1, ah2, ah3, aBaseH + aOff + ks*32);
        ldsm_x4(al0, al1, al2, al3, aBaseL + aOff + ks*32);
        #pragma unroll
        for (int p = 0; p < 4; p++) {
            uint32_t bh0,bh1,bh2,bh3, bl0,bl1,bl2,bl3;
            ldsm_x4(bh0, bh1, bh2, bh3, bufH + bOff[p]);
            ldsm_x4(bl0, bl1, bl2, bl3, bufL + bOff[p]);
            MMA_BF16(c[2*p],   ah0,ah1,ah2,ah3, bh0, bh1);
            MMA_BF16(c[2*p],   al0,al1,al2,al3, bh0, bh1);
            MMA_BF16(c[2*p],   ah0,ah1,ah2,ah3, bl0, bl1);
            MMA_BF16(c[2*p+1], ah0,ah1,ah2,ah3, bh2, bh3);
            MMA_BF16(c[2*p+1], al0,al1,al2,al3, bh2, bh3);
            MMA_BF16(c[2*p+1], ah0,ah1,ah2,ah3, bl2, bl3);
        }

        if (ks < 7) {
            int nb2 = (ks + 1) & 1;
            *(uint4*)(&s->Bh[nb2][cpDst]) = rh;
            *(uint4*)(&s->Bl[nb2][cpDst]) = rl;
            if (ks < 6) {
                rh = srcH[(ks + 2)*256 + cpSrc];
                rl = srcL[(ks + 2)*256 + cpSrc];
            }
        }
    }
}

// K=32 block-diagonal accum: kp = A(=kn) @ BD, BD staged compact (stride 20 words).
__device__ __forceinline__ void gemm_accum_kp(GemmSM* s, float c[8][4]) {
    int tid = threadIdx.x;
    int lane = tid & 31, wid = tid >> 5;
    int mw = wid >> 1, nw = wid & 1;
    int lt = lane >> 3, lrow = lane & 7;
    uint32_t aBaseH = (uint32_t)__cvta_generic_to_shared(s->Ah);
    uint32_t aBaseL = (uint32_t)__cvta_generic_to_shared(s->Al);
    uint32_t bBaseH = (uint32_t)__cvta_generic_to_shared(&s->Bh[0][0]);
    uint32_t bBaseL = (uint32_t)__cvta_generic_to_shared(&s->Bl[0][0]);
    int mrow = mw*16 + (lt & 1)*8 + lrow;
    uint32_t aOff = (uint32_t)((mrow*(AS/2) + (lt >> 1)*4) * 4);

    uint32_t ah[4][4], al[4][4];   // chunks nw*4 + ci (heads nw*2, nw*2+1)
    #pragma unroll
    for (int ci = 0; ci < 4; ci++) {
        int chunk = nw*4 + ci;
        ldsm_x4(ah[ci][0], ah[ci][1], ah[ci][2], ah[ci][3], aBaseH + aOff + chunk*32);
        ldsm_x4(al[ci][0], al[ci][1], al[ci][2], al[ci][3], aBaseL + aOff + chunk*32);
    }
    #pragma unroll
    for (int p = 0; p < 4; p++) {
        int ncol = nw*64 + (2*p + (lt >> 1))*8 + lrow;
        uint32_t bOffc = (uint32_t)((ncol*20 + (lt & 1)*4) * 4);
        #pragma unroll
        for (int ks2 = 0; ks2 < 2; ks2++) {
            int ci = (p >> 1)*2 + ks2;
            uint32_t bh0,bh1,bh2,bh3, bl0,bl1,bl2,bl3;
            ldsm_x4(bh0, bh1, bh2, bh3, bBaseH + bOffc + ks2*32);
            ldsm_x4(bl0, bl1, bl2, bl3, bBaseL + bOffc + ks2*32);
            MMA_BF16(c[2*p],   ah[ci][0],ah[ci][1],ah[ci][2],ah[ci][3], bh0, bh1);
            MMA_BF16(c[2*p],   al[ci][0],al[ci][1],al[ci][2],al[ci][3], bh0, bh1);
            MMA_BF16(c[2*p],   ah[ci][0],ah[ci][1],ah[ci][2],ah[ci][3], bl0, bl1);
            MMA_BF16(c[2*p+1], ah[ci][0],ah[ci][1],ah[ci][2],ah[ci][3], bh2, bh3);
            MMA_BF16(c[2*p+1], al[ci][0],al[ci][1],al[ci][2],al[ci][3], bh2, bh3);
            MMA_BF16(c[2*p+1], ah[ci][0],ah[ci][1],ah[ci][2],ah[ci][3], bl2, bl3);
        }
    }
}

// Write kn accumulator (+bias) back into the A smem tile (bf16 hi/lo).
__device__ __forceinline__ void restage_kn(GemmSM* s, float c[8][4], const float* bias) {
    int tid = threadIdx.x;
    int lane = tid & 31, wid = tid >> 5;
    int mw = wid >> 1, nw = wid & 1;
    int qr = lane >> 2, qt = lane & 3;
    __nv_bfloat162* Ah2 = (__nv_bfloat162*)s->Ah;
    __nv_bfloat162* Al2 = (__nv_bfloat162*)s->Al;
    int r0 = mw*16 + qr, r1 = r0 + 8;
    #pragma unroll
    for (int nb = 0; nb < 8; nb++) {
        int col = nw*64 + nb*8 + 2*qt;
        float2 bv = *(const float2*)(bias + col);
        int w = nw*32 + nb*4 + qt;
        __nv_bfloat16 h0,l0,h1,l1;
        split_bf16(c[nb][0] + bv.x, h0, l0);
        split_bf16(c[nb][1] + bv.y, h1, l1);
        Ah2[r0*(AS/2) + w] = __nv_bfloat162(h0, h1);
        Al2[r0*(AS/2) + w] = __nv_bfloat162(l0, l1);
        split_bf16(c[nb][2] + bv.x, h0, l0);
        split_bf16(c[nb][3] + bv.y, h1, l1);
        Ah2[r1*(AS/2) + w] = __nv_bfloat162(h0, h1);
        Al2[r1*(AS/2) + w] = __nv_bfloat162(l0, l1);
    }
}

__device__ __forceinline__ void gemm_epilogue(GemmSM* s, float c[8][4],
                                              const float* bias, float* __restrict__ Y,
                                              bool gelu) {
    int tid = threadIdx.x;
    int lane = tid & 31, wid = tid >> 5;
    int mw = wid >> 1, nw = wid & 1;
    int qr = lane >> 2, qt = lane & 3;
    int nd0 = s->rowNode[mw*16 + qr];
    int nd1 = s->rowNode[mw*16 + qr + 8];
    #pragma unroll
    for (int nb = 0; nb < 8; nb++) {
        int col = nw*64 + nb*8 + 2*qt;
        float2 bv = make_float2(0.f, 0.f);
        if (bias) bv = *(const float2*)(bias + col);
        float o0 = c[nb][0] + bv.x, o1 = c[nb][1] + bv.y;
        float o2 = c[nb][2] + bv.x, o3 = c[nb][3] + bv.y;
        if (gelu) {
            o0 = 0.5f*o0*(1.f + erff(o0*0.7071067811865475f));
            o1 = 0.5f*o1*(1.f + erff(o1*0.7071067811865475f));
            o2 = 0.5f*o2*(1.f + erff(o2*0.7071067811865475f));
            o3 = 0.5f*o3*(1.f + erff(o3*0.7071067811865475f));
        }
        if (nd0 >= 0) *(float2*)(Y + nd0*Dd + col) = make_float2(o0, o1);
        if (nd1 >= 0) *(float2*)(Y + nd1*Dd + col) = make_float2(o2, o3);
    }
}

__device__ __forceinline__ void czero(float c[8][4]) {
    #pragma unroll
    for (int nb = 0; nb < 8; nb++) { c[nb][0]=0.f; c[nb][1]=0.f; c[nb][2]=0.f; c[nb][3]=0.f; }
}

// ---------------- GEMM kernels ----------------
// q, v, kn (on-chip), then 5 block-diagonal kp GEMMs.
__global__ void k_gemm_qkv(const float* __restrict__ X,
                           const float* __restrict__ qb, const float* __restrict__ vb,
                           const float* __restrict__ kb)
{
    extern __shared__ char smraw[];
    GemmSM* sm = (GemmSM*)smraw;
    int row0 = blockIdx.x * 64;
    int t = 0;
    if (row0 >= g_offA[1]) t = 1;
    if (row0 >= g_offA[2]) t = 2;
    gemm_stage_rows(sm, row0, NPAD, g_perm);
    __syncthreads();
    gemm_stage_A(sm, X);
    float c[8][4];
    czero(c); gemm_accum(sm, 0 + t, c);  gemm_epilogue(sm, c, qb + t*Dd, g_qn, false);
    czero(c); gemm_accum(sm, 3 + t, c);  gemm_epilogue(sm, c, vb + t*Dd, g_vn, false);
    czero(c); gemm_accum(sm, 15 + t, c); // kn, stays on-chip
    __syncthreads();
    restage_kn(sm, c, kb + t*Dd);
    for (int r = 0; r < Rr; r++) {
        __syncthreads();
        for (int idx = threadIdx.x; idx < 512; idx += 256) {
            int n2 = idx >> 2, jj = idx & 3;
            *(uint4*)(&sm->Bh[0][n2*20 + jj*4]) = ((const uint4*)(g_BDh + r*2048))[idx];
            *(uint4*)(&sm->Bl[0][n2*20 + jj*4]) = ((const uint4*)(g_BDl + r*2048))[idx];
        }
        __syncthreads();
        czero(c);
        gemm_accum_kp(sm, c);
        gemm_epilogue(sm, c, nullptr, &g_kp[r][0], false);
    }
}

__global__ void k_gemm_V(const float* __restrict__ X) {
    extern __shared__ char smraw[];
    GemmSM* sm = (GemmSM*)smraw;
    int row0 = blockIdx.x * 64;
    gemm_stage_rows(sm, row0, Nn, nullptr);
    __syncthreads();
    gemm_stage_A(sm, X);
    float c[8][4];
    #pragma unroll
    for (int z = 0; z < Kk; z++) {
        czero(c);
        gemm_accum(sm, 9 + z, c);
        gemm_epilogue(sm, c, nullptr, &g_V[z][0], false);
    }
}

__global__ void k_gemm_res() {
    extern __shared__ char smraw[];
    GemmSM* sm = (GemmSM*)smraw;
    int row0 = blockIdx.x * 64;
    gemm_stage_rows(sm, row0, Nn, nullptr);
    float c[8][4];
    czero(c);
    #pragma unroll
    for (int z = 0; z < Kk; z++) {
        __syncthreads();
        gemm_stage_A(sm, &g_aggX[z][0]);
        gemm_accum(sm, 12 + z, c);
    }
    gemm_epilogue(sm, c, nullptr, g_hb, true);
}

__global__ void k_gemm_a(const float* __restrict__ ab) {
    extern __shared__ char smraw[];
    GemmSM* sm = (GemmSM*)smraw;
    int row0 = blockIdx.x * 64;
    int t = 0;
    if (row0 >= g_offA[1]) t = 1;
    if (row0 >= g_offA[2]) t = 2;
    gemm_stage_rows(sm, row0, NPAD, g_perm);
    __syncthreads();
    gemm_stage_A(sm, g_hb);
    float c[8][4];
    czero(c);
    gemm_accum(sm, 6 + t, c);
    gemm_epilogue(sm, c, ab + t*Dd, g_trans, false);
}

// ---------------- edge phase ----------------
__global__ void k_edge_logits(const int* __restrict__ ei, const int* __restrict__ et,
                              const float* __restrict__ rpri)
{
    int warp = threadIdx.x >> 5, lane = threadIdx.x & 31;
    int e = blockIdx.x*8 + warp;
    if (e >= Ee) return;
    int s = ei[e], tg = ei[Ee + e], r = et[e];
    float4 kv = ((const float4*)(&g_kp[r][0] + s*Dd))[lane];
    float4 qv = ((const float4*)(g_qn + tg*Dd))[lane];
    float p = kv.x*qv.x + kv.y*qv.y + kv.z*qv.z + kv.w*qv.w;
    p += __shfl_xor_sync(0xffffffffu, p, 1);
    p += __shfl_xor_sync(0xffffffffu, p, 2);
    p += __shfl_xor_sync(0xffffffffu, p, 4);
    int h = lane >> 3;
    if ((lane & 7) == 0) {
        float logit = p * rpri[r*Hh + h] * 0.17677669529663687f;
        g_ebuf[e*Hh + h] = logit;
        atomicMaxFloat(&g_nmax[tg*Hh + h], logit);
    }
    if (lane == 0) atomicAdd(&g_deg[tg], 1);
}

__global__ void k_edge_exp(const int* __restrict__ ei) {
    int idx = blockIdx.x * blockDim.x + threadIdx.x;
    if (idx >= Ee*Hh) return;
    int e = idx >> 2, h = idx & 3;
    int tg = ei[Ee + e];
    float ex = expf(g_ebuf[idx] - g_nmax[tg*Hh + h]);
    g_ebuf[idx] = ex;
    atomicAdd(&g_nsum[tg*Hh + h], ex);
}

__global__ void k_msg(const int* __restrict__ ei, const int* __restrict__ et,
                      const float* __restrict__ rmsg)
{
    __shared__ float sv[4][128];
    int warp = threadIdx.x >> 5, lane = threadIdx.x & 31;
    int n = blockIdx.x*4 + warp;
    if (n >= Nn) return;
    int s = ei[n], tg = ei[Ee + n], r = et[n];
    *(float4*)&sv[warp][lane*4] = ((const float4*)(g_vn + s*Dd))[lane];
    __syncwarp();
    int h = lane >> 3, m0 = (lane & 7) * 4;
    const float* A = rmsg + (r*Hh + h)*(DKk*DKk) + m0;
    float ax = 0.f, ay = 0.f, az = 0.f, aw = 0.f;
    const float* vh = &sv[warp][h*32];
    #pragma unroll
    for (int d = 0; d < DKk; d++) {
        float vv = vh[d];
        float4 a = *(const float4*)(A + d*DKk);
        ax += vv*a.x; ay += vv*a.y; az += vv*a.z; aw += vv*a.w;
    }
    float att = g_ebuf[n*Hh + h] / (g_nsum[tg*Hh + h] + 1e-16f);
    float c1 = (float)g_deg[n] * att;
    int base = n*Dd + lane*4;
    float4 o1, o2, o3;
    o1.x = c1*ax;       o1.y = c1*ay;       o1.z = c1*az;       o1.w = c1*aw;
    o2.x = c1*ax*ax;    o2.y = c1*ay*ay;    o2.z = c1*az*az;    o2.w = c1*aw*aw;
    o3.x = signed_cbrt(c1*ax*ax*ax);
    o3.y = signed_cbrt(c1*ay*ay*ay);
    o3.z = signed_cbrt(c1*az*az*az);
    o3.w = signed_cbrt(c1*aw*aw*aw);
    *(float4*)(&g_aggX[0][0] + base) = o1;
    *(float4*)(&g_aggX[1][0] + base) = o2;
    *(float4*)(&g_aggX[2][0] + base) = o3;
}

// ---------------- gate ----------------
__global__ void k_gate(const float* __restrict__ X) {
    int warp = threadIdx.x >> 5, lane = threadIdx.x & 31;
    int n = blockIdx.x*4 + warp;
    if (n >= Nn) return;
    int base = n*Dd + lane*4;
    float4 xv = *(const float4*)(X + base);
    #pragma unroll
    for (int k = 0; k < Kk; k++) {
        float4 vv = *(const float4*)(&g_V[k][0] + base);
        float4 ax = *(const float4*)(&g_aggX[k][0] + base);
        float4 uu = *(const float4*)(&g_u[k][0] + lane*4);
        float4 ww = *(const float4*)(&g_w[k][0] + lane*4);
        float p = vv.x*ax.x + vv.y*ax.y + vv.z*ax.z + vv.w*ax.w
                + xv.x*uu.x + xv.y*uu.y + xv.z*uu.z + xv.w*uu.w
                + ax.x*ww.x + ax.y*ww.y + ax.z*ww.z + ax.w*ww.w;
        p = warp_sum(p) + g_s[k];
        float tk = 1.f / (1.f + expf(-p));
        float4 o = make_float4(tk*ax.x, tk*ax.y, tk*ax.z, tk*ax.w);
        *(float4*)(&g_aggX[k][0] + base) = o;
    }
}

// ---------------- skip + layernorm ----------------
__global__ void k_final(const float* __restrict__ X, const int* __restrict__ ntype,
                        const float* __restrict__ skip, const float* __restrict__ lng,
                        const float* __restrict__ lnb, float* __restrict__ out)
{
    int warp = threadIdx.x >> 5, lane = threadIdx.x & 31;
    int n = blockIdx.x*4 + warp;
    if (n >= Nn) return;
    int t = ntype[n];
    float alpha = 1.f / (1.f + expf(-skip[t]));
    int base = n*Dd + lane*4;
    float4 x  = *(const float4*)(X + base);
    float4 tr = *(const float4*)(g_trans + base);
    float4 y;
    y.x = tr.x*alpha + x.x*(1.f - alpha);
    y.y = tr.y*alpha + x.y*(1.f - alpha);
    y.z = tr.z*alpha + x.z*(1.f - alpha);
    y.w = tr.w*alpha + x.w*(1.f - alpha);
    float mu = warp_sum(y.x + y.y + y.z + y.w) * (1.f/128.f);
    float4 d = make_float4(y.x - mu, y.y - mu, y.z - mu, y.w - mu);
    float var = warp_sum(d.x*d.x + d.y*d.y + d.z*d.z + d.w*d.w) * (1.f/128.f);
    float rstd = rsqrtf(var + 1e-5f);
    int gi = t*Dd + lane*4;
    float4 g = *(const float4*)(lng + gi);
    float4 b = *(const float4*)(lnb + gi);
    float4 o;
    o.x = d.x*rstd*g.x + b.x;
    o.y = d.y*rstd*g.y + b.y;
    o.z = d.z*rstd*g.z + b.z;
    o.w = d.w*rstd*g.w + b.w;
    *(float4*)(out + base) = o;
}

// ---------------- launch ----------------
extern "C" void kernel_launch(void* const* d_in, const int* in_sizes, int n_in,
                              void* d_out, int out_size)
{
    const float* meta = (const float*)d_in[0];
    const int*   ntype = (const int*)d_in[1];
    const int*   ei    = (const int*)d_in[2];
    const int*   et    = (const int*)d_in[3];
    const float* qw = (const float*)d_in[5],  *qb = (const float*)d_in[6];
    const float* kw = (const float*)d_in[7],  *kb = (const float*)d_in[8];
    const float* vw = (const float*)d_in[9],  *vb = (const float*)d_in[10];
    const float* aw = (const float*)d_in[11], *ab = (const float*)d_in[12];
    const float* rpri = (const float*)d_in[13];
    const float* ratt = (const float*)d_in[14];
    const float* rmsg = (const float*)d_in[15];
    const float* WMk  = (const float*)d_in[16];
    const float* Wak  = (const float*)d_in[17];
    const float* Wq   = (const float*)d_in[18], *bq  = (const float*)d_in[19];
    const float* Wkl  = (const float*)d_in[20], *bkl = (const float*)d_in[21];
    const float* skp  = (const float*)d_in[22];
    const float* lng  = (const float*)d_in[23], *lnb = (const float*)d_in[24];
    float* out = (float*)d_out;

    static int attrDone = 0;
    if (!attrDone) {
        cudaFuncSetAttribute(k_gemm_qkv, cudaFuncAttributeMaxDynamicSharedMemorySize, GEMM_SMEM);
        cudaFuncSetAttribute(k_gemm_V,   cudaFuncAttributeMaxDynamicSharedMemorySize, GEMM_SMEM);
        cudaFuncSetAttribute(k_gemm_res, cudaFuncAttributeMaxDynamicSharedMemorySize, GEMM_SMEM);
        cudaFuncSetAttribute(k_gemm_a,   cudaFuncAttributeMaxDynamicSharedMemorySize, GEMM_SMEM);
        attrDone = 1;
    }

    float* WcP = nullptr; float* T1P = nullptr; float* PP = nullptr;
    cudaGetSymbolAddress((void**)&WcP, g_Wc);
    cudaGetSymbolAddress((void**)&T1P, g_T1);
    cudaGetSymbolAddress((void**)&PP,  g_P);

    k_init<<<(Nn*Hh + 255)/256, 256>>>(ntype, qw, vw, aw, WMk, kw, ratt);  // 1
    k_offsets<<<1, 1>>>();                                                 // 2
    k_scatter<<<(Nn + 255)/256, 256>>>(ntype);                             // 3
    k_gemm_qkv<<<NPAD/64, 256, GEMM_SMEM>>>(meta, qb, vb, kb);             // 4 <- ncu slot

    k_ab<<<dim3(Dd,1,Kk), Dd>>>(WcP, Wq, Wak, 0, Dd*Dd);
    k_bc<<<Kk, Dd>>>(bq, Wak);
    k_abT<<<dim3(Dd,1,Kk), Dd>>>(T1P, WcP, Wkl, Dd*Dd, 0);
    k_abT<<<dim3(Dd,1,Kk), Dd>>>(PP, T1P, WMk, Dd*Dd, Dd*Dd);
    k_wprep<<<dim3(8,1,Kk), 256>>>(PP, 9);
    k_vecs<<<Kk, Dd>>>(Wkl, bkl, WMk);

    k_edge_logits<<<Ee/8, 256>>>(ei, et, rpri);
    k_edge_exp<<<(Ee*Hh + 255)/256, 256>>>(ei);
    k_msg<<<Nn/4, 128>>>(ei, et, rmsg);

    k_gemm_V<<<Nn/64, 256, GEMM_SMEM>>>(meta);
    k_gate<<<Nn/4, 128>>>(meta);
    k_gemm_res<<<Nn/64, 256, GEMM_SMEM>>>();
    k_gemm_a<<<NPAD/64, 256, GEMM_SMEM>>>(ab);
    k_final<<<Nn/4, 128>>>(meta, ntype, skp, lng, lnb, out);
}